// round 6
// baseline (speedup 1.0000x reference)
#include <cuda_runtime.h>
#include <math.h>

#define NPART 16
#define DDIM 3
#define HID 64
#define DLAT 5
#define TEMB 16
#define NFREQ 8
#define NPAIR 120
#define RHOIN 28
#define NTHREADS 128
#define BPB 4

typedef unsigned long long ull;

// ---- dynamic smem layout (float offsets) ----
#define OFF_PSI_W1T 0          // [16][64][4] k-tiled transposed psi W1 (4096)
#define OFF_H0S     4096       // psi h0 transposed [kt][kc][128] (8192); phi h0 [kt][16]f4 aliases at +0; phi W1T aliases at +4096
#define OFF_PHI_W1T (OFF_H0S + 4096)
#define OFF_PSI_W0  12288      // [6][64] (384)
#define OFF_PSI_B0  12672      // (64)
#define OFF_PSI_B1  12736      // (64)
#define OFF_PSI_W2  12800      // [64][5] (320)
#define OFF_PSI_B2  13120      // (8)
#define OFF_PHI_W0  13128      // [3][64] (192)
#define OFF_PHI_B0  13320      // (64)
#define OFF_PHI_B1  13384      // (64)
#define OFF_PHI_W2  13448      // (320)
#define OFF_PHI_B2  13768      // (8)
#define OFF_X       13776      // (48)
#define OFF_GATE    13824      // (128, rows 120..127 = 0)
#define OFF_RED     13952      // 14*4 (56)
#define OFF_RHOIN   14008      // (28)
#define OFF_RH0     14036      // (64)
#define OFF_TF      14100      // (17)
#define OFF_HT      14117      // (16)
#define OFF_MISC    14133      // (3)
#define SMEM_FLOATS 14136
#define SMEM_BYTES  (SMEM_FLOATS * 4)

// ---- packed f32x2 helpers ----
__device__ __forceinline__ ull pack2(float lo, float hi) {
    ull r; asm("mov.b64 %0, {%1, %2};" : "=l"(r) : "f"(lo), "f"(hi)); return r;
}
__device__ __forceinline__ ull dup2(float b) {
    ull r; asm("mov.b64 %0, {%1, %1};" : "=l"(r) : "f"(b)); return r;
}
__device__ __forceinline__ float2 unpack2(ull v) {
    float2 f; asm("mov.b64 {%0, %1}, %2;" : "=f"(f.x), "=f"(f.y) : "l"(v)); return f;
}
__device__ __forceinline__ void ffma2(ull& d, ull a, ull b) {
    asm("fma.rn.f32x2 %0, %1, %2, %0;" : "+l"(d) : "l"(a), "l"(b));
}
__device__ __forceinline__ ull fma2(ull a, ull b, ull c) {
    ull d; asm("fma.rn.f32x2 %0, %1, %2, %3;" : "=l"(d) : "l"(a), "l"(b), "l"(c)); return d;
}
__device__ __forceinline__ ull mul2(ull a, ull b) {
    ull d; asm("mul.rn.f32x2 %0, %1, %2;" : "=l"(d) : "l"(a), "l"(b)); return d;
}
__device__ __forceinline__ ull add2(ull a, ull b) {
    ull d; asm("add.rn.f32x2 %0, %1, %2;" : "=l"(d) : "l"(a), "l"(b)); return d;
}
__device__ __forceinline__ float rcp_approx(float x) {
    float r; asm("rcp.approx.f32 %0, %1;" : "=f"(r) : "f"(x)); return r;
}

// ---- gelu via A&S 7.1.28: 1-erf(z) = (1 + a1 z + ... + a6 z^6)^-16, |err|<=3e-7
//  gelu(x) = 0.5*((x+|x|) - |x|*q), q = (poly(|x|/sqrt2))^-16
__device__ __forceinline__ float gelu_f(float x) {
    float ax = fabsf(x);
    float z = ax * 0.70710678118f;
    float p = fmaf(4.30638e-5f, z, 2.765672e-4f);
    p = fmaf(p, z, 1.520143e-4f);
    p = fmaf(p, z, 9.2705272e-3f);
    p = fmaf(p, z, 4.22820123e-2f);
    p = fmaf(p, z, 7.05230784e-2f);
    p = fmaf(p, z, 1.0f);
    p = p * p; p = p * p; p = p * p; p = p * p;   // ^16 (may overflow to inf; rcp(inf)=0 ok)
    float q = rcp_approx(p);
    return 0.5f * ((x + ax) - ax * q);
}

__device__ __forceinline__ ull gelu2(ull x2) {
    ull ax2;
    asm("and.b64 %0, %1, %2;" : "=l"(ax2) : "l"(x2), "l"(0x7fffffff7fffffffULL));
    ull z2 = mul2(ax2, dup2(0.70710678118f));
    ull p = fma2(dup2(4.30638e-5f), z2, dup2(2.765672e-4f));
    p = fma2(p, z2, dup2(1.520143e-4f));
    p = fma2(p, z2, dup2(9.2705272e-3f));
    p = fma2(p, z2, dup2(4.22820123e-2f));
    p = fma2(p, z2, dup2(7.05230784e-2f));
    p = fma2(p, z2, dup2(1.0f));
    p = mul2(p, p); p = mul2(p, p); p = mul2(p, p); p = mul2(p, p);   // ^16
    float2 pv = unpack2(p);
    ull q2 = pack2(rcp_approx(pv.x), rcp_approx(pv.y));
    ull s2 = add2(x2, ax2);
    ull w2 = mul2(ax2, q2);
    return fma2(w2, dup2(-0.5f), mul2(s2, dup2(0.5f)));
}

__device__ __forceinline__ float blockReduceSum(float v, float* sRed) {
    const int tid = threadIdx.x;
    #pragma unroll
    for (int o = 16; o > 0; o >>= 1)
        v += __shfl_down_sync(0xffffffffu, v, o);
    if ((tid & 31) == 0) sRed[tid >> 5] = v;
    __syncthreads();
    float r = sRed[0] + sRed[1] + sRed[2] + sRed[3];
    __syncthreads();
    return r;
}

__global__ __launch_bounds__(NTHREADS, 4)
void tau_jastrow_kernel(
    const float* __restrict__ x, const float* __restrict__ tau, const float* __restrict__ freqs,
    const float* __restrict__ phi_w0, const float* __restrict__ phi_b0,
    const float* __restrict__ phi_w1, const float* __restrict__ phi_b1,
    const float* __restrict__ phi_w2, const float* __restrict__ phi_b2,
    const float* __restrict__ psi_w0, const float* __restrict__ psi_b0,
    const float* __restrict__ psi_w1, const float* __restrict__ psi_b1,
    const float* __restrict__ psi_w2, const float* __restrict__ psi_b2,
    const float* __restrict__ rho_w0, const float* __restrict__ rho_b0,
    const float* __restrict__ rho_w1, const float* __restrict__ rho_b1,
    const float* __restrict__ rho_w2, const float* __restrict__ rho_b2,
    const float* __restrict__ tp_w0, const float* __restrict__ tp_b0,
    const float* __restrict__ tp_w1, const float* __restrict__ tp_b1,
    float* __restrict__ out, int Btot)
{
    extern __shared__ float sm[];
    const int tid = threadIdx.x;

    // ---- preload psi weights (once per block) ----
    for (int idx = tid; idx < HID * HID; idx += NTHREADS) {
        int k = idx >> 6, j = idx & 63;
        sm[OFF_PSI_W1T + (k >> 2) * 256 + j * 4 + (k & 3)] = psi_w1[idx];
    }
    for (int i = tid; i < 6 * HID; i += NTHREADS) sm[OFF_PSI_W0 + i] = psi_w0[i];
    for (int i = tid; i < 3 * HID; i += NTHREADS) sm[OFF_PHI_W0 + i] = phi_w0[i];
    for (int i = tid; i < HID * DLAT; i += NTHREADS) {
        sm[OFF_PSI_W2 + i] = psi_w2[i];
        sm[OFF_PHI_W2 + i] = phi_w2[i];
    }
    if (tid < HID) {
        sm[OFF_PSI_B0 + tid] = psi_b0[tid]; sm[OFF_PSI_B1 + tid] = psi_b1[tid];
        sm[OFF_PHI_B0 + tid] = phi_b0[tid]; sm[OFF_PHI_B1 + tid] = phi_b1[tid];
    }
    if (tid < DLAT) {
        sm[OFF_PSI_B2 + tid] = psi_b2[tid];
        sm[OFF_PHI_B2 + tid] = phi_b2[tid];
    }
    if (tid >= NPAIR) sm[OFF_GATE + tid] = 0.f;   // padded rows: gate = 0, persists

    // ---- pair indices (triu k=1 row-major) ----
    int pi = 0, pj = 0;
    {
        int p2 = tid, i2 = 0, cnt = NPART - 1;
        while (cnt > 0 && p2 >= cnt) { p2 -= cnt; i2++; cnt--; }
        pi = i2; pj = i2 + 1 + p2;
        if (pj >= NPART) pj = NPART - 1;
    }
    const bool active = (tid < NPAIR);
    const float gamma = ((pi < NPART / 2) == (pj < NPART / 2))
                        ? (1.0f / (DDIM + 1)) : (1.0f / (DDIM - 1));

    const int base = blockIdx.x * BPB;
    for (int b = base; b < base + BPB && b < Btot; ++b) {
        if (tid < NPART * DDIM) sm[OFF_X + tid] = x[(size_t)b * (NPART * DDIM) + tid];
        __syncthreads();

        float vals[14];
        #pragma unroll
        for (int v = 0; v < 14; v++) vals[v] = 0.f;

        // ================= Phase A: psi pair features + h0 (packed, transposed store) =================
        if (active) {
            float d0 = sm[OFF_X + pi * 3 + 0] - sm[OFF_X + pj * 3 + 0];
            float d1 = sm[OFF_X + pi * 3 + 1] - sm[OFF_X + pj * 3 + 1];
            float d2 = sm[OFF_X + pi * 3 + 2] - sm[OFF_X + pj * 3 + 2];
            float r2 = d0 * d0 + d1 * d1 + d2 * d2;
            float r = sqrtf(r2 + 1.1920929e-7f);
            float rt2 = r2 + 0.04f;
            float u = rt2 * 25.0f;
            float tt = __fdividef(1.0f, 1.0f + u);
            float feat[6];
            float s1v = -__logf(tt);
            feat[0] = s1v;
            feat[1] = __fdividef(r2, rt2);
            feat[2] = u * __expf(-u);
            feat[4] = tt;                        // exp(-s1) = (1+u)^-1
            float t2v = tt * tt;
            feat[5] = t2v * t2v;                 // exp(-4 s1)
            feat[3] = sqrtf(sqrtf(tt));          // exp(-0.25 s1)
            float gatev = __fdividef(r2, r2 + 0.09f);
            sm[OFF_GATE + tid] = gatev;
            vals[5] = gatev;
            vals[6] = s1v;
            vals[7] = gamma * r * __expf(-r);

            ull feat2[6];
            #pragma unroll
            for (int i = 0; i < 6; i++) feat2[i] = dup2(feat[i]);

            const ulonglong2* w0p = (const ulonglong2*)(sm + OFF_PSI_W0);
            const ulonglong2* b0p = (const ulonglong2*)(sm + OFF_PSI_B0);
            #pragma unroll 2
            for (int kt = 0; kt < 16; kt++) {
                ulonglong2 bb = b0p[kt];
                ull alo = bb.x, ahi = bb.y;
                #pragma unroll
                for (int i = 0; i < 6; i++) {
                    ulonglong2 ww = w0p[i * 16 + kt];
                    alo = fma2(feat2[i], ww.x, alo);
                    ahi = fma2(feat2[i], ww.y, ahi);
                }
                float2 g0 = unpack2(gelu2(alo));
                float2 g1 = unpack2(gelu2(ahi));
                float* dst = sm + OFF_H0S + kt * 512 + tid;
                dst[0]   = g0.x;
                dst[128] = g0.y;
                dst[256] = g1.x;
                dst[384] = g1.y;
            }
        } else {
            #pragma unroll
            for (int kt = 0; kt < 16; kt++) {
                float* dst = sm + OFF_H0S + kt * 512 + tid;
                dst[0] = 0.f; dst[128] = 0.f; dst[256] = 0.f; dst[384] = 0.f;
            }
        }
        __syncthreads();

        // ================= psi h1 GEMM, packed f32x2 (128x64 @ 64x64) =================
        {
            const int rg = tid >> 4, cg = tid & 15;
            const int r0 = rg * 16;
            ull acc[8][4];
            #pragma unroll
            for (int c = 0; c < 4; c++) {
                ull bi = dup2(sm[OFF_PSI_B1 + cg + 16 * c]);
                #pragma unroll
                for (int q = 0; q < 8; q++) acc[q][c] = bi;
            }
            const float4* w1t4 = (const float4*)(sm + OFF_PSI_W1T);
            #pragma unroll 1
            for (int kt = 0; kt < 16; kt++) {
                float4 bv0 = w1t4[kt * 64 + cg];
                float4 bv1 = w1t4[kt * 64 + cg + 16];
                float4 bv2 = w1t4[kt * 64 + cg + 32];
                float4 bv3 = w1t4[kt * 64 + cg + 48];
                const float* hbase = sm + OFF_H0S + kt * 512 + r0;
                #define KC_STEP(kc, comp)                                           \
                {                                                                   \
                    ull b20 = dup2(bv0.comp);                                       \
                    ull b21 = dup2(bv1.comp);                                       \
                    ull b22 = dup2(bv2.comp);                                       \
                    ull b23 = dup2(bv3.comp);                                       \
                    const ulonglong2* ap =                                          \
                        (const ulonglong2*)(hbase + (kc) * 128);                    \
                    _Pragma("unroll")                                               \
                    for (int q2 = 0; q2 < 4; q2++) {                                \
                        ulonglong2 aa = ap[q2];                                     \
                        ffma2(acc[2 * q2][0], aa.x, b20);                           \
                        ffma2(acc[2 * q2][1], aa.x, b21);                           \
                        ffma2(acc[2 * q2][2], aa.x, b22);                           \
                        ffma2(acc[2 * q2][3], aa.x, b23);                           \
                        ffma2(acc[2 * q2 + 1][0], aa.y, b20);                       \
                        ffma2(acc[2 * q2 + 1][1], aa.y, b21);                       \
                        ffma2(acc[2 * q2 + 1][2], aa.y, b22);                       \
                        ffma2(acc[2 * q2 + 1][3], aa.y, b23);                       \
                    }                                                               \
                }
                KC_STEP(0, x) KC_STEP(1, y) KC_STEP(2, z) KC_STEP(3, w)
                #undef KC_STEP
            }
            // epilogue: packed gelu -> gate -> W2 (row-pairs stay packed)
            const ull* gt2p = (const ull*)(sm + OFF_GATE + r0);
            ull vals2[5];
            #pragma unroll
            for (int d = 0; d < 5; d++) vals2[d] = dup2(0.f);
            #pragma unroll
            for (int c = 0; c < 4; c++) {
                const int j = cg + 16 * c;
                ull w2d[5];
                #pragma unroll
                for (int d = 0; d < 5; d++) w2d[d] = dup2(sm[OFF_PSI_W2 + j * 5 + d]);
                #pragma unroll
                for (int q = 0; q < 8; q++) {
                    ull gg = mul2(gelu2(acc[q][c]), gt2p[q]);
                    #pragma unroll
                    for (int d = 0; d < 5; d++) vals2[d] = fma2(gg, w2d[d], vals2[d]);
                }
            }
            #pragma unroll
            for (int d = 0; d < 5; d++) {
                float2 f = unpack2(vals2[d]);
                vals[d] = f.x + f.y;
            }
        }
        __syncthreads();  // h0s region about to be reused by phi

        // ===== phi W1T reload (into h0s upper half) + phi h0 + time features =====
        {
            const float4* gw = (const float4*)phi_w1;
            #pragma unroll
            for (int i = 0; i < 8; i++) {
                int idx4 = tid + 128 * i;          // float4 index 0..1023
                float4 v = gw[idx4];
                int k = idx4 >> 4;
                int j0 = (idx4 & 15) * 4;
                float* d = sm + OFF_PHI_W1T + (k >> 2) * 256 + (k & 3) + j0 * 4;
                d[0] = v.x; d[4] = v.y; d[8] = v.z; d[12] = v.w;
            }
        }
        {
            int p = tid >> 3, c3 = tid & 7;
            float xv0 = sm[OFF_X + p * 3 + 0];
            float xv1 = sm[OFF_X + p * 3 + 1];
            float xv2 = sm[OFF_X + p * 3 + 2];
            const float4* w0 = (const float4*)(sm + OFF_PHI_W0);
            const float4* b0 = (const float4*)(sm + OFF_PHI_B0);
            float4* h0w = (float4*)(sm + OFF_H0S);
            #pragma unroll
            for (int t = 0; t < 2; t++) {
                int kt = 2 * c3 + t;
                float4 a = b0[kt];
                float4 w;
                w = w0[0 * 16 + kt];
                a.x += xv0 * w.x; a.y += xv0 * w.y; a.z += xv0 * w.z; a.w += xv0 * w.w;
                w = w0[1 * 16 + kt];
                a.x += xv1 * w.x; a.y += xv1 * w.y; a.z += xv1 * w.z; a.w += xv1 * w.w;
                w = w0[2 * 16 + kt];
                a.x += xv2 * w.x; a.y += xv2 * w.y; a.z += xv2 * w.z; a.w += xv2 * w.w;
                float2 g01 = unpack2(gelu2(pack2(a.x, a.y)));
                float2 g23 = unpack2(gelu2(pack2(a.z, a.w)));
                h0w[kt * 16 + p] = make_float4(g01.x, g01.y, g23.x, g23.y);
            }
        }
        float tb = tau[b];
        if (tid == 0) sm[OFF_TF + 0] = tb;
        if (tid < NFREQ) {
            float ft = freqs[tid] * tb;
            sm[OFF_TF + 1 + tid] = __sinf(ft);
            sm[OFF_TF + 1 + NFREQ + tid] = __cosf(ft);
        }
        __syncthreads();

        // ================= Phi h1 GEMM, packed f32x2 over k-pairs (16x64 @ 64x64) =================
        {
            int row = tid >> 3, cg = tid & 7;
            ull acc8[8];
            #pragma unroll
            for (int c = 0; c < 8; c++) acc8[c] = pack2(sm[OFF_PHI_B1 + cg + 8 * c], 0.f);
            const ulonglong2* w1p = (const ulonglong2*)(sm + OFF_PHI_W1T);
            const ulonglong2* h0p = (const ulonglong2*)(sm + OFF_H0S);
            #pragma unroll 2
            for (int kt = 0; kt < 16; kt++) {
                ulonglong2 a = h0p[kt * 16 + row];
                #pragma unroll
                for (int c = 0; c < 8; c++) {
                    ulonglong2 bb = w1p[kt * 64 + cg + 8 * c];
                    acc8[c] = fma2(a.x, bb.x, acc8[c]);
                    acc8[c] = fma2(a.y, bb.y, acc8[c]);
                }
            }
            float hc[8];
            #pragma unroll
            for (int c = 0; c < 8; c++) {
                float2 f = unpack2(acc8[c]);
                hc[c] = f.x + f.y;
            }
            #pragma unroll
            for (int t = 0; t < 4; t++) {
                float2 g = unpack2(gelu2(pack2(hc[2 * t], hc[2 * t + 1])));
                const int j0 = cg + 8 * (2 * t);
                const int j1 = cg + 8 * (2 * t + 1);
                #pragma unroll
                for (int d = 0; d < 5; d++) {
                    vals[8 + d] += g.x * sm[OFF_PHI_W2 + j0 * 5 + d];
                    vals[8 + d] += g.y * sm[OFF_PHI_W2 + j1 * 5 + d];
                }
            }
        }
        if (tid < NPART * DDIM) {
            float xv = sm[OFF_X + tid];
            vals[13] = xv * xv;
        }

        // ================= fused 14-value block reduction =================
        {
            const int lane = tid & 31, wid = tid >> 5;
            #pragma unroll
            for (int v = 0; v < 14; v++) {
                float t = vals[v];
                #pragma unroll
                for (int o = 16; o > 0; o >>= 1)
                    t += __shfl_down_sync(0xffffffffu, t, o);
                if (lane == 0) sm[OFF_RED + v * 4 + wid] = t;
            }
        }
        __syncthreads();
        if (tid < 14) {
            float s = sm[OFF_RED + tid * 4 + 0] + sm[OFF_RED + tid * 4 + 1]
                    + sm[OFF_RED + tid * 4 + 2] + sm[OFF_RED + tid * 4 + 3];
            if (tid < 5) {
                float gs = sm[OFF_RED + 20] + sm[OFF_RED + 21]
                         + sm[OFF_RED + 22] + sm[OFF_RED + 23];
                sm[OFF_RHOIN + 5 + tid] = (s + sm[OFF_PSI_B2 + tid] * gs) * (1.0f / NPAIR);
            } else if (tid == 6) {
                sm[OFF_RHOIN + 11] = s * (1.0f / NPAIR);
            } else if (tid == 7) {
                sm[OFF_MISC + 0] = s;   // cusp sum
            } else if (tid >= 8 && tid < 13) {
                sm[OFF_RHOIN + (tid - 8)] = s * (1.0f / NPART) + sm[OFF_PHI_B2 + tid - 8];
            } else if (tid == 13) {
                sm[OFF_RHOIN + 10] = s * (1.0f / (NPART * DDIM));
            }
        }
        // temb layer 1 (sTF synced by the reduction barrier)
        if (tid < TEMB) {
            float a = tp_b0[tid];
            #pragma unroll
            for (int i2 = 0; i2 < 2 * NFREQ + 1; i2++)
                a += sm[OFF_TF + i2] * tp_w0[i2 * TEMB + tid];
            sm[OFF_HT + tid] = gelu_f(a);
        }
        __syncthreads();
        if (tid < TEMB) {
            float a = tp_b1[tid];
            #pragma unroll
            for (int i2 = 0; i2 < TEMB; i2++)
                a += sm[OFF_HT + i2] * tp_w1[i2 * TEMB + tid];
            sm[OFF_RHOIN + 12 + tid] = a;
        }
        __syncthreads();

        // ================= rho MLP (28 -> 64 -> 64 -> 1) =================
        if (tid < HID) {
            float a = rho_b0[tid];
            #pragma unroll 4
            for (int i2 = 0; i2 < RHOIN; i2++)
                a += sm[OFF_RHOIN + i2] * rho_w0[i2 * HID + tid];
            sm[OFF_RH0 + tid] = gelu_f(a);
        }
        __syncthreads();
        float part = 0.f;
        if (tid < HID) {
            float a = rho_b1[tid];
            #pragma unroll 4
            for (int k = 0; k < HID; k++)
                a += sm[OFF_RH0 + k] * rho_w1[k * HID + tid];
            part = gelu_f(a) * rho_w2[tid];
        }
        float osum = blockReduceSum(part, sm + OFF_RED);
        if (tid == 0) out[b] = osum + rho_b2[0] + sm[OFF_MISC + 0];
        __syncthreads();
    }
}

extern "C" void kernel_launch(void* const* d_in, const int* in_sizes, int n_in,
                              void* d_out, int out_size) {
    const float* x      = (const float*)d_in[0];
    const float* tau    = (const float*)d_in[1];
    const float* freqs  = (const float*)d_in[2];
    const float* phi_w0 = (const float*)d_in[3];
    const float* phi_b0 = (const float*)d_in[4];
    const float* phi_w1 = (const float*)d_in[5];
    const float* phi_b1 = (const float*)d_in[6];
    const float* phi_w2 = (const float*)d_in[7];
    const float* phi_b2 = (const float*)d_in[8];
    const float* psi_w0 = (const float*)d_in[9];
    const float* psi_b0 = (const float*)d_in[10];
    const float* psi_w1 = (const float*)d_in[11];
    const float* psi_b1 = (const float*)d_in[12];
    const float* psi_w2 = (const float*)d_in[13];
    const float* psi_b2 = (const float*)d_in[14];
    const float* rho_w0 = (const float*)d_in[15];
    const float* rho_b0 = (const float*)d_in[16];
    const float* rho_w1 = (const float*)d_in[17];
    const float* rho_b1 = (const float*)d_in[18];
    const float* rho_w2 = (const float*)d_in[19];
    const float* rho_b2 = (const float*)d_in[20];
    const float* tp_w0  = (const float*)d_in[21];
    const float* tp_b0  = (const float*)d_in[22];
    const float* tp_w1  = (const float*)d_in[23];
    const float* tp_b1  = (const float*)d_in[24];
    float* out = (float*)d_out;

    const int Btot = in_sizes[1];
    const int nblocks = (Btot + BPB - 1) / BPB;

    cudaFuncSetAttribute(tau_jastrow_kernel,
                         cudaFuncAttributeMaxDynamicSharedMemorySize, SMEM_BYTES);

    tau_jastrow_kernel<<<nblocks, NTHREADS, SMEM_BYTES>>>(
        x, tau, freqs,
        phi_w0, phi_b0, phi_w1, phi_b1, phi_w2, phi_b2,
        psi_w0, psi_b0, psi_w1, psi_b1, psi_w2, psi_b2,
        rho_w0, rho_b0, rho_w1, rho_b1, rho_w2, rho_b2,
        tp_w0, tp_b0, tp_w1, tp_b1,
        out, Btot);
}

// round 7
// speedup vs baseline: 1.1054x; 1.1054x over previous
#include <cuda_runtime.h>
#include <math.h>

#define NPART 16
#define DDIM 3
#define HID 64
#define DLAT 5
#define TEMB 16
#define NFREQ 8
#define NPAIR 120
#define RHOIN 28
#define NTHREADS 128
#define BPB 4

typedef unsigned long long ull;

// ---- dynamic smem layout (float offsets) ----
#define OFF_PSI_W1T 0          // [16][64][4] k-tiled transposed psi W1 (4096)
#define OFF_H0S     4096       // psi h0 transposed [kt][kc][128] (8192); phi h0 [kt][16]f4 at +0; phi W1T at +4096
#define OFF_PHI_W1T (OFF_H0S + 4096)
// tail scratch aliases the (dead) H0S region:
#define OFF_TTF     OFF_H0S          // 4 x 17 = 68
#define OFF_THT     (OFF_H0S + 128)  // 4 x 16 = 64
#define OFF_TRH0    (OFF_H0S + 384)  // 4 x 64 = 256
#define OFF_PSI_W0  12288      // [6][64] (384)
#define OFF_PSI_B0  12672      // (64)
#define OFF_PSI_B1  12736      // (64)
#define OFF_PSI_W2  12800      // [64][5] (320)
#define OFF_PSI_B2  13120      // (8)
#define OFF_PHI_W0  13128      // [3][64] (192)
#define OFF_PHI_B0  13320      // (64)
#define OFF_PHI_B1  13384      // (64)
#define OFF_PHI_W2  13448      // (320)
#define OFF_PHI_B2  13768      // (8)
#define OFF_X       13776      // (48)
#define OFF_GATE    13824      // (128, rows 120..127 = 0)
#define OFF_RED     13952      // (56)
#define OFF_RHOIN4  14008      // 4 x 28 (112)
#define OFF_CUSP    14120      // (4)
#define SMEM_FLOATS 14124
#define SMEM_BYTES  (SMEM_FLOATS * 4)

// ---- packed f32x2 helpers ----
__device__ __forceinline__ ull pack2(float lo, float hi) {
    ull r; asm("mov.b64 %0, {%1, %2};" : "=l"(r) : "f"(lo), "f"(hi)); return r;
}
__device__ __forceinline__ ull dup2(float b) {
    ull r; asm("mov.b64 %0, {%1, %1};" : "=l"(r) : "f"(b)); return r;
}
__device__ __forceinline__ float2 unpack2(ull v) {
    float2 f; asm("mov.b64 {%0, %1}, %2;" : "=f"(f.x), "=f"(f.y) : "l"(v)); return f;
}
__device__ __forceinline__ void ffma2(ull& d, ull a, ull b) {
    asm("fma.rn.f32x2 %0, %1, %2, %0;" : "+l"(d) : "l"(a), "l"(b));
}
__device__ __forceinline__ ull fma2(ull a, ull b, ull c) {
    ull d; asm("fma.rn.f32x2 %0, %1, %2, %3;" : "=l"(d) : "l"(a), "l"(b), "l"(c)); return d;
}
__device__ __forceinline__ ull mul2(ull a, ull b) {
    ull d; asm("mul.rn.f32x2 %0, %1, %2;" : "=l"(d) : "l"(a), "l"(b)); return d;
}
__device__ __forceinline__ ull add2(ull a, ull b) {
    ull d; asm("add.rn.f32x2 %0, %1, %2;" : "=l"(d) : "l"(a), "l"(b)); return d;
}

// ---- gelu: A&S 7.1.26 erf (|err|<=1.5e-7), branchless (R5 form; EX2 on MUFU pipe)
__device__ __forceinline__ float gelu_f(float x) {
    float ax = fabsf(x);
    float z = ax * 0.70710678118f;
    float t = __fdividef(1.0f, fmaf(0.3275911f, z, 1.0f));
    float p = t * fmaf(t, fmaf(t, fmaf(t, fmaf(t, 1.061405429f, -1.453152027f),
                         1.421413741f), -0.284496736f), 0.254829592f);
    float q = p * exp2f(-1.442695041f * z * z);
    return 0.5f * ((x + ax) - ax * q);
}

__device__ __forceinline__ ull gelu2(ull x2) {
    ull ax2;
    asm("and.b64 %0, %1, %2;" : "=l"(ax2) : "l"(x2), "l"(0x7fffffff7fffffffULL));
    ull z2 = mul2(ax2, dup2(0.70710678118f));
    float2 z = unpack2(z2);
    float tx = __fdividef(1.0f, fmaf(0.3275911f, z.x, 1.0f));
    float ty = __fdividef(1.0f, fmaf(0.3275911f, z.y, 1.0f));
    ull t2 = pack2(tx, ty);
    ull p2 = fma2(t2, dup2(1.061405429f), dup2(-1.453152027f));
    p2 = fma2(p2, t2, dup2(1.421413741f));
    p2 = fma2(p2, t2, dup2(-0.284496736f));
    p2 = fma2(p2, t2, dup2(0.254829592f));
    p2 = mul2(p2, t2);
    float2 m = unpack2(mul2(mul2(z2, z2), dup2(-1.442695041f)));
    ull q2 = mul2(p2, pack2(exp2f(m.x), exp2f(m.y)));
    ull s2 = add2(x2, ax2);
    ull w2 = mul2(ax2, q2);
    return fma2(w2, dup2(-0.5f), mul2(s2, dup2(0.5f)));
}

__global__ __launch_bounds__(NTHREADS, 4)
void tau_jastrow_kernel(
    const float* __restrict__ x, const float* __restrict__ tau, const float* __restrict__ freqs,
    const float* __restrict__ phi_w0, const float* __restrict__ phi_b0,
    const float* __restrict__ phi_w1, const float* __restrict__ phi_b1,
    const float* __restrict__ phi_w2, const float* __restrict__ phi_b2,
    const float* __restrict__ psi_w0, const float* __restrict__ psi_b0,
    const float* __restrict__ psi_w1, const float* __restrict__ psi_b1,
    const float* __restrict__ psi_w2, const float* __restrict__ psi_b2,
    const float* __restrict__ rho_w0, const float* __restrict__ rho_b0,
    const float* __restrict__ rho_w1, const float* __restrict__ rho_b1,
    const float* __restrict__ rho_w2, const float* __restrict__ rho_b2,
    const float* __restrict__ tp_w0, const float* __restrict__ tp_b0,
    const float* __restrict__ tp_w1, const float* __restrict__ tp_b1,
    float* __restrict__ out, int Btot)
{
    extern __shared__ float sm[];
    const int tid = threadIdx.x;

    // ---- preload psi weights (once per block) ----
    for (int idx = tid; idx < HID * HID; idx += NTHREADS) {
        int k = idx >> 6, j = idx & 63;
        sm[OFF_PSI_W1T + (k >> 2) * 256 + j * 4 + (k & 3)] = psi_w1[idx];
    }
    for (int i = tid; i < 6 * HID; i += NTHREADS) sm[OFF_PSI_W0 + i] = psi_w0[i];
    for (int i = tid; i < 3 * HID; i += NTHREADS) sm[OFF_PHI_W0 + i] = phi_w0[i];
    for (int i = tid; i < HID * DLAT; i += NTHREADS) {
        sm[OFF_PSI_W2 + i] = psi_w2[i];
        sm[OFF_PHI_W2 + i] = phi_w2[i];
    }
    if (tid < HID) {
        sm[OFF_PSI_B0 + tid] = psi_b0[tid]; sm[OFF_PSI_B1 + tid] = psi_b1[tid];
        sm[OFF_PHI_B0 + tid] = phi_b0[tid]; sm[OFF_PHI_B1 + tid] = phi_b1[tid];
    }
    if (tid < DLAT) {
        sm[OFF_PSI_B2 + tid] = psi_b2[tid];
        sm[OFF_PHI_B2 + tid] = phi_b2[tid];
    }
    if (tid >= NPAIR) sm[OFF_GATE + tid] = 0.f;   // padded rows: gate = 0, persists

    // ---- pair indices (triu k=1 row-major) ----
    int pi = 0, pj = 0;
    {
        int p2 = tid, i2 = 0, cnt = NPART - 1;
        while (cnt > 0 && p2 >= cnt) { p2 -= cnt; i2++; cnt--; }
        pi = i2; pj = i2 + 1 + p2;
        if (pj >= NPART) pj = NPART - 1;
    }
    const bool active = (tid < NPAIR);
    const float gamma = ((pi < NPART / 2) == (pj < NPART / 2))
                        ? (1.0f / (DDIM + 1)) : (1.0f / (DDIM - 1));

    const int base = blockIdx.x * BPB;
    const int nb = (Btot - base < BPB) ? (Btot - base) : BPB;

    for (int bi = 0; bi < nb; ++bi) {
        const int b = base + bi;
        if (tid < NPART * DDIM) sm[OFF_X + tid] = x[(size_t)b * (NPART * DDIM) + tid];
        __syncthreads();

        float vals[14];
        #pragma unroll
        for (int v = 0; v < 14; v++) vals[v] = 0.f;

        // ================= Phase A: psi pair features + h0 (packed, transposed store) =================
        if (active) {
            float d0 = sm[OFF_X + pi * 3 + 0] - sm[OFF_X + pj * 3 + 0];
            float d1 = sm[OFF_X + pi * 3 + 1] - sm[OFF_X + pj * 3 + 1];
            float d2 = sm[OFF_X + pi * 3 + 2] - sm[OFF_X + pj * 3 + 2];
            float r2 = d0 * d0 + d1 * d1 + d2 * d2;
            float r = sqrtf(r2 + 1.1920929e-7f);
            float rt2 = r2 + 0.04f;
            float u = rt2 * 25.0f;
            float tt = __fdividef(1.0f, 1.0f + u);
            float feat[6];
            float s1v = -__logf(tt);
            feat[0] = s1v;
            feat[1] = __fdividef(r2, rt2);
            feat[2] = u * __expf(-u);
            feat[4] = tt;                        // exp(-s1)
            float t2v = tt * tt;
            feat[5] = t2v * t2v;                 // exp(-4 s1)
            feat[3] = sqrtf(sqrtf(tt));          // exp(-0.25 s1)
            float gatev = __fdividef(r2, r2 + 0.09f);
            sm[OFF_GATE + tid] = gatev;
            vals[5] = gatev;
            vals[6] = s1v;
            vals[7] = gamma * r * __expf(-r);

            ull feat2[6];
            #pragma unroll
            for (int i = 0; i < 6; i++) feat2[i] = dup2(feat[i]);

            const ulonglong2* w0p = (const ulonglong2*)(sm + OFF_PSI_W0);
            const ulonglong2* b0p = (const ulonglong2*)(sm + OFF_PSI_B0);
            #pragma unroll 2
            for (int kt = 0; kt < 16; kt++) {
                ulonglong2 bb = b0p[kt];
                ull alo = bb.x, ahi = bb.y;
                #pragma unroll
                for (int i = 0; i < 6; i++) {
                    ulonglong2 ww = w0p[i * 16 + kt];
                    alo = fma2(feat2[i], ww.x, alo);
                    ahi = fma2(feat2[i], ww.y, ahi);
                }
                float2 g0 = unpack2(gelu2(alo));
                float2 g1 = unpack2(gelu2(ahi));
                float* dst = sm + OFF_H0S + kt * 512 + tid;
                dst[0]   = g0.x;
                dst[128] = g0.y;
                dst[256] = g1.x;
                dst[384] = g1.y;
            }
        } else {
            #pragma unroll
            for (int kt = 0; kt < 16; kt++) {
                float* dst = sm + OFF_H0S + kt * 512 + tid;
                dst[0] = 0.f; dst[128] = 0.f; dst[256] = 0.f; dst[384] = 0.f;
            }
        }
        __syncthreads();

        // ================= psi h1 GEMM, packed f32x2 (128x64 @ 64x64) =================
        {
            const int rg = tid >> 4, cg = tid & 15;
            const int r0 = rg * 16;
            ull acc[8][4];
            #pragma unroll
            for (int c = 0; c < 4; c++) {
                ull bi2 = dup2(sm[OFF_PSI_B1 + cg + 16 * c]);
                #pragma unroll
                for (int q = 0; q < 8; q++) acc[q][c] = bi2;
            }
            const float4* w1t4 = (const float4*)(sm + OFF_PSI_W1T);
            #pragma unroll 1
            for (int kt = 0; kt < 16; kt++) {
                float4 bv0 = w1t4[kt * 64 + cg];
                float4 bv1 = w1t4[kt * 64 + cg + 16];
                float4 bv2 = w1t4[kt * 64 + cg + 32];
                float4 bv3 = w1t4[kt * 64 + cg + 48];
                const float* hbase = sm + OFF_H0S + kt * 512 + r0;
                #define KC_STEP(kc, comp)                                           \
                {                                                                   \
                    ull b20 = dup2(bv0.comp);                                       \
                    ull b21 = dup2(bv1.comp);                                       \
                    ull b22 = dup2(bv2.comp);                                       \
                    ull b23 = dup2(bv3.comp);                                       \
                    const ulonglong2* ap =                                          \
                        (const ulonglong2*)(hbase + (kc) * 128);                    \
                    _Pragma("unroll")                                               \
                    for (int q2 = 0; q2 < 4; q2++) {                                \
                        ulonglong2 aa = ap[q2];                                     \
                        ffma2(acc[2 * q2][0], aa.x, b20);                           \
                        ffma2(acc[2 * q2][1], aa.x, b21);                           \
                        ffma2(acc[2 * q2][2], aa.x, b22);                           \
                        ffma2(acc[2 * q2][3], aa.x, b23);                           \
                        ffma2(acc[2 * q2 + 1][0], aa.y, b20);                       \
                        ffma2(acc[2 * q2 + 1][1], aa.y, b21);                       \
                        ffma2(acc[2 * q2 + 1][2], aa.y, b22);                       \
                        ffma2(acc[2 * q2 + 1][3], aa.y, b23);                       \
                    }                                                               \
                }
                KC_STEP(0, x) KC_STEP(1, y) KC_STEP(2, z) KC_STEP(3, w)
                #undef KC_STEP
            }
            // epilogue: packed gelu -> gate -> W2 -> scalar partial sums (R5 form)
            const ull* gt2p = (const ull*)(sm + OFF_GATE + r0);
            #pragma unroll
            for (int c = 0; c < 4; c++) {
                const int j = cg + 16 * c;
                float w2r[5];
                #pragma unroll
                for (int d = 0; d < 5; d++) w2r[d] = sm[OFF_PSI_W2 + j * 5 + d];
                #pragma unroll
                for (int q = 0; q < 8; q++) {
                    ull pr = mul2(gelu2(acc[q][c]), gt2p[q]);
                    float2 prf = unpack2(pr);
                    float g = prf.x + prf.y;
                    #pragma unroll
                    for (int d = 0; d < 5; d++) vals[d] += g * w2r[d];
                }
            }
        }
        __syncthreads();  // h0s region about to be reused by phi

        // ===== phi W1T reload (into h0s upper half) + phi h0 =====
        {
            const float4* gw = (const float4*)phi_w1;
            #pragma unroll
            for (int i = 0; i < 8; i++) {
                int idx4 = tid + 128 * i;
                float4 v = gw[idx4];
                int k = idx4 >> 4;
                int j0 = (idx4 & 15) * 4;
                float* d = sm + OFF_PHI_W1T + (k >> 2) * 256 + (k & 3) + j0 * 4;
                d[0] = v.x; d[4] = v.y; d[8] = v.z; d[12] = v.w;
            }
        }
        {
            int p = tid >> 3, c3 = tid & 7;
            float xv0 = sm[OFF_X + p * 3 + 0];
            float xv1 = sm[OFF_X + p * 3 + 1];
            float xv2 = sm[OFF_X + p * 3 + 2];
            const float4* w0 = (const float4*)(sm + OFF_PHI_W0);
            const float4* b0 = (const float4*)(sm + OFF_PHI_B0);
            float4* h0w = (float4*)(sm + OFF_H0S);
            #pragma unroll
            for (int t = 0; t < 2; t++) {
                int kt = 2 * c3 + t;
                float4 a = b0[kt];
                float4 w;
                w = w0[0 * 16 + kt];
                a.x += xv0 * w.x; a.y += xv0 * w.y; a.z += xv0 * w.z; a.w += xv0 * w.w;
                w = w0[1 * 16 + kt];
                a.x += xv1 * w.x; a.y += xv1 * w.y; a.z += xv1 * w.z; a.w += xv1 * w.w;
                w = w0[2 * 16 + kt];
                a.x += xv2 * w.x; a.y += xv2 * w.y; a.z += xv2 * w.z; a.w += xv2 * w.w;
                a.x = gelu_f(a.x); a.y = gelu_f(a.y);
                a.z = gelu_f(a.z); a.w = gelu_f(a.w);
                h0w[kt * 16 + p] = a;
            }
        }
        __syncthreads();

        // ================= Phi h1 GEMM (16x64 @ 64x64, R5 scalar form) =================
        {
            int row = tid >> 3, cg = tid & 7;
            float acc8[8];
            #pragma unroll
            for (int c = 0; c < 8; c++) acc8[c] = sm[OFF_PHI_B1 + cg + 8 * c];
            const float4* w1t = (const float4*)(sm + OFF_PHI_W1T);
            const float4* h0 = (const float4*)(sm + OFF_H0S);
            #pragma unroll 2
            for (int kt = 0; kt < 16; kt++) {
                float4 a = h0[kt * 16 + row];
                #pragma unroll
                for (int c = 0; c < 8; c++) {
                    float4 bv = w1t[kt * 64 + cg + 8 * c];
                    acc8[c] += a.x * bv.x; acc8[c] += a.y * bv.y;
                    acc8[c] += a.z * bv.z; acc8[c] += a.w * bv.w;
                }
            }
            #pragma unroll
            for (int c = 0; c < 8; c++) {
                float g = gelu_f(acc8[c]);
                #pragma unroll
                for (int d = 0; d < 5; d++)
                    vals[8 + d] += g * sm[OFF_PHI_W2 + (cg + 8 * c) * 5 + d];
            }
        }
        if (tid < NPART * DDIM) {
            float xv = sm[OFF_X + tid];
            vals[13] = xv * xv;
        }

        // ================= fused 14-value block reduction =================
        {
            const int lane = tid & 31, wid = tid >> 5;
            #pragma unroll
            for (int v = 0; v < 14; v++) {
                float t = vals[v];
                #pragma unroll
                for (int o = 16; o > 0; o >>= 1)
                    t += __shfl_down_sync(0xffffffffu, t, o);
                if (lane == 0) sm[OFF_RED + v * 4 + wid] = t;
            }
        }
        __syncthreads();
        if (tid < 14) {
            float s = sm[OFF_RED + tid * 4 + 0] + sm[OFF_RED + tid * 4 + 1]
                    + sm[OFF_RED + tid * 4 + 2] + sm[OFF_RED + tid * 4 + 3];
            float* rin = sm + OFF_RHOIN4 + bi * 28;
            if (tid < 5) {
                float gs = sm[OFF_RED + 20] + sm[OFF_RED + 21]
                         + sm[OFF_RED + 22] + sm[OFF_RED + 23];
                rin[5 + tid] = (s + sm[OFF_PSI_B2 + tid] * gs) * (1.0f / NPAIR);
            } else if (tid == 6) {
                rin[11] = s * (1.0f / NPAIR);
            } else if (tid == 7) {
                sm[OFF_CUSP + bi] = s;
            } else if (tid >= 8 && tid < 13) {
                rin[tid - 8] = s * (1.0f / NPART) + sm[OFF_PHI_B2 + tid - 8];
            } else if (tid == 13) {
                rin[10] = s * (1.0f / (NPART * DDIM));
            }
        }
        // no sync needed here: next iteration's first sync orders these writes
    }

    // ================= batched tail: temb + rho for all nb batches =================
    // tail scratch aliases H0S (all H0S reads completed before last loop sync)
    if (tid < 4 && tid < nb) sm[OFF_TTF + tid * 17] = tau[base + tid];
    if (tid < 32) {
        int q = tid >> 3, i = tid & 7;
        if (q < nb) {
            float t = tau[base + q];
            float ft = freqs[i] * t;
            sm[OFF_TTF + q * 17 + 1 + i] = __sinf(ft);
            sm[OFF_TTF + q * 17 + 9 + i] = __cosf(ft);
        }
    }
    __syncthreads();
    if (tid < 64) {
        int q = tid >> 4, j = tid & 15;
        float a = tp_b0[j];
        #pragma unroll
        for (int i = 0; i < 2 * NFREQ + 1; i++)
            a += sm[OFF_TTF + q * 17 + i] * tp_w0[i * TEMB + j];
        sm[OFF_THT + q * 16 + j] = gelu_f(a);
    }
    __syncthreads();
    if (tid < 64) {
        int q = tid >> 4, j = tid & 15;
        float a = tp_b1[j];
        #pragma unroll
        for (int i = 0; i < TEMB; i++)
            a += sm[OFF_THT + q * 16 + i] * tp_w1[i * TEMB + j];
        sm[OFF_RHOIN4 + q * 28 + 12 + j] = a;
    }
    __syncthreads();
    // rho h0: 256 outputs, 2 per thread
    #pragma unroll
    for (int s = 0; s < 2; s++) {
        int idx = tid + s * 128;
        int q = idx >> 6, j = idx & 63;
        float a = rho_b0[j];
        const float* rin = sm + OFF_RHOIN4 + q * 28;
        #pragma unroll 4
        for (int i = 0; i < RHOIN; i++) a += rin[i] * rho_w0[i * HID + j];
        sm[OFF_TRH0 + q * 64 + j] = gelu_f(a);
    }
    __syncthreads();
    // rho h1 + w2, then per-batch reduce
    float part[2];
    #pragma unroll
    for (int s = 0; s < 2; s++) {
        int idx = tid + s * 128;
        int q = idx >> 6, j = idx & 63;
        float a = rho_b1[j];
        const float* rh = sm + OFF_TRH0 + q * 64;
        #pragma unroll 4
        for (int k = 0; k < HID; k++) a += rh[k] * rho_w1[k * HID + j];
        part[s] = gelu_f(a) * rho_w2[j];
    }
    {
        const int lane = tid & 31, wid = tid >> 5;
        #pragma unroll
        for (int o = 16; o > 0; o >>= 1) {
            part[0] += __shfl_down_sync(0xffffffffu, part[0], o);
            part[1] += __shfl_down_sync(0xffffffffu, part[1], o);
        }
        if (lane == 0) { sm[OFF_RED + wid] = part[0]; sm[OFF_RED + 4 + wid] = part[1]; }
    }
    __syncthreads();
    if (tid < 4 && tid < nb) {
        // batch q partial sums live in sRed[2q], sRed[2q+1]
        float ssum = sm[OFF_RED + 2 * tid] + sm[OFF_RED + 2 * tid + 1];
        out[base + tid] = ssum + rho_b2[0] + sm[OFF_CUSP + tid];
    }
}

extern "C" void kernel_launch(void* const* d_in, const int* in_sizes, int n_in,
                              void* d_out, int out_size) {
    const float* x      = (const float*)d_in[0];
    const float* tau    = (const float*)d_in[1];
    const float* freqs  = (const float*)d_in[2];
    const float* phi_w0 = (const float*)d_in[3];
    const float* phi_b0 = (const float*)d_in[4];
    const float* phi_w1 = (const float*)d_in[5];
    const float* phi_b1 = (const float*)d_in[6];
    const float* phi_w2 = (const float*)d_in[7];
    const float* phi_b2 = (const float*)d_in[8];
    const float* psi_w0 = (const float*)d_in[9];
    const float* psi_b0 = (const float*)d_in[10];
    const float* psi_w1 = (const float*)d_in[11];
    const float* psi_b1 = (const float*)d_in[12];
    const float* psi_w2 = (const float*)d_in[13];
    const float* psi_b2 = (const float*)d_in[14];
    const float* rho_w0 = (const float*)d_in[15];
    const float* rho_b0 = (const float*)d_in[16];
    const float* rho_w1 = (const float*)d_in[17];
    const float* rho_b1 = (const float*)d_in[18];
    const float* rho_w2 = (const float*)d_in[19];
    const float* rho_b2 = (const float*)d_in[20];
    const float* tp_w0  = (const float*)d_in[21];
    const float* tp_b0  = (const float*)d_in[22];
    const float* tp_w1  = (const float*)d_in[23];
    const float* tp_b1  = (const float*)d_in[24];
    float* out = (float*)d_out;

    const int Btot = in_sizes[1];
    const int nblocks = (Btot + BPB - 1) / BPB;

    cudaFuncSetAttribute(tau_jastrow_kernel,
                         cudaFuncAttributeMaxDynamicSharedMemorySize, SMEM_BYTES);

    tau_jastrow_kernel<<<nblocks, NTHREADS, SMEM_BYTES>>>(
        x, tau, freqs,
        phi_w0, phi_b0, phi_w1, phi_b1, phi_w2, phi_b2,
        psi_w0, psi_b0, psi_w1, psi_b1, psi_w2, psi_b2,
        rho_w0, rho_b0, rho_w1, rho_b1, rho_w2, rho_b2,
        tp_w0, tp_b0, tp_w1, tp_b1,
        out, Btot);
}

// round 8
// speedup vs baseline: 1.2146x; 1.0988x over previous
#include <cuda_runtime.h>
#include <math.h>

#define NPART 16
#define DDIM 3
#define HID 64
#define DLAT 5
#define TEMB 16
#define NFREQ 8
#define NPAIR 120
#define RHOIN 28
#define NTHREADS 128
#define BPB 4

typedef unsigned long long ull;

// ---- dynamic smem layout (float offsets) ----
#define OFF_PSI_W1T 0          // [16][64][4] k-tiled transposed psi W1 (4096)
#define OFF_H0S     4096       // psi h0 transposed [kt][kc][128] (8192)
// tail: phi h0 [16][64] float4 at OFF_H0S (4096); phi W1T at +4096
#define OFF_PHI_W1T (OFF_H0S + 4096)
// tail temb/rho scratch aliases H0S (dead after phi GEMM):
#define OFF_TTF     OFF_H0S          // 4 x 17
#define OFF_THT     (OFF_H0S + 128)  // 4 x 16
#define OFF_TRH0    (OFF_H0S + 384)  // 4 x 64
#define OFF_PSI_W0  12288      // [6][64] (384)
#define OFF_PSI_B0  12672      // (64)
#define OFF_PSI_B1  12736      // (64)
#define OFF_PSI_W2  12800      // [64][5] (320)
#define OFF_PSI_B2  13120      // (8)
#define OFF_PHI_W0  13128      // [3][64] (192)
#define OFF_PHI_B0  13320      // (64)
#define OFF_PHI_B1  13384      // (64)
#define OFF_PHI_W2  13448      // (320)
#define OFF_PHI_B2  13768      // (8)
#define OFF_X       13776      // (48)
#define OFF_GATE    13824      // (128, rows 120..127 = 0)
#define OFF_RED     13952      // (56)
#define OFF_RHOIN4  14008      // 4 x 28 (112)
#define OFF_CUSP    14120      // (4)
#define SMEM_FLOATS 14124
#define SMEM_BYTES  (SMEM_FLOATS * 4)

// ---- packed f32x2 helpers ----
__device__ __forceinline__ ull pack2(float lo, float hi) {
    ull r; asm("mov.b64 %0, {%1, %2};" : "=l"(r) : "f"(lo), "f"(hi)); return r;
}
__device__ __forceinline__ ull dup2(float b) {
    ull r; asm("mov.b64 %0, {%1, %1};" : "=l"(r) : "f"(b)); return r;
}
__device__ __forceinline__ float2 unpack2(ull v) {
    float2 f; asm("mov.b64 {%0, %1}, %2;" : "=f"(f.x), "=f"(f.y) : "l"(v)); return f;
}
__device__ __forceinline__ void ffma2(ull& d, ull a, ull b) {
    asm("fma.rn.f32x2 %0, %1, %2, %0;" : "+l"(d) : "l"(a), "l"(b));
}
__device__ __forceinline__ ull fma2(ull a, ull b, ull c) {
    ull d; asm("fma.rn.f32x2 %0, %1, %2, %3;" : "=l"(d) : "l"(a), "l"(b), "l"(c)); return d;
}
__device__ __forceinline__ ull mul2(ull a, ull b) {
    ull d; asm("mul.rn.f32x2 %0, %1, %2;" : "=l"(d) : "l"(a), "l"(b)); return d;
}
__device__ __forceinline__ ull add2(ull a, ull b) {
    ull d; asm("add.rn.f32x2 %0, %1, %2;" : "=l"(d) : "l"(a), "l"(b)); return d;
}

// ---- gelu: A&S 7.1.26 erf (|err|<=1.5e-7), branchless (EX2 on MUFU pipe)
__device__ __forceinline__ float gelu_f(float x) {
    float ax = fabsf(x);
    float z = ax * 0.70710678118f;
    float t = __fdividef(1.0f, fmaf(0.3275911f, z, 1.0f));
    float p = t * fmaf(t, fmaf(t, fmaf(t, fmaf(t, 1.061405429f, -1.453152027f),
                         1.421413741f), -0.284496736f), 0.254829592f);
    float q = p * exp2f(-1.442695041f * z * z);
    return 0.5f * ((x + ax) - ax * q);
}

__device__ __forceinline__ ull gelu2(ull x2) {
    ull ax2;
    asm("and.b64 %0, %1, %2;" : "=l"(ax2) : "l"(x2), "l"(0x7fffffff7fffffffULL));
    ull z2 = mul2(ax2, dup2(0.70710678118f));
    float2 z = unpack2(z2);
    float tx = __fdividef(1.0f, fmaf(0.3275911f, z.x, 1.0f));
    float ty = __fdividef(1.0f, fmaf(0.3275911f, z.y, 1.0f));
    ull t2 = pack2(tx, ty);
    ull p2 = fma2(t2, dup2(1.061405429f), dup2(-1.453152027f));
    p2 = fma2(p2, t2, dup2(1.421413741f));
    p2 = fma2(p2, t2, dup2(-0.284496736f));
    p2 = fma2(p2, t2, dup2(0.254829592f));
    p2 = mul2(p2, t2);
    float2 m = unpack2(mul2(mul2(z2, z2), dup2(-1.442695041f)));
    ull q2 = mul2(p2, pack2(exp2f(m.x), exp2f(m.y)));
    ull s2 = add2(x2, ax2);
    ull w2 = mul2(ax2, q2);
    return fma2(w2, dup2(-0.5f), mul2(s2, dup2(0.5f)));
}

__global__ __launch_bounds__(NTHREADS, 4)
void tau_jastrow_kernel(
    const float* __restrict__ x, const float* __restrict__ tau, const float* __restrict__ freqs,
    const float* __restrict__ phi_w0, const float* __restrict__ phi_b0,
    const float* __restrict__ phi_w1, const float* __restrict__ phi_b1,
    const float* __restrict__ phi_w2, const float* __restrict__ phi_b2,
    const float* __restrict__ psi_w0, const float* __restrict__ psi_b0,
    const float* __restrict__ psi_w1, const float* __restrict__ psi_b1,
    const float* __restrict__ psi_w2, const float* __restrict__ psi_b2,
    const float* __restrict__ rho_w0, const float* __restrict__ rho_b0,
    const float* __restrict__ rho_w1, const float* __restrict__ rho_b1,
    const float* __restrict__ rho_w2, const float* __restrict__ rho_b2,
    const float* __restrict__ tp_w0, const float* __restrict__ tp_b0,
    const float* __restrict__ tp_w1, const float* __restrict__ tp_b1,
    float* __restrict__ out, int Btot)
{
    extern __shared__ float sm[];
    const int tid = threadIdx.x;

    // ---- preload psi + small weights (once per block) ----
    for (int idx = tid; idx < HID * HID; idx += NTHREADS) {
        int k = idx >> 6, j = idx & 63;
        sm[OFF_PSI_W1T + (k >> 2) * 256 + j * 4 + (k & 3)] = psi_w1[idx];
    }
    for (int i = tid; i < 6 * HID; i += NTHREADS) sm[OFF_PSI_W0 + i] = psi_w0[i];
    for (int i = tid; i < 3 * HID; i += NTHREADS) sm[OFF_PHI_W0 + i] = phi_w0[i];
    for (int i = tid; i < HID * DLAT; i += NTHREADS) {
        sm[OFF_PSI_W2 + i] = psi_w2[i];
        sm[OFF_PHI_W2 + i] = phi_w2[i];
    }
    if (tid < HID) {
        sm[OFF_PSI_B0 + tid] = psi_b0[tid]; sm[OFF_PSI_B1 + tid] = psi_b1[tid];
        sm[OFF_PHI_B0 + tid] = phi_b0[tid]; sm[OFF_PHI_B1 + tid] = phi_b1[tid];
    }
    if (tid < DLAT) {
        sm[OFF_PSI_B2 + tid] = psi_b2[tid];
        sm[OFF_PHI_B2 + tid] = phi_b2[tid];
    }
    if (tid >= NPAIR) sm[OFF_GATE + tid] = 0.f;   // padded rows: gate = 0, persists

    // ---- pair indices (triu k=1 row-major) ----
    int pi = 0, pj = 0;
    {
        int p2 = tid, i2 = 0, cnt = NPART - 1;
        while (cnt > 0 && p2 >= cnt) { p2 -= cnt; i2++; cnt--; }
        pi = i2; pj = i2 + 1 + p2;
        if (pj >= NPART) pj = NPART - 1;
    }
    const bool active = (tid < NPAIR);
    const float gamma = ((pi < NPART / 2) == (pj < NPART / 2))
                        ? (1.0f / (DDIM + 1)) : (1.0f / (DDIM - 1));

    const int base = blockIdx.x * BPB;
    const int nb = (Btot - base < BPB) ? (Btot - base) : BPB;

    // ======================= per-batch main loop (psi only) =======================
    for (int bi = 0; bi < nb; ++bi) {
        const int b = base + bi;
        if (tid < NPART * DDIM) sm[OFF_X + tid] = x[(size_t)b * (NPART * DDIM) + tid];
        __syncthreads();

        float vals[9];
        #pragma unroll
        for (int v = 0; v < 9; v++) vals[v] = 0.f;
        if (tid < NPART * DDIM) {
            float xv = sm[OFF_X + tid];
            vals[8] = xv * xv;
        }

        // ---- Phase A: pair features + psi h0 (packed, transposed store) ----
        if (active) {
            float d0 = sm[OFF_X + pi * 3 + 0] - sm[OFF_X + pj * 3 + 0];
            float d1 = sm[OFF_X + pi * 3 + 1] - sm[OFF_X + pj * 3 + 1];
            float d2 = sm[OFF_X + pi * 3 + 2] - sm[OFF_X + pj * 3 + 2];
            float r2 = d0 * d0 + d1 * d1 + d2 * d2;
            float r = sqrtf(r2 + 1.1920929e-7f);
            float rt2 = r2 + 0.04f;
            float u = rt2 * 25.0f;
            float tt = __fdividef(1.0f, 1.0f + u);
            float feat[6];
            float s1v = -__logf(tt);
            feat[0] = s1v;
            feat[1] = __fdividef(r2, rt2);
            feat[2] = u * __expf(-u);
            feat[4] = tt;                        // exp(-s1)
            float t2v = tt * tt;
            feat[5] = t2v * t2v;                 // exp(-4 s1)
            feat[3] = sqrtf(sqrtf(tt));          // exp(-0.25 s1)
            float gatev = __fdividef(r2, r2 + 0.09f);
            sm[OFF_GATE + tid] = gatev;
            vals[5] = gatev;
            vals[6] = s1v;
            vals[7] = gamma * r * __expf(-r);

            ull feat2[6];
            #pragma unroll
            for (int i = 0; i < 6; i++) feat2[i] = dup2(feat[i]);

            const ulonglong2* w0p = (const ulonglong2*)(sm + OFF_PSI_W0);
            const ulonglong2* b0p = (const ulonglong2*)(sm + OFF_PSI_B0);
            #pragma unroll 2
            for (int kt = 0; kt < 16; kt++) {
                ulonglong2 bb = b0p[kt];
                ull alo = bb.x, ahi = bb.y;
                #pragma unroll
                for (int i = 0; i < 6; i++) {
                    ulonglong2 ww = w0p[i * 16 + kt];
                    alo = fma2(feat2[i], ww.x, alo);
                    ahi = fma2(feat2[i], ww.y, ahi);
                }
                float2 g0 = unpack2(gelu2(alo));
                float2 g1 = unpack2(gelu2(ahi));
                float* dst = sm + OFF_H0S + kt * 512 + tid;
                dst[0]   = g0.x;
                dst[128] = g0.y;
                dst[256] = g1.x;
                dst[384] = g1.y;
            }
        } else {
            #pragma unroll
            for (int kt = 0; kt < 16; kt++) {
                float* dst = sm + OFF_H0S + kt * 512 + tid;
                dst[0] = 0.f; dst[128] = 0.f; dst[256] = 0.f; dst[384] = 0.f;
            }
        }
        __syncthreads();

        // ---- psi h1 GEMM, packed f32x2 (128x64 @ 64x64) ----
        {
            const int rg = tid >> 4, cg = tid & 15;
            const int r0 = rg * 16;
            ull acc[8][4];
            #pragma unroll
            for (int c = 0; c < 4; c++) {
                ull bi2 = dup2(sm[OFF_PSI_B1 + cg + 16 * c]);
                #pragma unroll
                for (int q = 0; q < 8; q++) acc[q][c] = bi2;
            }
            const float4* w1t4 = (const float4*)(sm + OFF_PSI_W1T);
            #pragma unroll 1
            for (int kt = 0; kt < 16; kt++) {
                float4 bv0 = w1t4[kt * 64 + cg];
                float4 bv1 = w1t4[kt * 64 + cg + 16];
                float4 bv2 = w1t4[kt * 64 + cg + 32];
                float4 bv3 = w1t4[kt * 64 + cg + 48];
                const float* hbase = sm + OFF_H0S + kt * 512 + r0;
                #define KC_STEP(kc, comp)                                           \
                {                                                                   \
                    ull b20 = dup2(bv0.comp);                                       \
                    ull b21 = dup2(bv1.comp);                                       \
                    ull b22 = dup2(bv2.comp);                                       \
                    ull b23 = dup2(bv3.comp);                                       \
                    const ulonglong2* ap =                                          \
                        (const ulonglong2*)(hbase + (kc) * 128);                    \
                    _Pragma("unroll")                                               \
                    for (int q2 = 0; q2 < 4; q2++) {                                \
                        ulonglong2 aa = ap[q2];                                     \
                        ffma2(acc[2 * q2][0], aa.x, b20);                           \
                        ffma2(acc[2 * q2][1], aa.x, b21);                           \
                        ffma2(acc[2 * q2][2], aa.x, b22);                           \
                        ffma2(acc[2 * q2][3], aa.x, b23);                           \
                        ffma2(acc[2 * q2 + 1][0], aa.y, b20);                       \
                        ffma2(acc[2 * q2 + 1][1], aa.y, b21);                       \
                        ffma2(acc[2 * q2 + 1][2], aa.y, b22);                       \
                        ffma2(acc[2 * q2 + 1][3], aa.y, b23);                       \
                    }                                                               \
                }
                KC_STEP(0, x) KC_STEP(1, y) KC_STEP(2, z) KC_STEP(3, w)
                #undef KC_STEP
            }
            // epilogue: packed gelu -> gate -> W2 -> scalar partial sums
            const ull* gt2p = (const ull*)(sm + OFF_GATE + r0);
            #pragma unroll
            for (int c = 0; c < 4; c++) {
                const int j = cg + 16 * c;
                float w2r[5];
                #pragma unroll
                for (int d = 0; d < 5; d++) w2r[d] = sm[OFF_PSI_W2 + j * 5 + d];
                #pragma unroll
                for (int q = 0; q < 8; q++) {
                    ull pr = mul2(gelu2(acc[q][c]), gt2p[q]);
                    float2 prf = unpack2(pr);
                    float g = prf.x + prf.y;
                    #pragma unroll
                    for (int d = 0; d < 5; d++) vals[d] += g * w2r[d];
                }
            }
        }

        // ---- fused 9-value block reduction ----
        {
            const int lane = tid & 31, wid = tid >> 5;
            #pragma unroll
            for (int v = 0; v < 9; v++) {
                float t = vals[v];
                #pragma unroll
                for (int o = 16; o > 0; o >>= 1)
                    t += __shfl_down_sync(0xffffffffu, t, o);
                if (lane == 0) sm[OFF_RED + v * 4 + wid] = t;
            }
        }
        __syncthreads();
        if (tid < 9) {
            float s = sm[OFF_RED + tid * 4 + 0] + sm[OFF_RED + tid * 4 + 1]
                    + sm[OFF_RED + tid * 4 + 2] + sm[OFF_RED + tid * 4 + 3];
            float* rin = sm + OFF_RHOIN4 + bi * 28;
            if (tid < 5) {
                float gs = sm[OFF_RED + 20] + sm[OFF_RED + 21]
                         + sm[OFF_RED + 22] + sm[OFF_RED + 23];
                rin[5 + tid] = (s + sm[OFF_PSI_B2 + tid] * gs) * (1.0f / NPAIR);
            } else if (tid == 6) {
                rin[11] = s * (1.0f / NPAIR);
            } else if (tid == 7) {
                sm[OFF_CUSP + bi] = s;
            } else if (tid == 8) {
                rin[10] = s * (1.0f / (NPART * DDIM));
            }
        }
        // next iteration's top sync orders these writes
    }

    // ======================= batched tail =======================
    // ---- stage phi W1T once (into H0S upper half) ----
    {
        const float4* gw = (const float4*)phi_w1;
        #pragma unroll
        for (int i = 0; i < 8; i++) {
            int idx4 = tid + 128 * i;
            float4 v = gw[idx4];
            int k = idx4 >> 4;
            int j0 = (idx4 & 15) * 4;
            float* d = sm + OFF_PHI_W1T + (k >> 2) * 256 + (k & 3) + j0 * 4;
            d[0] = v.x; d[4] = v.y; d[8] = v.z; d[12] = v.w;
        }
    }
    // ---- phi h0 for all nb batches: 64 rows (batch q = R>>4, particle p = R&15) ----
    {
        const int R = tid >> 1, q = R >> 4, p = R & 15, kh = tid & 1;
        const int qq = (q < nb) ? q : 0;
        const float* xb = x + (size_t)(base + qq) * (NPART * DDIM) + p * 3;
        float xv0 = xb[0], xv1 = xb[1], xv2 = xb[2];
        const float4* w0 = (const float4*)(sm + OFF_PHI_W0);
        const float4* b0 = (const float4*)(sm + OFF_PHI_B0);
        float4* h0w = (float4*)(sm + OFF_H0S);
        #pragma unroll
        for (int t8 = 0; t8 < 8; t8++) {
            int kt = kh * 8 + t8;
            float4 a = b0[kt];
            float4 w;
            w = w0[0 * 16 + kt];
            a.x += xv0 * w.x; a.y += xv0 * w.y; a.z += xv0 * w.z; a.w += xv0 * w.w;
            w = w0[1 * 16 + kt];
            a.x += xv1 * w.x; a.y += xv1 * w.y; a.z += xv1 * w.z; a.w += xv1 * w.w;
            w = w0[2 * 16 + kt];
            a.x += xv2 * w.x; a.y += xv2 * w.y; a.z += xv2 * w.z; a.w += xv2 * w.w;
            float2 g01 = unpack2(gelu2(pack2(a.x, a.y)));
            float2 g23 = unpack2(gelu2(pack2(a.z, a.w)));
            h0w[kt * 64 + R] = make_float4(g01.x, g01.y, g23.x, g23.y);
        }
    }
    __syncthreads();
    // ---- phi h1 GEMM (64x64 @ 64x64): thread tile 8 rows x 4 cols; warp w == batch w ----
    {
        const int rg = tid >> 4, cg = tid & 15;   // rg 0..7 (8 rows each), cg 0..15 (4 cols)
        const int q = rg >> 1;                    // batch (== warp id)
        float acc[8][4];
        #pragma unroll
        for (int c = 0; c < 4; c++) {
            float bi1 = sm[OFF_PHI_B1 + cg + 16 * c];
            #pragma unroll
            for (int r = 0; r < 8; r++) acc[r][c] = bi1;
        }
        const float4* w1t4 = (const float4*)(sm + OFF_PHI_W1T);
        const float4* h0f4 = (const float4*)(sm + OFF_H0S);
        #pragma unroll 2
        for (int kt = 0; kt < 16; kt++) {
            float4 bv0 = w1t4[kt * 64 + cg];
            float4 bv1 = w1t4[kt * 64 + cg + 16];
            float4 bv2 = w1t4[kt * 64 + cg + 32];
            float4 bv3 = w1t4[kt * 64 + cg + 48];
            #pragma unroll
            for (int r = 0; r < 8; r++) {
                float4 a = h0f4[kt * 64 + rg * 8 + r];
                acc[r][0] += a.x * bv0.x + a.y * bv0.y + a.z * bv0.z + a.w * bv0.w;
                acc[r][1] += a.x * bv1.x + a.y * bv1.y + a.z * bv1.z + a.w * bv1.w;
                acc[r][2] += a.x * bv2.x + a.y * bv2.y + a.z * bv2.z + a.w * bv2.w;
                acc[r][3] += a.x * bv3.x + a.y * bv3.y + a.z * bv3.z + a.w * bv3.w;
            }
        }
        float pv[5] = {0.f, 0.f, 0.f, 0.f, 0.f};
        #pragma unroll
        for (int c = 0; c < 4; c++) {
            const int j = cg + 16 * c;
            float w2r[5];
            #pragma unroll
            for (int d = 0; d < 5; d++) w2r[d] = sm[OFF_PHI_W2 + j * 5 + d];
            #pragma unroll
            for (int t = 0; t < 4; t++) {
                float2 g = unpack2(gelu2(pack2(acc[2 * t][c], acc[2 * t + 1][c])));
                float gs = g.x + g.y;
                #pragma unroll
                for (int d = 0; d < 5; d++) pv[d] += gs * w2r[d];
            }
        }
        // warp-level reduce (warp == batch)
        #pragma unroll
        for (int d = 0; d < 5; d++) {
            float t = pv[d];
            #pragma unroll
            for (int o = 16; o > 0; o >>= 1)
                t += __shfl_down_sync(0xffffffffu, t, o);
            pv[d] = t;
        }
        if ((tid & 31) == 0 && q < nb) {
            float* rin = sm + OFF_RHOIN4 + q * 28;
            #pragma unroll
            for (int d = 0; d < 5; d++)
                rin[d] = pv[d] * (1.0f / NPART) + sm[OFF_PHI_B2 + d];
        }
    }
    __syncthreads();
    // ---- temb for all nb batches (scratch aliases dead h0 region) ----
    if (tid < 32) {
        int q = tid >> 3, i = tid & 7;
        if (q < nb) {
            float t = tau[base + q];
            if (i == 0) sm[OFF_TTF + q * 17] = t;
            float ft = freqs[i] * t;
            sm[OFF_TTF + q * 17 + 1 + i] = __sinf(ft);
            sm[OFF_TTF + q * 17 + 9 + i] = __cosf(ft);
        }
    }
    __syncthreads();
    if (tid < 64) {
        int q = tid >> 4, j = tid & 15;
        float a = tp_b0[j];
        #pragma unroll
        for (int i = 0; i < 2 * NFREQ + 1; i++)
            a += sm[OFF_TTF + q * 17 + i] * tp_w0[i * TEMB + j];
        sm[OFF_THT + q * 16 + j] = gelu_f(a);
    }
    __syncthreads();
    if (tid < 64) {
        int q = tid >> 4, j = tid & 15;
        float a = tp_b1[j];
        #pragma unroll
        for (int i = 0; i < TEMB; i++)
            a += sm[OFF_THT + q * 16 + i] * tp_w1[i * TEMB + j];
        sm[OFF_RHOIN4 + q * 28 + 12 + j] = a;
    }
    __syncthreads();
    // ---- rho h0: 256 outputs, 2 per thread ----
    #pragma unroll
    for (int s = 0; s < 2; s++) {
        int idx = tid + s * 128;
        int q = idx >> 6, j = idx & 63;
        float a = rho_b0[j];
        const float* rin = sm + OFF_RHOIN4 + q * 28;
        #pragma unroll 4
        for (int i = 0; i < RHOIN; i++) a += rin[i] * rho_w0[i * HID + j];
        sm[OFF_TRH0 + q * 64 + j] = gelu_f(a);
    }
    __syncthreads();
    // ---- rho h1 + w2, per-batch reduce ----
    float part[2];
    #pragma unroll
    for (int s = 0; s < 2; s++) {
        int idx = tid + s * 128;
        int q = idx >> 6, j = idx & 63;
        float a = rho_b1[j];
        const float* rh = sm + OFF_TRH0 + q * 64;
        #pragma unroll 4
        for (int k = 0; k < HID; k++) a += rh[k] * rho_w1[k * HID + j];
        part[s] = gelu_f(a) * rho_w2[j];
    }
    {
        const int lane = tid & 31, wid = tid >> 5;
        #pragma unroll
        for (int o = 16; o > 0; o >>= 1) {
            part[0] += __shfl_down_sync(0xffffffffu, part[0], o);
            part[1] += __shfl_down_sync(0xffffffffu, part[1], o);
        }
        if (lane == 0) { sm[OFF_RED + wid] = part[0]; sm[OFF_RED + 4 + wid] = part[1]; }
    }
    __syncthreads();
    if (tid < 4 && tid < nb) {
        float ssum = sm[OFF_RED + 2 * tid] + sm[OFF_RED + 2 * tid + 1];
        out[base + tid] = ssum + rho_b2[0] + sm[OFF_CUSP + tid];
    }
}

extern "C" void kernel_launch(void* const* d_in, const int* in_sizes, int n_in,
                              void* d_out, int out_size) {
    const float* x      = (const float*)d_in[0];
    const float* tau    = (const float*)d_in[1];
    const float* freqs  = (const float*)d_in[2];
    const float* phi_w0 = (const float*)d_in[3];
    const float* phi_b0 = (const float*)d_in[4];
    const float* phi_w1 = (const float*)d_in[5];
    const float* phi_b1 = (const float*)d_in[6];
    const float* phi_w2 = (const float*)d_in[7];
    const float* phi_b2 = (const float*)d_in[8];
    const float* psi_w0 = (const float*)d_in[9];
    const float* psi_b0 = (const float*)d_in[10];
    const float* psi_w1 = (const float*)d_in[11];
    const float* psi_b1 = (const float*)d_in[12];
    const float* psi_w2 = (const float*)d_in[13];
    const float* psi_b2 = (const float*)d_in[14];
    const float* rho_w0 = (const float*)d_in[15];
    const float* rho_b0 = (const float*)d_in[16];
    const float* rho_w1 = (const float*)d_in[17];
    const float* rho_b1 = (const float*)d_in[18];
    const float* rho_w2 = (const float*)d_in[19];
    const float* rho_b2 = (const float*)d_in[20];
    const float* tp_w0  = (const float*)d_in[21];
    const float* tp_b0  = (const float*)d_in[22];
    const float* tp_w1  = (const float*)d_in[23];
    const float* tp_b1  = (const float*)d_in[24];
    float* out = (float*)d_out;

    const int Btot = in_sizes[1];
    const int nblocks = (Btot + BPB - 1) / BPB;

    cudaFuncSetAttribute(tau_jastrow_kernel,
                         cudaFuncAttributeMaxDynamicSharedMemorySize, SMEM_BYTES);

    tau_jastrow_kernel<<<nblocks, NTHREADS, SMEM_BYTES>>>(
        x, tau, freqs,
        phi_w0, phi_b0, phi_w1, phi_b1, phi_w2, phi_b2,
        psi_w0, psi_b0, psi_w1, psi_b1, psi_w2, psi_b2,
        rho_w0, rho_b0, rho_w1, rho_b1, rho_w2, rho_b2,
        tp_w0, tp_b0, tp_w1, tp_b1,
        out, Btot);
}

// round 9
// speedup vs baseline: 2.5709x; 2.1167x over previous
#include <cuda_runtime.h>
#include <math.h>

#define NPART 16
#define DDIM 3
#define HID 64
#define DLAT 5
#define TEMB 16
#define NFREQ 8
#define NPAIR 120
#define RHOIN 28
#define NTHREADS 128
#define BPB 4

#define TAB_N 1024
#define TAB_SLOTS (TAB_N + 4)                       // 1028 knots (incl -1 and +2 guards)
#define TAB_T0 0.6931471805599453f
#define TAB_TMAX 9.0f
#define TAB_H ((TAB_TMAX - TAB_T0) / (float)TAB_N)
#define TAB_INVH ((float)TAB_N / (TAB_TMAX - TAB_T0))

typedef unsigned long long ull;

// table: channels 0-3 of psi_out*gate in float4, channel 4 separate
__device__ float4 g_tab4[TAB_SLOTS];
__device__ float  g_tab1[TAB_SLOTS];

// ---- dynamic smem layout (float offsets) ----
#define OFF_TAB4    0              // 1028 float4 = 4112 floats
#define OFF_TAB1    4112           // 1028
// tail aliases (table dead after main loop):
//   phi h0 [16][64] float4 = 4096 floats at OFF_TAB4
//   TTF at OFF_TAB4+0 (68), THT at +128 (64), TRH0 at +384 (256) -- after phi GEMM
#define OFF_TTF     0
#define OFF_THT     128
#define OFF_TRH0    384
#define OFF_PHI_W1T 5140           // 4096
#define OFF_PHI_W0  9236           // 192
#define OFF_PHI_B0  9428           // 64
#define OFF_PHI_B1  9492           // 64
#define OFF_PHI_W2  9556           // 320
#define OFF_PHI_B2  9876           // 8
#define OFF_X       9884           // 48
#define OFF_RED     9932           // 56
#define OFF_RHOIN4  9988           // 4 x 28 = 112
#define OFF_CUSP    10100          // 4
#define SMEM_FLOATS 10104
#define SMEM_BYTES  (SMEM_FLOATS * 4)

// ---- packed f32x2 helpers ----
__device__ __forceinline__ ull pack2(float lo, float hi) {
    ull r; asm("mov.b64 %0, {%1, %2};" : "=l"(r) : "f"(lo), "f"(hi)); return r;
}
__device__ __forceinline__ ull dup2(float b) {
    ull r; asm("mov.b64 %0, {%1, %1};" : "=l"(r) : "f"(b)); return r;
}
__device__ __forceinline__ float2 unpack2(ull v) {
    float2 f; asm("mov.b64 {%0, %1}, %2;" : "=f"(f.x), "=f"(f.y) : "l"(v)); return f;
}
__device__ __forceinline__ ull fma2(ull a, ull b, ull c) {
    ull d; asm("fma.rn.f32x2 %0, %1, %2, %3;" : "=l"(d) : "l"(a), "l"(b), "l"(c)); return d;
}
__device__ __forceinline__ ull mul2(ull a, ull b) {
    ull d; asm("mul.rn.f32x2 %0, %1, %2;" : "=l"(d) : "l"(a), "l"(b)); return d;
}
__device__ __forceinline__ ull add2(ull a, ull b) {
    ull d; asm("add.rn.f32x2 %0, %1, %2;" : "=l"(d) : "l"(a), "l"(b)); return d;
}

// ---- gelu: A&S 7.1.26 erf (|err|<=1.5e-7), branchless (EX2 on MUFU pipe)
__device__ __forceinline__ float gelu_f(float x) {
    float ax = fabsf(x);
    float z = ax * 0.70710678118f;
    float t = __fdividef(1.0f, fmaf(0.3275911f, z, 1.0f));
    float p = t * fmaf(t, fmaf(t, fmaf(t, fmaf(t, 1.061405429f, -1.453152027f),
                         1.421413741f), -0.284496736f), 0.254829592f);
    float q = p * exp2f(-1.442695041f * z * z);
    return 0.5f * ((x + ax) - ax * q);
}

__device__ __forceinline__ ull gelu2(ull x2) {
    ull ax2;
    asm("and.b64 %0, %1, %2;" : "=l"(ax2) : "l"(x2), "l"(0x7fffffff7fffffffULL));
    ull z2 = mul2(ax2, dup2(0.70710678118f));
    float2 z = unpack2(z2);
    float tx = __fdividef(1.0f, fmaf(0.3275911f, z.x, 1.0f));
    float ty = __fdividef(1.0f, fmaf(0.3275911f, z.y, 1.0f));
    ull t2 = pack2(tx, ty);
    ull p2 = fma2(t2, dup2(1.061405429f), dup2(-1.453152027f));
    p2 = fma2(p2, t2, dup2(1.421413741f));
    p2 = fma2(p2, t2, dup2(-0.284496736f));
    p2 = fma2(p2, t2, dup2(0.254829592f));
    p2 = mul2(p2, t2);
    float2 m = unpack2(mul2(mul2(z2, z2), dup2(-1.442695041f)));
    ull q2 = mul2(p2, pack2(exp2f(m.x), exp2f(m.y)));
    ull s2 = add2(x2, ax2);
    ull w2 = mul2(ax2, q2);
    return fma2(w2, dup2(-0.5f), mul2(s2, dup2(0.5f)));
}

// precise gelu for the table builder (matches reference erf-gelu to fp32 rounding)
__device__ __forceinline__ float gelu_exact(float x) {
    return 0.5f * x * (1.0f + erff(x * 0.70710678118654752f));
}

// ================= table builder: exact psi MLP at each knot =================
__global__ void build_tab_kernel(
    const float* __restrict__ psi_w0, const float* __restrict__ psi_b0,
    const float* __restrict__ psi_w1, const float* __restrict__ psi_b1,
    const float* __restrict__ psi_w2, const float* __restrict__ psi_b2)
{
    int j = blockIdx.x * blockDim.x + threadIdx.x;
    if (j >= TAB_SLOTS) return;
    float t = TAB_T0 + (float)(j - 1) * TAB_H;      // knot j-1
    float r2 = expm1f(t) * 0.04f - 0.04f;           // invert t = log1p(25*(r2+0.04))
    float rt2 = r2 + 0.04f;
    float u = rt2 * 25.0f;
    float feat[6];
    float s1 = log1pf(u);
    feat[0] = s1;
    feat[1] = r2 / rt2;
    feat[2] = u * expf(-u);
    feat[3] = expf(-0.25f * s1);
    feat[4] = expf(-s1);
    feat[5] = expf(-4.0f * s1);
    float gate = r2 / (r2 + 0.09f);

    float h1[HID];
    #pragma unroll 4
    for (int q = 0; q < HID; q++) h1[q] = psi_b1[q];
    for (int k = 0; k < HID; k++) {
        float a = psi_b0[k];
        #pragma unroll
        for (int i = 0; i < 6; i++) a += feat[i] * psi_w0[i * HID + k];
        float h0k = gelu_exact(a);
        #pragma unroll 4
        for (int q = 0; q < HID; q++) h1[q] += h0k * psi_w1[k * HID + q];
    }
    float outv[DLAT];
    #pragma unroll
    for (int d = 0; d < DLAT; d++) outv[d] = psi_b2[d];
    for (int q = 0; q < HID; q++) {
        float g = gelu_exact(h1[q]);
        #pragma unroll
        for (int d = 0; d < DLAT; d++) outv[d] += g * psi_w2[q * DLAT + d];
    }
    g_tab4[j] = make_float4(outv[0] * gate, outv[1] * gate, outv[2] * gate, outv[3] * gate);
    g_tab1[j] = outv[4] * gate;
}

// ================= main kernel =================
__global__ __launch_bounds__(NTHREADS, 5)
void tau_jastrow_kernel(
    const float* __restrict__ x, const float* __restrict__ tau, const float* __restrict__ freqs,
    const float* __restrict__ phi_w0, const float* __restrict__ phi_b0,
    const float* __restrict__ phi_w1, const float* __restrict__ phi_b1,
    const float* __restrict__ phi_w2, const float* __restrict__ phi_b2,
    const float* __restrict__ rho_w0, const float* __restrict__ rho_b0,
    const float* __restrict__ rho_w1, const float* __restrict__ rho_b1,
    const float* __restrict__ rho_w2, const float* __restrict__ rho_b2,
    const float* __restrict__ tp_w0, const float* __restrict__ tp_b0,
    const float* __restrict__ tp_w1, const float* __restrict__ tp_b1,
    float* __restrict__ out, int Btot)
{
    extern __shared__ float sm[];
    const int tid = threadIdx.x;

    // ---- stage table + phi small weights ----
    {
        float4* st4 = (float4*)(sm + OFF_TAB4);
        for (int i = tid; i < TAB_SLOTS; i += NTHREADS) st4[i] = g_tab4[i];
        for (int i = tid; i < TAB_SLOTS; i += NTHREADS) sm[OFF_TAB1 + i] = g_tab1[i];
    }
    for (int i = tid; i < 3 * HID; i += NTHREADS) sm[OFF_PHI_W0 + i] = phi_w0[i];
    for (int i = tid; i < HID * DLAT; i += NTHREADS) sm[OFF_PHI_W2 + i] = phi_w2[i];
    if (tid < HID) { sm[OFF_PHI_B0 + tid] = phi_b0[tid]; sm[OFF_PHI_B1 + tid] = phi_b1[tid]; }
    if (tid < DLAT) sm[OFF_PHI_B2 + tid] = phi_b2[tid];

    // ---- pair indices (triu k=1 row-major) ----
    int pi = 0, pj = 0;
    {
        int p2 = tid, i2 = 0, cnt = NPART - 1;
        while (cnt > 0 && p2 >= cnt) { p2 -= cnt; i2++; cnt--; }
        pi = i2; pj = i2 + 1 + p2;
        if (pj >= NPART) pj = NPART - 1;
    }
    const bool active = (tid < NPAIR);
    const float gamma = ((pi < NPART / 2) == (pj < NPART / 2))
                        ? (1.0f / (DDIM + 1)) : (1.0f / (DDIM - 1));

    const int base = blockIdx.x * BPB;
    const int nb = (Btot - base < BPB) ? (Btot - base) : BPB;

    // ======================= per-batch main loop (spline psi) =======================
    for (int bi = 0; bi < nb; ++bi) {
        const int b = base + bi;
        if (tid < NPART * DDIM) sm[OFF_X + tid] = x[(size_t)b * (NPART * DDIM) + tid];
        __syncthreads();   // orders staging on first iter, x thereafter

        float vals[8];
        #pragma unroll
        for (int v = 0; v < 8; v++) vals[v] = 0.f;
        if (tid < NPART * DDIM) {
            float xv = sm[OFF_X + tid];
            vals[7] = xv * xv;
        }

        if (active) {
            float d0 = sm[OFF_X + pi * 3 + 0] - sm[OFF_X + pj * 3 + 0];
            float d1 = sm[OFF_X + pi * 3 + 1] - sm[OFF_X + pj * 3 + 1];
            float d2 = sm[OFF_X + pi * 3 + 2] - sm[OFF_X + pj * 3 + 2];
            float r2 = d0 * d0 + d1 * d1 + d2 * d2;
            float rt2 = r2 + 0.04f;
            float tt = __fdividef(1.0f, fmaf(25.0f, rt2, 1.0f));
            float t = -__logf(tt);                       // s1
            float r = sqrtf(r2 + 1.1920929e-7f);
            vals[5] = t;
            vals[6] = gamma * r * __expf(-r);            // cusp (exact path)

            // Catmull-Rom spline eval
            float idxf = (t - TAB_T0) * TAB_INVH;
            int i = (int)idxf;
            if (i > TAB_N - 1) i = TAB_N - 1;
            if (i < 0) i = 0;
            float uf = idxf - (float)i;
            float u2 = uf * uf, u3 = u2 * uf;
            float cw0 = 0.5f * (-u3 + 2.0f * u2 - uf);
            float cw1 = 0.5f * (3.0f * u3 - 5.0f * u2 + 2.0f);
            float cw2 = 0.5f * (-3.0f * u3 + 4.0f * u2 + uf);
            float cw3 = 0.5f * (u3 - u2);
            const float4* t4 = (const float4*)(sm + OFF_TAB4);
            float4 e0 = t4[i], e1 = t4[i + 1], e2 = t4[i + 2], e3 = t4[i + 3];
            vals[0] = cw0 * e0.x + cw1 * e1.x + cw2 * e2.x + cw3 * e3.x;
            vals[1] = cw0 * e0.y + cw1 * e1.y + cw2 * e2.y + cw3 * e3.y;
            vals[2] = cw0 * e0.z + cw1 * e1.z + cw2 * e2.z + cw3 * e3.z;
            vals[3] = cw0 * e0.w + cw1 * e1.w + cw2 * e2.w + cw3 * e3.w;
            vals[4] = cw0 * sm[OFF_TAB1 + i]     + cw1 * sm[OFF_TAB1 + i + 1]
                    + cw2 * sm[OFF_TAB1 + i + 2] + cw3 * sm[OFF_TAB1 + i + 3];
        }

        // ---- fused 8-value block reduction ----
        {
            const int lane = tid & 31, wid = tid >> 5;
            #pragma unroll
            for (int v = 0; v < 8; v++) {
                float t = vals[v];
                #pragma unroll
                for (int o = 16; o > 0; o >>= 1)
                    t += __shfl_down_sync(0xffffffffu, t, o);
                if (lane == 0) sm[OFF_RED + v * 4 + wid] = t;
            }
        }
        __syncthreads();
        if (tid < 8) {
            float s = sm[OFF_RED + tid * 4 + 0] + sm[OFF_RED + tid * 4 + 1]
                    + sm[OFF_RED + tid * 4 + 2] + sm[OFF_RED + tid * 4 + 3];
            float* rin = sm + OFF_RHOIN4 + bi * 28;
            if (tid < 5) {
                rin[5 + tid] = s * (1.0f / NPAIR);       // table folds b2 and gate
            } else if (tid == 5) {
                rin[11] = s * (1.0f / NPAIR);            // s1_mean
            } else if (tid == 6) {
                sm[OFF_CUSP + bi] = s;
            } else {
                rin[10] = s * (1.0f / (NPART * DDIM));   // r2_mean
            }
        }
        // next iteration's top sync orders these writes
    }
    __syncthreads();   // table region about to be reused by phi h0

    // ======================= batched tail =======================
    // ---- stage phi W1T (k-tiled transposed) ----
    {
        const float4* gw = (const float4*)phi_w1;
        #pragma unroll
        for (int i = 0; i < 8; i++) {
            int idx4 = tid + 128 * i;
            float4 v = gw[idx4];
            int k = idx4 >> 4;
            int j0 = (idx4 & 15) * 4;
            float* d = sm + OFF_PHI_W1T + (k >> 2) * 256 + (k & 3) + j0 * 4;
            d[0] = v.x; d[4] = v.y; d[8] = v.z; d[12] = v.w;
        }
    }
    // ---- phi h0 for all nb batches: 64 rows (batch q = R>>4, particle p = R&15) ----
    {
        const int R = tid >> 1, q = R >> 4, p = R & 15, kh = tid & 1;
        const int qq = (q < nb) ? q : 0;
        const float* xb = x + (size_t)(base + qq) * (NPART * DDIM) + p * 3;
        float xv0 = xb[0], xv1 = xb[1], xv2 = xb[2];
        const float4* w0 = (const float4*)(sm + OFF_PHI_W0);
        const float4* b0 = (const float4*)(sm + OFF_PHI_B0);
        float4* h0w = (float4*)(sm + OFF_TAB4);   // aliases dead table
        #pragma unroll
        for (int t8 = 0; t8 < 8; t8++) {
            int kt = kh * 8 + t8;
            float4 a = b0[kt];
            float4 w;
            w = w0[0 * 16 + kt];
            a.x += xv0 * w.x; a.y += xv0 * w.y; a.z += xv0 * w.z; a.w += xv0 * w.w;
            w = w0[1 * 16 + kt];
            a.x += xv1 * w.x; a.y += xv1 * w.y; a.z += xv1 * w.z; a.w += xv1 * w.w;
            w = w0[2 * 16 + kt];
            a.x += xv2 * w.x; a.y += xv2 * w.y; a.z += xv2 * w.z; a.w += xv2 * w.w;
            float2 g01 = unpack2(gelu2(pack2(a.x, a.y)));
            float2 g23 = unpack2(gelu2(pack2(a.z, a.w)));
            h0w[kt * 64 + R] = make_float4(g01.x, g01.y, g23.x, g23.y);
        }
    }
    __syncthreads();
    // ---- phi h1 GEMM (64x64 @ 64x64): thread tile 8 rows x 4 cols; warp w == batch w ----
    {
        const int rg = tid >> 4, cg = tid & 15;
        const int q = rg >> 1;
        float acc[8][4];
        #pragma unroll
        for (int c = 0; c < 4; c++) {
            float bi1 = sm[OFF_PHI_B1 + cg + 16 * c];
            #pragma unroll
            for (int r = 0; r < 8; r++) acc[r][c] = bi1;
        }
        const float4* w1t4 = (const float4*)(sm + OFF_PHI_W1T);
        const float4* h0f4 = (const float4*)(sm + OFF_TAB4);
        #pragma unroll 2
        for (int kt = 0; kt < 16; kt++) {
            float4 bv0 = w1t4[kt * 64 + cg];
            float4 bv1 = w1t4[kt * 64 + cg + 16];
            float4 bv2 = w1t4[kt * 64 + cg + 32];
            float4 bv3 = w1t4[kt * 64 + cg + 48];
            #pragma unroll
            for (int r = 0; r < 8; r++) {
                float4 a = h0f4[kt * 64 + rg * 8 + r];
                acc[r][0] += a.x * bv0.x + a.y * bv0.y + a.z * bv0.z + a.w * bv0.w;
                acc[r][1] += a.x * bv1.x + a.y * bv1.y + a.z * bv1.z + a.w * bv1.w;
                acc[r][2] += a.x * bv2.x + a.y * bv2.y + a.z * bv2.z + a.w * bv2.w;
                acc[r][3] += a.x * bv3.x + a.y * bv3.y + a.z * bv3.z + a.w * bv3.w;
            }
        }
        float pv[5] = {0.f, 0.f, 0.f, 0.f, 0.f};
        #pragma unroll
        for (int c = 0; c < 4; c++) {
            const int j = cg + 16 * c;
            float w2r[5];
            #pragma unroll
            for (int d = 0; d < 5; d++) w2r[d] = sm[OFF_PHI_W2 + j * 5 + d];
            #pragma unroll
            for (int t = 0; t < 4; t++) {
                float2 g = unpack2(gelu2(pack2(acc[2 * t][c], acc[2 * t + 1][c])));
                float gs = g.x + g.y;
                #pragma unroll
                for (int d = 0; d < 5; d++) pv[d] += gs * w2r[d];
            }
        }
        #pragma unroll
        for (int d = 0; d < 5; d++) {
            float t = pv[d];
            #pragma unroll
            for (int o = 16; o > 0; o >>= 1)
                t += __shfl_down_sync(0xffffffffu, t, o);
            pv[d] = t;
        }
        if ((tid & 31) == 0 && q < nb) {
            float* rin = sm + OFF_RHOIN4 + q * 28;
            #pragma unroll
            for (int d = 0; d < 5; d++)
                rin[d] = pv[d] * (1.0f / NPART) + sm[OFF_PHI_B2 + d];
        }
    }
    __syncthreads();
    // ---- temb for all nb batches (scratch aliases dead phi h0) ----
    if (tid < 32) {
        int q = tid >> 3, i = tid & 7;
        if (q < nb) {
            float t = tau[base + q];
            if (i == 0) sm[OFF_TTF + q * 17] = t;
            float ft = freqs[i] * t;
            sm[OFF_TTF + q * 17 + 1 + i] = __sinf(ft);
            sm[OFF_TTF + q * 17 + 9 + i] = __cosf(ft);
        }
    }
    __syncthreads();
    if (tid < 64) {
        int q = tid >> 4, j = tid & 15;
        float a = tp_b0[j];
        #pragma unroll
        for (int i = 0; i < 2 * NFREQ + 1; i++)
            a += sm[OFF_TTF + q * 17 + i] * tp_w0[i * TEMB + j];
        sm[OFF_THT + q * 16 + j] = gelu_f(a);
    }
    __syncthreads();
    if (tid < 64) {
        int q = tid >> 4, j = tid & 15;
        float a = tp_b1[j];
        #pragma unroll
        for (int i = 0; i < TEMB; i++)
            a += sm[OFF_THT + q * 16 + i] * tp_w1[i * TEMB + j];
        sm[OFF_RHOIN4 + q * 28 + 12 + j] = a;
    }
    __syncthreads();
    // ---- rho h0: 256 outputs, 2 per thread ----
    #pragma unroll
    for (int s = 0; s < 2; s++) {
        int idx = tid + s * 128;
        int q = idx >> 6, j = idx & 63;
        float a = rho_b0[j];
        const float* rin = sm + OFF_RHOIN4 + q * 28;
        #pragma unroll 4
        for (int i = 0; i < RHOIN; i++) a += rin[i] * rho_w0[i * HID + j];
        sm[OFF_TRH0 + q * 64 + j] = gelu_f(a);
    }
    __syncthreads();
    // ---- rho h1 + w2, per-batch reduce ----
    float part[2];
    #pragma unroll
    for (int s = 0; s < 2; s++) {
        int idx = tid + s * 128;
        int q = idx >> 6, j = idx & 63;
        float a = rho_b1[j];
        const float* rh = sm + OFF_TRH0 + q * 64;
        #pragma unroll 4
        for (int k = 0; k < HID; k++) a += rh[k] * rho_w1[k * HID + j];
        part[s] = gelu_f(a) * rho_w2[j];
    }
    {
        const int lane = tid & 31, wid = tid >> 5;
        #pragma unroll
        for (int o = 16; o > 0; o >>= 1) {
            part[0] += __shfl_down_sync(0xffffffffu, part[0], o);
            part[1] += __shfl_down_sync(0xffffffffu, part[1], o);
        }
        if (lane == 0) { sm[OFF_RED + wid] = part[0]; sm[OFF_RED + 4 + wid] = part[1]; }
    }
    __syncthreads();
    if (tid < 4 && tid < nb) {
        float ssum = sm[OFF_RED + 2 * tid] + sm[OFF_RED + 2 * tid + 1];
        out[base + tid] = ssum + rho_b2[0] + sm[OFF_CUSP + tid];
    }
}

extern "C" void kernel_launch(void* const* d_in, const int* in_sizes, int n_in,
                              void* d_out, int out_size) {
    const float* x      = (const float*)d_in[0];
    const float* tau    = (const float*)d_in[1];
    const float* freqs  = (const float*)d_in[2];
    const float* phi_w0 = (const float*)d_in[3];
    const float* phi_b0 = (const float*)d_in[4];
    const float* phi_w1 = (const float*)d_in[5];
    const float* phi_b1 = (const float*)d_in[6];
    const float* phi_w2 = (const float*)d_in[7];
    const float* phi_b2 = (const float*)d_in[8];
    const float* psi_w0 = (const float*)d_in[9];
    const float* psi_b0 = (const float*)d_in[10];
    const float* psi_w1 = (const float*)d_in[11];
    const float* psi_b1 = (const float*)d_in[12];
    const float* psi_w2 = (const float*)d_in[13];
    const float* psi_b2 = (const float*)d_in[14];
    const float* rho_w0 = (const float*)d_in[15];
    const float* rho_b0 = (const float*)d_in[16];
    const float* rho_w1 = (const float*)d_in[17];
    const float* rho_b1 = (const float*)d_in[18];
    const float* rho_w2 = (const float*)d_in[19];
    const float* rho_b2 = (const float*)d_in[20];
    const float* tp_w0  = (const float*)d_in[21];
    const float* tp_b0  = (const float*)d_in[22];
    const float* tp_w1  = (const float*)d_in[23];
    const float* tp_b1  = (const float*)d_in[24];
    float* out = (float*)d_out;

    const int Btot = in_sizes[1];

    // 1) build the psi spline table from this call's weights
    build_tab_kernel<<<(TAB_SLOTS + 127) / 128, 128>>>(
        psi_w0, psi_b0, psi_w1, psi_b1, psi_w2, psi_b2);

    // 2) main kernel
    const int nblocks = (Btot + BPB - 1) / BPB;
    cudaFuncSetAttribute(tau_jastrow_kernel,
                         cudaFuncAttributeMaxDynamicSharedMemorySize, SMEM_BYTES);
    tau_jastrow_kernel<<<nblocks, NTHREADS, SMEM_BYTES>>>(
        x, tau, freqs,
        phi_w0, phi_b0, phi_w1, phi_b1, phi_w2, phi_b2,
        rho_w0, rho_b0, rho_w1, rho_b1, rho_w2, rho_b2,
        tp_w0, tp_b0, tp_w1, tp_b1,
        out, Btot);
}

// round 11
// speedup vs baseline: 4.8663x; 1.8928x over previous
#include <cuda_runtime.h>
#include <math.h>

#define NPART 16
#define DDIM 3
#define HID 64
#define DLAT 5
#define TEMB 16
#define NFREQ 8
#define NPAIR 120
#define RHOIN 28
#define NTHREADS 128
#define BPB 4

#define TAB_N 1024
#define TAB_SLOTS (TAB_N + 4)                       // 1028 knots (incl -1 and +2 guards)
#define TAB_T0 0.6931471805599453f
#define TAB_TMAX 9.0f
#define TAB_H ((TAB_TMAX - TAB_T0) / (float)TAB_N)
#define TAB_INVH ((float)TAB_N / (TAB_TMAX - TAB_T0))

typedef unsigned long long ull;

// table: channels 0-3 of psi_out*gate in float4, channel 4 separate
__device__ float4 g_tab4[TAB_SLOTS];
__device__ float  g_tab1[TAB_SLOTS];

// ---- dynamic smem layout (float offsets) ----
#define OFF_TAB4    0              // 1028 float4 = 4112 floats
#define OFF_TAB1    4112           // 1028
// tail aliases (table dead after main loop):
//   phi h0 transposed [16][4][64] = 4096 floats at OFF_TAB4
//   TTF at +0 (68), THT at +128 (64), TRH0 at +384 (256) -- after phi GEMM
#define OFF_TTF     0
#define OFF_THT     128
#define OFF_TRH0    384
#define OFF_PHI_W1T 5140           // 4096
#define OFF_PHI_W0  9236           // 192
#define OFF_PHI_B0  9428           // 64
#define OFF_PHI_B1  9492           // 64
#define OFF_PHI_W2  9556           // 320
#define OFF_PHI_B2  9876           // 8
#define OFF_X       9884           // 48
#define OFF_RED     9932           // 56
#define OFF_RHOIN4  9988           // 4 x 28 = 112
#define OFF_CUSP    10100          // 4
#define SMEM_FLOATS 10104
#define SMEM_BYTES  (SMEM_FLOATS * 4)

// ---- packed f32x2 helpers ----
__device__ __forceinline__ ull pack2(float lo, float hi) {
    ull r; asm("mov.b64 %0, {%1, %2};" : "=l"(r) : "f"(lo), "f"(hi)); return r;
}
__device__ __forceinline__ ull dup2(float b) {
    ull r; asm("mov.b64 %0, {%1, %1};" : "=l"(r) : "f"(b)); return r;
}
__device__ __forceinline__ float2 unpack2(ull v) {
    float2 f; asm("mov.b64 {%0, %1}, %2;" : "=f"(f.x), "=f"(f.y) : "l"(v)); return f;
}
__device__ __forceinline__ void ffma2(ull& d, ull a, ull b) {
    asm("fma.rn.f32x2 %0, %1, %2, %0;" : "+l"(d) : "l"(a), "l"(b));
}
__device__ __forceinline__ ull fma2(ull a, ull b, ull c) {
    ull d; asm("fma.rn.f32x2 %0, %1, %2, %3;" : "=l"(d) : "l"(a), "l"(b), "l"(c)); return d;
}
__device__ __forceinline__ ull mul2(ull a, ull b) {
    ull d; asm("mul.rn.f32x2 %0, %1, %2;" : "=l"(d) : "l"(a), "l"(b)); return d;
}
__device__ __forceinline__ ull add2(ull a, ull b) {
    ull d; asm("add.rn.f32x2 %0, %1, %2;" : "=l"(d) : "l"(a), "l"(b)); return d;
}

// ---- gelu: A&S 7.1.26 erf (|err|<=1.5e-7), branchless (EX2 on MUFU pipe)
__device__ __forceinline__ float gelu_f(float x) {
    float ax = fabsf(x);
    float z = ax * 0.70710678118f;
    float t = __fdividef(1.0f, fmaf(0.3275911f, z, 1.0f));
    float p = t * fmaf(t, fmaf(t, fmaf(t, fmaf(t, 1.061405429f, -1.453152027f),
                         1.421413741f), -0.284496736f), 0.254829592f);
    float q = p * exp2f(-1.442695041f * z * z);
    return 0.5f * ((x + ax) - ax * q);
}

__device__ __forceinline__ ull gelu2(ull x2) {
    ull ax2;
    asm("and.b64 %0, %1, %2;" : "=l"(ax2) : "l"(x2), "l"(0x7fffffff7fffffffULL));
    ull z2 = mul2(ax2, dup2(0.70710678118f));
    float2 z = unpack2(z2);
    float tx = __fdividef(1.0f, fmaf(0.3275911f, z.x, 1.0f));
    float ty = __fdividef(1.0f, fmaf(0.3275911f, z.y, 1.0f));
    ull t2 = pack2(tx, ty);
    ull p2 = fma2(t2, dup2(1.061405429f), dup2(-1.453152027f));
    p2 = fma2(p2, t2, dup2(1.421413741f));
    p2 = fma2(p2, t2, dup2(-0.284496736f));
    p2 = fma2(p2, t2, dup2(0.254829592f));
    p2 = mul2(p2, t2);
    float2 m = unpack2(mul2(mul2(z2, z2), dup2(-1.442695041f)));
    ull q2 = mul2(p2, pack2(exp2f(m.x), exp2f(m.y)));
    ull s2 = add2(x2, ax2);
    ull w2 = mul2(ax2, q2);
    return fma2(w2, dup2(-0.5f), mul2(s2, dup2(0.5f)));
}

// precise gelu for the table builder
__device__ __forceinline__ float gelu_exact(float x) {
    return 0.5f * x * (1.0f + erff(x * 0.70710678118654752f));
}

// ================= table builder: warp per knot =================
__global__ void build_tab_kernel(
    const float* __restrict__ psi_w0, const float* __restrict__ psi_b0,
    const float* __restrict__ psi_w1, const float* __restrict__ psi_b1,
    const float* __restrict__ psi_w2, const float* __restrict__ psi_b2)
{
    __shared__ float h0s[4][HID];
    const int wid = threadIdx.x >> 5, lane = threadIdx.x & 31;
    const int j = blockIdx.x * 4 + wid;
    if (j >= TAB_SLOTS) return;

    float t = TAB_T0 + (float)(j - 1) * TAB_H;      // knot j-1
    float r2 = expm1f(t) * 0.04f - 0.04f;           // invert t = log1p(25*(r2+0.04))
    float rt2 = r2 + 0.04f;
    float u = rt2 * 25.0f;
    float feat[6];
    float s1 = log1pf(u);
    feat[0] = s1;
    feat[1] = r2 / rt2;
    feat[2] = u * expf(-u);
    feat[3] = expf(-0.25f * s1);
    feat[4] = expf(-s1);
    feat[5] = expf(-4.0f * s1);
    float gate = r2 / (r2 + 0.09f);

    // h0 for k = lane, lane+32
    #pragma unroll
    for (int s = 0; s < 2; s++) {
        int k = lane + 32 * s;
        float a = psi_b0[k];
        #pragma unroll
        for (int i = 0; i < 6; i++) a += feat[i] * psi_w0[i * HID + k];
        h0s[wid][k] = gelu_exact(a);
    }
    __syncwarp();

    // h1 + W2 contraction for q = lane, lane+32
    float outv[DLAT] = {0.f, 0.f, 0.f, 0.f, 0.f};
    #pragma unroll
    for (int s = 0; s < 2; s++) {
        int q = lane + 32 * s;
        float a = psi_b1[q];
        #pragma unroll 8
        for (int k = 0; k < HID; k++) a += h0s[wid][k] * psi_w1[k * HID + q];
        float g = gelu_exact(a);
        #pragma unroll
        for (int d = 0; d < DLAT; d++) outv[d] += g * psi_w2[q * DLAT + d];
    }
    #pragma unroll
    for (int d = 0; d < DLAT; d++) {
        float v = outv[d];
        #pragma unroll
        for (int o = 16; o > 0; o >>= 1)
            v += __shfl_down_sync(0xffffffffu, v, o);
        outv[d] = v;
    }
    if (lane == 0) {
        #pragma unroll
        for (int d = 0; d < DLAT; d++) outv[d] += psi_b2[d];
        g_tab4[j] = make_float4(outv[0] * gate, outv[1] * gate,
                                outv[2] * gate, outv[3] * gate);
        g_tab1[j] = outv[4] * gate;
    }
}

// ================= main kernel =================
__global__ __launch_bounds__(NTHREADS, 5)
void tau_jastrow_kernel(
    const float* __restrict__ x, const float* __restrict__ tau, const float* __restrict__ freqs,
    const float* __restrict__ phi_w0, const float* __restrict__ phi_b0,
    const float* __restrict__ phi_w1, const float* __restrict__ phi_b1,
    const float* __restrict__ phi_w2, const float* __restrict__ phi_b2,
    const float* __restrict__ rho_w0, const float* __restrict__ rho_b0,
    const float* __restrict__ rho_w1, const float* __restrict__ rho_b1,
    const float* __restrict__ rho_w2, const float* __restrict__ rho_b2,
    const float* __restrict__ tp_w0, const float* __restrict__ tp_b0,
    const float* __restrict__ tp_w1, const float* __restrict__ tp_b1,
    float* __restrict__ out, int Btot)
{
    extern __shared__ float sm[];
    const int tid = threadIdx.x;

    // ---- stage table + phi small weights ----
    {
        float4* st4 = (float4*)(sm + OFF_TAB4);
        for (int i = tid; i < TAB_SLOTS; i += NTHREADS) st4[i] = g_tab4[i];
        for (int i = tid; i < TAB_SLOTS; i += NTHREADS) sm[OFF_TAB1 + i] = g_tab1[i];
    }
    for (int i = tid; i < 3 * HID; i += NTHREADS) sm[OFF_PHI_W0 + i] = phi_w0[i];
    for (int i = tid; i < HID * DLAT; i += NTHREADS) sm[OFF_PHI_W2 + i] = phi_w2[i];
    if (tid < HID) { sm[OFF_PHI_B0 + tid] = phi_b0[tid]; sm[OFF_PHI_B1 + tid] = phi_b1[tid]; }
    if (tid < DLAT) sm[OFF_PHI_B2 + tid] = phi_b2[tid];

    // ---- pair indices (triu k=1 row-major) ----
    int pi = 0, pj = 0;
    {
        int p2 = tid, i2 = 0, cnt = NPART - 1;
        while (cnt > 0 && p2 >= cnt) { p2 -= cnt; i2++; cnt--; }
        pi = i2; pj = i2 + 1 + p2;
        if (pj >= NPART) pj = NPART - 1;
    }
    const bool active = (tid < NPAIR);
    const float gamma = ((pi < NPART / 2) == (pj < NPART / 2))
                        ? (1.0f / (DDIM + 1)) : (1.0f / (DDIM - 1));

    const int base = blockIdx.x * BPB;
    const int nb = (Btot - base < BPB) ? (Btot - base) : BPB;

    // ======================= per-batch main loop (spline psi) =======================
    for (int bi = 0; bi < nb; ++bi) {
        const int b = base + bi;
        if (tid < NPART * DDIM) sm[OFF_X + tid] = x[(size_t)b * (NPART * DDIM) + tid];
        __syncthreads();

        float vals[8];
        #pragma unroll
        for (int v = 0; v < 8; v++) vals[v] = 0.f;
        if (tid < NPART * DDIM) {
            float xv = sm[OFF_X + tid];
            vals[7] = xv * xv;
        }

        if (active) {
            float d0 = sm[OFF_X + pi * 3 + 0] - sm[OFF_X + pj * 3 + 0];
            float d1 = sm[OFF_X + pi * 3 + 1] - sm[OFF_X + pj * 3 + 1];
            float d2 = sm[OFF_X + pi * 3 + 2] - sm[OFF_X + pj * 3 + 2];
            float r2 = d0 * d0 + d1 * d1 + d2 * d2;
            float rt2 = r2 + 0.04f;
            float tt = __fdividef(1.0f, fmaf(25.0f, rt2, 1.0f));
            float t = -__logf(tt);                       // s1
            float r = sqrtf(r2 + 1.1920929e-7f);
            vals[5] = t;
            vals[6] = gamma * r * __expf(-r);            // cusp (exact path)

            // Catmull-Rom spline eval
            float idxf = (t - TAB_T0) * TAB_INVH;
            int i = (int)idxf;
            if (i > TAB_N - 1) i = TAB_N - 1;
            if (i < 0) i = 0;
            float uf = idxf - (float)i;
            float u2 = uf * uf, u3 = u2 * uf;
            float cw0 = 0.5f * (-u3 + 2.0f * u2 - uf);
            float cw1 = 0.5f * (3.0f * u3 - 5.0f * u2 + 2.0f);
            float cw2 = 0.5f * (-3.0f * u3 + 4.0f * u2 + uf);
            float cw3 = 0.5f * (u3 - u2);
            const float4* t4 = (const float4*)(sm + OFF_TAB4);
            float4 e0 = t4[i], e1 = t4[i + 1], e2 = t4[i + 2], e3 = t4[i + 3];
            vals[0] = cw0 * e0.x + cw1 * e1.x + cw2 * e2.x + cw3 * e3.x;
            vals[1] = cw0 * e0.y + cw1 * e1.y + cw2 * e2.y + cw3 * e3.y;
            vals[2] = cw0 * e0.z + cw1 * e1.z + cw2 * e2.z + cw3 * e3.z;
            vals[3] = cw0 * e0.w + cw1 * e1.w + cw2 * e2.w + cw3 * e3.w;
            vals[4] = cw0 * sm[OFF_TAB1 + i]     + cw1 * sm[OFF_TAB1 + i + 1]
                    + cw2 * sm[OFF_TAB1 + i + 2] + cw3 * sm[OFF_TAB1 + i + 3];
        }

        // ---- fused 8-value block reduction ----
        {
            const int lane = tid & 31, wid = tid >> 5;
            #pragma unroll
            for (int v = 0; v < 8; v++) {
                float t = vals[v];
                #pragma unroll
                for (int o = 16; o > 0; o >>= 1)
                    t += __shfl_down_sync(0xffffffffu, t, o);
                if (lane == 0) sm[OFF_RED + v * 4 + wid] = t;
            }
        }
        __syncthreads();
        if (tid < 8) {
            float s = sm[OFF_RED + tid * 4 + 0] + sm[OFF_RED + tid * 4 + 1]
                    + sm[OFF_RED + tid * 4 + 2] + sm[OFF_RED + tid * 4 + 3];
            float* rin = sm + OFF_RHOIN4 + bi * 28;
            if (tid < 5) {
                rin[5 + tid] = s * (1.0f / NPAIR);       // table folds b2 and gate
            } else if (tid == 5) {
                rin[11] = s * (1.0f / NPAIR);            // s1_mean
            } else if (tid == 6) {
                sm[OFF_CUSP + bi] = s;
            } else {
                rin[10] = s * (1.0f / (NPART * DDIM));   // r2_mean
            }
        }
        // next iteration's top sync orders these writes
    }
    __syncthreads();   // table region about to be reused by phi h0

    // ======================= batched tail =======================
    // ---- stage phi W1T (k-tiled transposed) ----
    {
        const float4* gw = (const float4*)phi_w1;
        #pragma unroll
        for (int i = 0; i < 8; i++) {
            int idx4 = tid + 128 * i;
            float4 v = gw[idx4];
            int k = idx4 >> 4;
            int j0 = (idx4 & 15) * 4;
            float* d = sm + OFF_PHI_W1T + (k >> 2) * 256 + (k & 3) + j0 * 4;
            d[0] = v.x; d[4] = v.y; d[8] = v.z; d[12] = v.w;
        }
    }
    // ---- phi h0 for all nb batches, TRANSPOSED store [kt][kc][row] ----
    {
        const int R = tid >> 1, q = R >> 4, p = R & 15, kh = tid & 1;
        const int qq = (q < nb) ? q : 0;
        const float* xb = x + (size_t)(base + qq) * (NPART * DDIM) + p * 3;
        float xv0 = xb[0], xv1 = xb[1], xv2 = xb[2];
        const float4* w0 = (const float4*)(sm + OFF_PHI_W0);
        const float4* b0 = (const float4*)(sm + OFF_PHI_B0);
        #pragma unroll
        for (int t8 = 0; t8 < 8; t8++) {
            int kt = kh * 8 + t8;
            float4 a = b0[kt];
            float4 w;
            w = w0[0 * 16 + kt];
            a.x += xv0 * w.x; a.y += xv0 * w.y; a.z += xv0 * w.z; a.w += xv0 * w.w;
            w = w0[1 * 16 + kt];
            a.x += xv1 * w.x; a.y += xv1 * w.y; a.z += xv1 * w.z; a.w += xv1 * w.w;
            w = w0[2 * 16 + kt];
            a.x += xv2 * w.x; a.y += xv2 * w.y; a.z += xv2 * w.z; a.w += xv2 * w.w;
            float2 g01 = unpack2(gelu2(pack2(a.x, a.y)));
            float2 g23 = unpack2(gelu2(pack2(a.z, a.w)));
            float* dst = sm + OFF_TAB4 + kt * 256 + R;   // aliases dead table
            dst[0]   = g01.x;
            dst[64]  = g01.y;
            dst[128] = g23.x;
            dst[192] = g23.y;
        }
    }
    __syncthreads();
    // ---- phi h1 GEMM (64x64 @ 64x64) packed f32x2; warp w == batch w ----
    {
        const int rg = tid >> 4, cg = tid & 15;   // rg: 8 rows (4 row-pairs); cg: 4 cols
        const int q = rg >> 1;
        ull acc[4][4];
        #pragma unroll
        for (int c = 0; c < 4; c++) {
            ull bi1 = dup2(sm[OFF_PHI_B1 + cg + 16 * c]);
            #pragma unroll
            for (int p = 0; p < 4; p++) acc[p][c] = bi1;
        }
        const float4* w1t4 = (const float4*)(sm + OFF_PHI_W1T);
        #pragma unroll 1
        for (int kt = 0; kt < 16; kt++) {
            float4 bv0 = w1t4[kt * 64 + cg];
            float4 bv1 = w1t4[kt * 64 + cg + 16];
            float4 bv2 = w1t4[kt * 64 + cg + 32];
            float4 bv3 = w1t4[kt * 64 + cg + 48];
            const float* hb = sm + OFF_TAB4 + kt * 256 + rg * 8;
            #define KC_STEP(kc, comp)                                       \
            {                                                               \
                ull b20 = dup2(bv0.comp);                                   \
                ull b21 = dup2(bv1.comp);                                   \
                ull b22 = dup2(bv2.comp);                                   \
                ull b23 = dup2(bv3.comp);                                   \
                const ull* ap = (const ull*)(hb + (kc) * 64);               \
                _Pragma("unroll")                                           \
                for (int p = 0; p < 4; p++) {                               \
                    ull aa = ap[p];                                         \
                    ffma2(acc[p][0], aa, b20);                              \
                    ffma2(acc[p][1], aa, b21);                              \
                    ffma2(acc[p][2], aa, b22);                              \
                    ffma2(acc[p][3], aa, b23);                              \
                }                                                           \
            }
            KC_STEP(0, x) KC_STEP(1, y) KC_STEP(2, z) KC_STEP(3, w)
            #undef KC_STEP
        }
        // epilogue: packed gelu -> W2 (row-pairs stay packed; both rows same batch)
        ull pv2[5];
        #pragma unroll
        for (int d = 0; d < 5; d++) pv2[d] = dup2(0.f);
        #pragma unroll
        for (int c = 0; c < 4; c++) {
            const int j = cg + 16 * c;
            ull w2d[5];
            #pragma unroll
            for (int d = 0; d < 5; d++) w2d[d] = dup2(sm[OFF_PHI_W2 + j * 5 + d]);
            #pragma unroll
            for (int p = 0; p < 4; p++) {
                ull gg = gelu2(acc[p][c]);
                #pragma unroll
                for (int d = 0; d < 5; d++) pv2[d] = fma2(gg, w2d[d], pv2[d]);
            }
        }
        float pv[5];
        #pragma unroll
        for (int d = 0; d < 5; d++) {
            float2 f = unpack2(pv2[d]);
            float t = f.x + f.y;
            #pragma unroll
            for (int o = 16; o > 0; o >>= 1)
                t += __shfl_down_sync(0xffffffffu, t, o);
            pv[d] = t;
        }
        if ((tid & 31) == 0 && q < nb) {
            float* rin = sm + OFF_RHOIN4 + q * 28;
            #pragma unroll
            for (int d = 0; d < 5; d++)
                rin[d] = pv[d] * (1.0f / NPART) + sm[OFF_PHI_B2 + d];
        }
    }
    __syncthreads();
    // ---- temb for all nb batches (scratch aliases dead phi h0) ----
    if (tid < 32) {
        int q = tid >> 3, i = tid & 7;
        if (q < nb) {
            float t = tau[base + q];
            if (i == 0) sm[OFF_TTF + q * 17] = t;
            float ft = freqs[i] * t;
            sm[OFF_TTF + q * 17 + 1 + i] = __sinf(ft);
            sm[OFF_TTF + q * 17 + 9 + i] = __cosf(ft);
        }
    }
    __syncthreads();
    if (tid < 64) {
        int q = tid >> 4, j = tid & 15;
        float a = tp_b0[j];
        #pragma unroll
        for (int i = 0; i < 2 * NFREQ + 1; i++)
            a += sm[OFF_TTF + q * 17 + i] * tp_w0[i * TEMB + j];
        sm[OFF_THT + q * 16 + j] = gelu_f(a);
    }
    __syncthreads();
    if (tid < 64) {
        int q = tid >> 4, j = tid & 15;
        float a = tp_b1[j];
        #pragma unroll
        for (int i = 0; i < TEMB; i++)
            a += sm[OFF_THT + q * 16 + i] * tp_w1[i * TEMB + j];
        sm[OFF_RHOIN4 + q * 28 + 12 + j] = a;
    }
    __syncthreads();
    // ---- rho h0: 256 outputs, 2 per thread ----
    #pragma unroll
    for (int s = 0; s < 2; s++) {
        int idx = tid + s * 128;
        int q = idx >> 6, j = idx & 63;
        float a = rho_b0[j];
        const float* rin = sm + OFF_RHOIN4 + q * 28;
        #pragma unroll 4
        for (int i = 0; i < RHOIN; i++) a += rin[i] * rho_w0[i * HID + j];
        sm[OFF_TRH0 + q * 64 + j] = gelu_f(a);
    }
    __syncthreads();
    // ---- rho h1 + w2, per-batch reduce ----
    float part[2];
    #pragma unroll
    for (int s = 0; s < 2; s++) {
        int idx = tid + s * 128;
        int q = idx >> 6, j = idx & 63;
        float a = rho_b1[j];
        const float* rh = sm + OFF_TRH0 + q * 64;
        #pragma unroll 4
        for (int k = 0; k < HID; k++) a += rh[k] * rho_w1[k * HID + j];
        part[s] = gelu_f(a) * rho_w2[j];
    }
    {
        const int lane = tid & 31, wid = tid >> 5;
        #pragma unroll
        for (int o = 16; o > 0; o >>= 1) {
            part[0] += __shfl_down_sync(0xffffffffu, part[0], o);
            part[1] += __shfl_down_sync(0xffffffffu, part[1], o);
        }
        if (lane == 0) { sm[OFF_RED + wid] = part[0]; sm[OFF_RED + 4 + wid] = part[1]; }
    }
    __syncthreads();
    if (tid < 4 && tid < nb) {
        float ssum = sm[OFF_RED + 2 * tid] + sm[OFF_RED + 2 * tid + 1];
        out[base + tid] = ssum + rho_b2[0] + sm[OFF_CUSP + tid];
    }
}

extern "C" void kernel_launch(void* const* d_in, const int* in_sizes, int n_in,
                              void* d_out, int out_size) {
    const float* x      = (const float*)d_in[0];
    const float* tau    = (const float*)d_in[1];
    const float* freqs  = (const float*)d_in[2];
    const float* phi_w0 = (const float*)d_in[3];
    const float* phi_b0 = (const float*)d_in[4];
    const float* phi_w1 = (const float*)d_in[5];
    const float* phi_b1 = (const float*)d_in[6];
    const float* phi_w2 = (const float*)d_in[7];
    const float* phi_b2 = (const float*)d_in[8];
    const float* psi_w0 = (const float*)d_in[9];
    const float* psi_b0 = (const float*)d_in[10];
    const float* psi_w1 = (const float*)d_in[11];
    const float* psi_b1 = (const float*)d_in[12];
    const float* psi_w2 = (const float*)d_in[13];
    const float* psi_b2 = (const float*)d_in[14];
    const float* rho_w0 = (const float*)d_in[15];
    const float* rho_b0 = (const float*)d_in[16];
    const float* rho_w1 = (const float*)d_in[17];
    const float* rho_b1 = (const float*)d_in[18];
    const float* rho_w2 = (const float*)d_in[19];
    const float* rho_b2 = (const float*)d_in[20];
    const float* tp_w0  = (const float*)d_in[21];
    const float* tp_b0  = (const float*)d_in[22];
    const float* tp_w1  = (const float*)d_in[23];
    const float* tp_b1  = (const float*)d_in[24];
    float* out = (float*)d_out;

    const int Btot = in_sizes[1];

    // 1) build the psi spline table (warp per knot)
    build_tab_kernel<<<(TAB_SLOTS + 3) / 4, 128>>>(
        psi_w0, psi_b0, psi_w1, psi_b1, psi_w2, psi_b2);

    // 2) main kernel
    const int nblocks = (Btot + BPB - 1) / BPB;
    cudaFuncSetAttribute(tau_jastrow_kernel,
                         cudaFuncAttributeMaxDynamicSharedMemorySize, SMEM_BYTES);
    tau_jastrow_kernel<<<nblocks, NTHREADS, SMEM_BYTES>>>(
        x, tau, freqs,
        phi_w0, phi_b0, phi_w1, phi_b1, phi_w2, phi_b2,
        rho_w0, rho_b0, rho_w1, rho_b1, rho_w2, rho_b2,
        tp_w0, tp_b0, tp_w1, tp_b1,
        out, Btot);
}

// round 12
// speedup vs baseline: 5.4994x; 1.1301x over previous
#include <cuda_runtime.h>
#include <math.h>

#define NPART 16
#define DDIM 3
#define HID 64
#define DLAT 5
#define TEMB 16
#define NFREQ 8
#define NPAIR 120
#define RHOIN 28
#define NTHREADS 128
#define BPB 4

#define TAB_N 512
#define TAB_SLOTS (TAB_N + 4)                       // 516 knots (incl -1 and +2 guards)
#define TAB_T0 0.6931471805599453f
#define TAB_TMAX 9.0f
#define TAB_H ((TAB_TMAX - TAB_T0) / (float)TAB_N)
#define TAB_INVH ((float)TAB_N / (TAB_TMAX - TAB_T0))

typedef unsigned long long ull;

// table: channels 0-3 of psi_out*gate in float4, channel 4 separate
__device__ float4 g_tab4[TAB_SLOTS];
__device__ float  g_tab1[TAB_SLOTS];

// ---- dynamic smem layout (float offsets) ----
// union region [0, 4096): table (2580 floats) during main loop;
// phi h0 transposed [16][4][64] (4096) + TTF/THT/TRH0 scratch during tail
#define OFF_TAB4    0              // 516 float4 = 2064 floats
#define OFF_TAB1    2064           // 516  (table total 2580)
#define OFF_TTF     0
#define OFF_THT     128
#define OFF_TRH0    384
#define OFF_H0T     0              // tail phi h0 transposed base (4096)
#define OFF_PHI_W1T 4096           // 4096
#define OFF_PHI_W0  8192           // 192
#define OFF_PHI_B0  8384           // 64
#define OFF_PHI_B1  8448           // 64
#define OFF_PHI_W2  8512           // 320
#define OFF_PHI_B2  8832           // 8
#define OFF_X       8840           // 48
#define OFF_RED     8888           // 56
#define OFF_RHOIN4  8944           // 4 x 28 = 112
#define OFF_CUSP    9056           // 4
#define SMEM_FLOATS 9060
#define SMEM_BYTES  (SMEM_FLOATS * 4)

// ---- packed f32x2 helpers ----
__device__ __forceinline__ ull pack2(float lo, float hi) {
    ull r; asm("mov.b64 %0, {%1, %2};" : "=l"(r) : "f"(lo), "f"(hi)); return r;
}
__device__ __forceinline__ ull dup2(float b) {
    ull r; asm("mov.b64 %0, {%1, %1};" : "=l"(r) : "f"(b)); return r;
}
__device__ __forceinline__ float2 unpack2(ull v) {
    float2 f; asm("mov.b64 {%0, %1}, %2;" : "=f"(f.x), "=f"(f.y) : "l"(v)); return f;
}
__device__ __forceinline__ void ffma2(ull& d, ull a, ull b) {
    asm("fma.rn.f32x2 %0, %1, %2, %0;" : "+l"(d) : "l"(a), "l"(b));
}
__device__ __forceinline__ ull fma2(ull a, ull b, ull c) {
    ull d; asm("fma.rn.f32x2 %0, %1, %2, %3;" : "=l"(d) : "l"(a), "l"(b), "l"(c)); return d;
}
__device__ __forceinline__ ull mul2(ull a, ull b) {
    ull d; asm("mul.rn.f32x2 %0, %1, %2;" : "=l"(d) : "l"(a), "l"(b)); return d;
}
__device__ __forceinline__ ull add2(ull a, ull b) {
    ull d; asm("add.rn.f32x2 %0, %1, %2;" : "=l"(d) : "l"(a), "l"(b)); return d;
}

// ---- gelu: A&S 7.1.26 erf (|err|<=1.5e-7), branchless (EX2 on MUFU pipe)
__device__ __forceinline__ float gelu_f(float x) {
    float ax = fabsf(x);
    float z = ax * 0.70710678118f;
    float t = __fdividef(1.0f, fmaf(0.3275911f, z, 1.0f));
    float p = t * fmaf(t, fmaf(t, fmaf(t, fmaf(t, 1.061405429f, -1.453152027f),
                         1.421413741f), -0.284496736f), 0.254829592f);
    float q = p * exp2f(-1.442695041f * z * z);
    return 0.5f * ((x + ax) - ax * q);
}

__device__ __forceinline__ ull gelu2(ull x2) {
    ull ax2;
    asm("and.b64 %0, %1, %2;" : "=l"(ax2) : "l"(x2), "l"(0x7fffffff7fffffffULL));
    ull z2 = mul2(ax2, dup2(0.70710678118f));
    float2 z = unpack2(z2);
    float tx = __fdividef(1.0f, fmaf(0.3275911f, z.x, 1.0f));
    float ty = __fdividef(1.0f, fmaf(0.3275911f, z.y, 1.0f));
    ull t2 = pack2(tx, ty);
    ull p2 = fma2(t2, dup2(1.061405429f), dup2(-1.453152027f));
    p2 = fma2(p2, t2, dup2(1.421413741f));
    p2 = fma2(p2, t2, dup2(-0.284496736f));
    p2 = fma2(p2, t2, dup2(0.254829592f));
    p2 = mul2(p2, t2);
    float2 m = unpack2(mul2(mul2(z2, z2), dup2(-1.442695041f)));
    ull q2 = mul2(p2, pack2(exp2f(m.x), exp2f(m.y)));
    ull s2 = add2(x2, ax2);
    ull w2 = mul2(ax2, q2);
    return fma2(w2, dup2(-0.5f), mul2(s2, dup2(0.5f)));
}

// precise gelu for the table builder
__device__ __forceinline__ float gelu_exact(float x) {
    return 0.5f * x * (1.0f + erff(x * 0.70710678118654752f));
}

// ================= table builder: warp per knot =================
__global__ void build_tab_kernel(
    const float* __restrict__ psi_w0, const float* __restrict__ psi_b0,
    const float* __restrict__ psi_w1, const float* __restrict__ psi_b1,
    const float* __restrict__ psi_w2, const float* __restrict__ psi_b2)
{
    __shared__ float h0s[4][HID];
    const int wid = threadIdx.x >> 5, lane = threadIdx.x & 31;
    const int j = blockIdx.x * 4 + wid;
    if (j >= TAB_SLOTS) return;

    float t = TAB_T0 + (float)(j - 1) * TAB_H;      // knot j-1
    float r2 = expm1f(t) * 0.04f - 0.04f;           // invert t = log1p(25*(r2+0.04))
    float rt2 = r2 + 0.04f;
    float u = rt2 * 25.0f;
    float feat[6];
    float s1 = log1pf(u);
    feat[0] = s1;
    feat[1] = r2 / rt2;
    feat[2] = u * expf(-u);
    feat[3] = expf(-0.25f * s1);
    feat[4] = expf(-s1);
    feat[5] = expf(-4.0f * s1);
    float gate = r2 / (r2 + 0.09f);

    // h0 for k = lane, lane+32
    #pragma unroll
    for (int s = 0; s < 2; s++) {
        int k = lane + 32 * s;
        float a = psi_b0[k];
        #pragma unroll
        for (int i = 0; i < 6; i++) a += feat[i] * psi_w0[i * HID + k];
        h0s[wid][k] = gelu_exact(a);
    }
    __syncwarp();

    // h1 + W2 contraction for q = lane, lane+32
    float outv[DLAT] = {0.f, 0.f, 0.f, 0.f, 0.f};
    #pragma unroll
    for (int s = 0; s < 2; s++) {
        int q = lane + 32 * s;
        float a = psi_b1[q];
        #pragma unroll 8
        for (int k = 0; k < HID; k++) a += h0s[wid][k] * psi_w1[k * HID + q];
        float g = gelu_exact(a);
        #pragma unroll
        for (int d = 0; d < DLAT; d++) outv[d] += g * psi_w2[q * DLAT + d];
    }
    #pragma unroll
    for (int d = 0; d < DLAT; d++) {
        float v = outv[d];
        #pragma unroll
        for (int o = 16; o > 0; o >>= 1)
            v += __shfl_down_sync(0xffffffffu, v, o);
        outv[d] = v;
    }
    if (lane == 0) {
        #pragma unroll
        for (int d = 0; d < DLAT; d++) outv[d] += psi_b2[d];
        g_tab4[j] = make_float4(outv[0] * gate, outv[1] * gate,
                                outv[2] * gate, outv[3] * gate);
        g_tab1[j] = outv[4] * gate;
    }
}

// ================= main kernel =================
__global__ __launch_bounds__(NTHREADS, 6)
void tau_jastrow_kernel(
    const float* __restrict__ x, const float* __restrict__ tau, const float* __restrict__ freqs,
    const float* __restrict__ phi_w0, const float* __restrict__ phi_b0,
    const float* __restrict__ phi_w1, const float* __restrict__ phi_b1,
    const float* __restrict__ phi_w2, const float* __restrict__ phi_b2,
    const float* __restrict__ rho_w0, const float* __restrict__ rho_b0,
    const float* __restrict__ rho_w1, const float* __restrict__ rho_b1,
    const float* __restrict__ rho_w2, const float* __restrict__ rho_b2,
    const float* __restrict__ tp_w0, const float* __restrict__ tp_b0,
    const float* __restrict__ tp_w1, const float* __restrict__ tp_b1,
    float* __restrict__ out, int Btot)
{
    extern __shared__ float sm[];
    const int tid = threadIdx.x;

    // ---- stage table + phi small weights ----
    {
        float4* st4 = (float4*)(sm + OFF_TAB4);
        for (int i = tid; i < TAB_SLOTS; i += NTHREADS) st4[i] = g_tab4[i];
        for (int i = tid; i < TAB_SLOTS; i += NTHREADS) sm[OFF_TAB1 + i] = g_tab1[i];
    }
    for (int i = tid; i < 3 * HID; i += NTHREADS) sm[OFF_PHI_W0 + i] = phi_w0[i];
    for (int i = tid; i < HID * DLAT; i += NTHREADS) sm[OFF_PHI_W2 + i] = phi_w2[i];
    if (tid < HID) { sm[OFF_PHI_B0 + tid] = phi_b0[tid]; sm[OFF_PHI_B1 + tid] = phi_b1[tid]; }
    if (tid < DLAT) sm[OFF_PHI_B2 + tid] = phi_b2[tid];

    // ---- pair indices (triu k=1 row-major) ----
    int pi = 0, pj = 0;
    {
        int p2 = tid, i2 = 0, cnt = NPART - 1;
        while (cnt > 0 && p2 >= cnt) { p2 -= cnt; i2++; cnt--; }
        pi = i2; pj = i2 + 1 + p2;
        if (pj >= NPART) pj = NPART - 1;
    }
    const bool active = (tid < NPAIR);
    const float gamma = ((pi < NPART / 2) == (pj < NPART / 2))
                        ? (1.0f / (DDIM + 1)) : (1.0f / (DDIM - 1));

    const int base = blockIdx.x * BPB;
    const int nb = (Btot - base < BPB) ? (Btot - base) : BPB;

    // ======================= per-batch main loop (spline psi) =======================
    for (int bi = 0; bi < nb; ++bi) {
        const int b = base + bi;
        if (tid < NPART * DDIM) sm[OFF_X + tid] = x[(size_t)b * (NPART * DDIM) + tid];
        __syncthreads();

        float vals[8];
        #pragma unroll
        for (int v = 0; v < 8; v++) vals[v] = 0.f;
        if (tid < NPART * DDIM) {
            float xv = sm[OFF_X + tid];
            vals[7] = xv * xv;
        }

        if (active) {
            float d0 = sm[OFF_X + pi * 3 + 0] - sm[OFF_X + pj * 3 + 0];
            float d1 = sm[OFF_X + pi * 3 + 1] - sm[OFF_X + pj * 3 + 1];
            float d2 = sm[OFF_X + pi * 3 + 2] - sm[OFF_X + pj * 3 + 2];
            float r2 = d0 * d0 + d1 * d1 + d2 * d2;
            float rt2 = r2 + 0.04f;
            float tt = __fdividef(1.0f, fmaf(25.0f, rt2, 1.0f));
            float t = -__logf(tt);                       // s1
            float r = sqrtf(r2 + 1.1920929e-7f);
            vals[5] = t;
            vals[6] = gamma * r * __expf(-r);            // cusp (exact path)

            // Catmull-Rom spline eval
            float idxf = (t - TAB_T0) * TAB_INVH;
            int i = (int)idxf;
            if (i > TAB_N - 1) i = TAB_N - 1;
            if (i < 0) i = 0;
            float uf = idxf - (float)i;
            float u2 = uf * uf, u3 = u2 * uf;
            float cw0 = 0.5f * (-u3 + 2.0f * u2 - uf);
            float cw1 = 0.5f * (3.0f * u3 - 5.0f * u2 + 2.0f);
            float cw2 = 0.5f * (-3.0f * u3 + 4.0f * u2 + uf);
            float cw3 = 0.5f * (u3 - u2);
            const float4* t4 = (const float4*)(sm + OFF_TAB4);
            float4 e0 = t4[i], e1 = t4[i + 1], e2 = t4[i + 2], e3 = t4[i + 3];
            vals[0] = cw0 * e0.x + cw1 * e1.x + cw2 * e2.x + cw3 * e3.x;
            vals[1] = cw0 * e0.y + cw1 * e1.y + cw2 * e2.y + cw3 * e3.y;
            vals[2] = cw0 * e0.z + cw1 * e1.z + cw2 * e2.z + cw3 * e3.z;
            vals[3] = cw0 * e0.w + cw1 * e1.w + cw2 * e2.w + cw3 * e3.w;
            vals[4] = cw0 * sm[OFF_TAB1 + i]     + cw1 * sm[OFF_TAB1 + i + 1]
                    + cw2 * sm[OFF_TAB1 + i + 2] + cw3 * sm[OFF_TAB1 + i + 3];
        }

        // ---- fused 8-value block reduction ----
        {
            const int lane = tid & 31, wid = tid >> 5;
            #pragma unroll
            for (int v = 0; v < 8; v++) {
                float t = vals[v];
                #pragma unroll
                for (int o = 16; o > 0; o >>= 1)
                    t += __shfl_down_sync(0xffffffffu, t, o);
                if (lane == 0) sm[OFF_RED + v * 4 + wid] = t;
            }
        }
        __syncthreads();
        if (tid < 8) {
            float s = sm[OFF_RED + tid * 4 + 0] + sm[OFF_RED + tid * 4 + 1]
                    + sm[OFF_RED + tid * 4 + 2] + sm[OFF_RED + tid * 4 + 3];
            float* rin = sm + OFF_RHOIN4 + bi * 28;
            if (tid < 5) {
                rin[5 + tid] = s * (1.0f / NPAIR);       // table folds b2 and gate
            } else if (tid == 5) {
                rin[11] = s * (1.0f / NPAIR);            // s1_mean
            } else if (tid == 6) {
                sm[OFF_CUSP + bi] = s;
            } else {
                rin[10] = s * (1.0f / (NPART * DDIM));   // r2_mean
            }
        }
        // next iteration's top sync orders these writes
    }
    __syncthreads();   // table region about to be reused by phi h0

    // ======================= batched tail =======================
    // ---- stage phi W1T (k-tiled transposed) ----
    {
        const float4* gw = (const float4*)phi_w1;
        #pragma unroll
        for (int i = 0; i < 8; i++) {
            int idx4 = tid + 128 * i;
            float4 v = gw[idx4];
            int k = idx4 >> 4;
            int j0 = (idx4 & 15) * 4;
            float* d = sm + OFF_PHI_W1T + (k >> 2) * 256 + (k & 3) + j0 * 4;
            d[0] = v.x; d[4] = v.y; d[8] = v.z; d[12] = v.w;
        }
    }
    // ---- phi h0 for all nb batches, TRANSPOSED store [kt][kc][row] ----
    {
        const int R = tid >> 1, q = R >> 4, p = R & 15, kh = tid & 1;
        const int qq = (q < nb) ? q : 0;
        const float* xb = x + (size_t)(base + qq) * (NPART * DDIM) + p * 3;
        float xv0 = xb[0], xv1 = xb[1], xv2 = xb[2];
        const float4* w0 = (const float4*)(sm + OFF_PHI_W0);
        const float4* b0 = (const float4*)(sm + OFF_PHI_B0);
        #pragma unroll
        for (int t8 = 0; t8 < 8; t8++) {
            int kt = kh * 8 + t8;
            float4 a = b0[kt];
            float4 w;
            w = w0[0 * 16 + kt];
            a.x += xv0 * w.x; a.y += xv0 * w.y; a.z += xv0 * w.z; a.w += xv0 * w.w;
            w = w0[1 * 16 + kt];
            a.x += xv1 * w.x; a.y += xv1 * w.y; a.z += xv1 * w.z; a.w += xv1 * w.w;
            w = w0[2 * 16 + kt];
            a.x += xv2 * w.x; a.y += xv2 * w.y; a.z += xv2 * w.z; a.w += xv2 * w.w;
            float2 g01 = unpack2(gelu2(pack2(a.x, a.y)));
            float2 g23 = unpack2(gelu2(pack2(a.z, a.w)));
            float* dst = sm + OFF_H0T + kt * 256 + R;   // aliases dead table
            dst[0]   = g01.x;
            dst[64]  = g01.y;
            dst[128] = g23.x;
            dst[192] = g23.y;
        }
    }
    __syncthreads();
    // ---- phi h1 GEMM (64x64 @ 64x64) packed f32x2; warp w == batch w ----
    {
        const int rg = tid >> 4, cg = tid & 15;   // rg: 8 rows (4 row-pairs); cg: 4 cols
        const int q = rg >> 1;
        ull acc[4][4];
        #pragma unroll
        for (int c = 0; c < 4; c++) {
            ull bi1 = dup2(sm[OFF_PHI_B1 + cg + 16 * c]);
            #pragma unroll
            for (int p = 0; p < 4; p++) acc[p][c] = bi1;
        }
        const float4* w1t4 = (const float4*)(sm + OFF_PHI_W1T);
        #pragma unroll 1
        for (int kt = 0; kt < 16; kt++) {
            float4 bv0 = w1t4[kt * 64 + cg];
            float4 bv1 = w1t4[kt * 64 + cg + 16];
            float4 bv2 = w1t4[kt * 64 + cg + 32];
            float4 bv3 = w1t4[kt * 64 + cg + 48];
            const float* hb = sm + OFF_H0T + kt * 256 + rg * 8;
            #define KC_STEP(kc, comp)                                       \
            {                                                               \
                ull b20 = dup2(bv0.comp);                                   \
                ull b21 = dup2(bv1.comp);                                   \
                ull b22 = dup2(bv2.comp);                                   \
                ull b23 = dup2(bv3.comp);                                   \
                const ull* ap = (const ull*)(hb + (kc) * 64);               \
                _Pragma("unroll")                                           \
                for (int p = 0; p < 4; p++) {                               \
                    ull aa = ap[p];                                         \
                    ffma2(acc[p][0], aa, b20);                              \
                    ffma2(acc[p][1], aa, b21);                              \
                    ffma2(acc[p][2], aa, b22);                              \
                    ffma2(acc[p][3], aa, b23);                              \
                }                                                           \
            }
            KC_STEP(0, x) KC_STEP(1, y) KC_STEP(2, z) KC_STEP(3, w)
            #undef KC_STEP
        }
        // epilogue: packed gelu -> W2 (row-pairs stay packed; both rows same batch)
        ull pv2[5];
        #pragma unroll
        for (int d = 0; d < 5; d++) pv2[d] = dup2(0.f);
        #pragma unroll
        for (int c = 0; c < 4; c++) {
            const int j = cg + 16 * c;
            ull w2d[5];
            #pragma unroll
            for (int d = 0; d < 5; d++) w2d[d] = dup2(sm[OFF_PHI_W2 + j * 5 + d]);
            #pragma unroll
            for (int p = 0; p < 4; p++) {
                ull gg = gelu2(acc[p][c]);
                #pragma unroll
                for (int d = 0; d < 5; d++) pv2[d] = fma2(gg, w2d[d], pv2[d]);
            }
        }
        float pv[5];
        #pragma unroll
        for (int d = 0; d < 5; d++) {
            float2 f = unpack2(pv2[d]);
            float t = f.x + f.y;
            #pragma unroll
            for (int o = 16; o > 0; o >>= 1)
                t += __shfl_down_sync(0xffffffffu, t, o);
            pv[d] = t;
        }
        if ((tid & 31) == 0 && q < nb) {
            float* rin = sm + OFF_RHOIN4 + q * 28;
            #pragma unroll
            for (int d = 0; d < 5; d++)
                rin[d] = pv[d] * (1.0f / NPART) + sm[OFF_PHI_B2 + d];
        }
    }
    __syncthreads();
    // ---- temb for all nb batches (scratch aliases dead phi h0) ----
    if (tid < 32) {
        int q = tid >> 3, i = tid & 7;
        if (q < nb) {
            float t = tau[base + q];
            if (i == 0) sm[OFF_TTF + q * 17] = t;
            float ft = freqs[i] * t;
            sm[OFF_TTF + q * 17 + 1 + i] = __sinf(ft);
            sm[OFF_TTF + q * 17 + 9 + i] = __cosf(ft);
        }
    }
    __syncthreads();
    if (tid < 64) {
        int q = tid >> 4, j = tid & 15;
        float a = tp_b0[j];
        #pragma unroll
        for (int i = 0; i < 2 * NFREQ + 1; i++)
            a += sm[OFF_TTF + q * 17 + i] * tp_w0[i * TEMB + j];
        sm[OFF_THT + q * 16 + j] = gelu_f(a);
    }
    __syncthreads();
    if (tid < 64) {
        int q = tid >> 4, j = tid & 15;
        float a = tp_b1[j];
        #pragma unroll
        for (int i = 0; i < TEMB; i++)
            a += sm[OFF_THT + q * 16 + i] * tp_w1[i * TEMB + j];
        sm[OFF_RHOIN4 + q * 28 + 12 + j] = a;
    }
    __syncthreads();
    // ---- rho h0: 256 outputs, 2 per thread ----
    #pragma unroll
    for (int s = 0; s < 2; s++) {
        int idx = tid + s * 128;
        int q = idx >> 6, j = idx & 63;
        float a = rho_b0[j];
        const float* rin = sm + OFF_RHOIN4 + q * 28;
        #pragma unroll 4
        for (int i = 0; i < RHOIN; i++) a += rin[i] * rho_w0[i * HID + j];
        sm[OFF_TRH0 + q * 64 + j] = gelu_f(a);
    }
    __syncthreads();
    // ---- rho h1 + w2, per-batch reduce ----
    float part[2];
    #pragma unroll
    for (int s = 0; s < 2; s++) {
        int idx = tid + s * 128;
        int q = idx >> 6, j = idx & 63;
        float a = rho_b1[j];
        const float* rh = sm + OFF_TRH0 + q * 64;
        #pragma unroll 4
        for (int k = 0; k < HID; k++) a += rh[k] * rho_w1[k * HID + j];
        part[s] = gelu_f(a) * rho_w2[j];
    }
    {
        const int lane = tid & 31, wid = tid >> 5;
        #pragma unroll
        for (int o = 16; o > 0; o >>= 1) {
            part[0] += __shfl_down_sync(0xffffffffu, part[0], o);
            part[1] += __shfl_down_sync(0xffffffffu, part[1], o);
        }
        if (lane == 0) { sm[OFF_RED + wid] = part[0]; sm[OFF_RED + 4 + wid] = part[1]; }
    }
    __syncthreads();
    if (tid < 4 && tid < nb) {
        float ssum = sm[OFF_RED + 2 * tid] + sm[OFF_RED + 2 * tid + 1];
        out[base + tid] = ssum + rho_b2[0] + sm[OFF_CUSP + tid];
    }
}

extern "C" void kernel_launch(void* const* d_in, const int* in_sizes, int n_in,
                              void* d_out, int out_size) {
    const float* x      = (const float*)d_in[0];
    const float* tau    = (const float*)d_in[1];
    const float* freqs  = (const float*)d_in[2];
    const float* phi_w0 = (const float*)d_in[3];
    const float* phi_b0 = (const float*)d_in[4];
    const float* phi_w1 = (const float*)d_in[5];
    const float* phi_b1 = (const float*)d_in[6];
    const float* phi_w2 = (const float*)d_in[7];
    const float* phi_b2 = (const float*)d_in[8];
    const float* psi_w0 = (const float*)d_in[9];
    const float* psi_b0 = (const float*)d_in[10];
    const float* psi_w1 = (const float*)d_in[11];
    const float* psi_b1 = (const float*)d_in[12];
    const float* psi_w2 = (const float*)d_in[13];
    const float* psi_b2 = (const float*)d_in[14];
    const float* rho_w0 = (const float*)d_in[15];
    const float* rho_b0 = (const float*)d_in[16];
    const float* rho_w1 = (const float*)d_in[17];
    const float* rho_b1 = (const float*)d_in[18];
    const float* rho_w2 = (const float*)d_in[19];
    const float* rho_b2 = (const float*)d_in[20];
    const float* tp_w0  = (const float*)d_in[21];
    const float* tp_b0  = (const float*)d_in[22];
    const float* tp_w1  = (const float*)d_in[23];
    const float* tp_b1  = (const float*)d_in[24];
    float* out = (float*)d_out;

    const int Btot = in_sizes[1];

    // 1) build the psi spline table (warp per knot)
    build_tab_kernel<<<(TAB_SLOTS + 3) / 4, 128>>>(
        psi_w0, psi_b0, psi_w1, psi_b1, psi_w2, psi_b2);

    // 2) main kernel
    const int nblocks = (Btot + BPB - 1) / BPB;
    cudaFuncSetAttribute(tau_jastrow_kernel,
                         cudaFuncAttributeMaxDynamicSharedMemorySize, SMEM_BYTES);
    tau_jastrow_kernel<<<nblocks, NTHREADS, SMEM_BYTES>>>(
        x, tau, freqs,
        phi_w0, phi_b0, phi_w1, phi_b1, phi_w2, phi_b2,
        rho_w0, rho_b0, rho_w1, rho_b1, rho_w2, rho_b2,
        tp_w0, tp_b0, tp_w1, tp_b1,
        out, Btot);
}

// round 13
// speedup vs baseline: 5.6207x; 1.0221x over previous
#include <cuda_runtime.h>
#include <math.h>

#define NPART 16
#define DDIM 3
#define HID 64
#define DLAT 5
#define TEMB 16
#define NFREQ 8
#define NPAIR 120
#define RHOIN 28
#define NTHREADS 128
#define BPB 4

#define TAB_N 512
#define TAB_SLOTS (TAB_N + 4)                       // 516 knots (incl -1 and +2 guards)
#define TAB_T0 0.6931471805599453f
#define TAB_TMAX 9.0f
#define TAB_H ((TAB_TMAX - TAB_T0) / (float)TAB_N)
#define TAB_INVH ((float)TAB_N / (TAB_TMAX - TAB_T0))

typedef unsigned long long ull;

// table: channels 0-3 of psi_out*gate in float4, channel 4 separate
__device__ float4 g_tab4[TAB_SLOTS];
__device__ float  g_tab1[TAB_SLOTS];

// ---- dynamic smem layout (float offsets) ----
// union region [0, 4096): table (2580 floats) during main loop;
// phi h0 transposed [16][4][64] (4096) + TTF/THT/TRH0 scratch during tail
#define OFF_TAB4    0              // 516 float4 = 2064 floats
#define OFF_TAB1    2064           // 516  (table total 2580)
#define OFF_TTF     0
#define OFF_THT     128
#define OFF_TRH0    384
#define OFF_H0T     0              // tail phi h0 transposed base (4096)
#define OFF_PHI_W1T 4096           // 4096
#define OFF_PHI_W0  8192           // 192
#define OFF_PHI_B0  8384           // 64
#define OFF_PHI_B1  8448           // 64
#define OFF_PHI_W2  8512           // 320
#define OFF_PHI_B2  8832           // 8
#define OFF_X4      8840           // 4 x 48 = 192
#define OFF_PART    9032           // 4 batches x 8 ch x 4 warps = 128
#define OFF_RED     9160           // 56
#define OFF_RHOIN4  9216           // 4 x 28 = 112
#define OFF_CUSP    9328           // 4
#define SMEM_FLOATS 9332
#define SMEM_BYTES  (SMEM_FLOATS * 4)

// ---- packed f32x2 helpers ----
__device__ __forceinline__ ull pack2(float lo, float hi) {
    ull r; asm("mov.b64 %0, {%1, %2};" : "=l"(r) : "f"(lo), "f"(hi)); return r;
}
__device__ __forceinline__ ull dup2(float b) {
    ull r; asm("mov.b64 %0, {%1, %1};" : "=l"(r) : "f"(b)); return r;
}
__device__ __forceinline__ float2 unpack2(ull v) {
    float2 f; asm("mov.b64 {%0, %1}, %2;" : "=f"(f.x), "=f"(f.y) : "l"(v)); return f;
}
__device__ __forceinline__ void ffma2(ull& d, ull a, ull b) {
    asm("fma.rn.f32x2 %0, %1, %2, %0;" : "+l"(d) : "l"(a), "l"(b));
}
__device__ __forceinline__ ull fma2(ull a, ull b, ull c) {
    ull d; asm("fma.rn.f32x2 %0, %1, %2, %3;" : "=l"(d) : "l"(a), "l"(b), "l"(c)); return d;
}
__device__ __forceinline__ ull mul2(ull a, ull b) {
    ull d; asm("mul.rn.f32x2 %0, %1, %2;" : "=l"(d) : "l"(a), "l"(b)); return d;
}
__device__ __forceinline__ ull add2(ull a, ull b) {
    ull d; asm("add.rn.f32x2 %0, %1, %2;" : "=l"(d) : "l"(a), "l"(b)); return d;
}

// ---- gelu: A&S 7.1.26 erf (|err|<=1.5e-7), branchless (EX2 on MUFU pipe)
__device__ __forceinline__ float gelu_f(float x) {
    float ax = fabsf(x);
    float z = ax * 0.70710678118f;
    float t = __fdividef(1.0f, fmaf(0.3275911f, z, 1.0f));
    float p = t * fmaf(t, fmaf(t, fmaf(t, fmaf(t, 1.061405429f, -1.453152027f),
                         1.421413741f), -0.284496736f), 0.254829592f);
    float q = p * exp2f(-1.442695041f * z * z);
    return 0.5f * ((x + ax) - ax * q);
}

__device__ __forceinline__ ull gelu2(ull x2) {
    ull ax2;
    asm("and.b64 %0, %1, %2;" : "=l"(ax2) : "l"(x2), "l"(0x7fffffff7fffffffULL));
    ull z2 = mul2(ax2, dup2(0.70710678118f));
    float2 z = unpack2(z2);
    float tx = __fdividef(1.0f, fmaf(0.3275911f, z.x, 1.0f));
    float ty = __fdividef(1.0f, fmaf(0.3275911f, z.y, 1.0f));
    ull t2 = pack2(tx, ty);
    ull p2 = fma2(t2, dup2(1.061405429f), dup2(-1.453152027f));
    p2 = fma2(p2, t2, dup2(1.421413741f));
    p2 = fma2(p2, t2, dup2(-0.284496736f));
    p2 = fma2(p2, t2, dup2(0.254829592f));
    p2 = mul2(p2, t2);
    float2 m = unpack2(mul2(mul2(z2, z2), dup2(-1.442695041f)));
    ull q2 = mul2(p2, pack2(exp2f(m.x), exp2f(m.y)));
    ull s2 = add2(x2, ax2);
    ull w2 = mul2(ax2, q2);
    return fma2(w2, dup2(-0.5f), mul2(s2, dup2(0.5f)));
}

// precise gelu for the table builder
__device__ __forceinline__ float gelu_exact(float x) {
    return 0.5f * x * (1.0f + erff(x * 0.70710678118654752f));
}

// ================= table builder: warp per knot =================
__global__ void build_tab_kernel(
    const float* __restrict__ psi_w0, const float* __restrict__ psi_b0,
    const float* __restrict__ psi_w1, const float* __restrict__ psi_b1,
    const float* __restrict__ psi_w2, const float* __restrict__ psi_b2)
{
    __shared__ float h0s[4][HID];
    const int wid = threadIdx.x >> 5, lane = threadIdx.x & 31;
    const int j = blockIdx.x * 4 + wid;
    if (j >= TAB_SLOTS) return;

    float t = TAB_T0 + (float)(j - 1) * TAB_H;      // knot j-1
    float r2 = expm1f(t) * 0.04f - 0.04f;           // invert t = log1p(25*(r2+0.04))
    float rt2 = r2 + 0.04f;
    float u = rt2 * 25.0f;
    float feat[6];
    float s1 = log1pf(u);
    feat[0] = s1;
    feat[1] = r2 / rt2;
    feat[2] = u * expf(-u);
    feat[3] = expf(-0.25f * s1);
    feat[4] = expf(-s1);
    feat[5] = expf(-4.0f * s1);
    float gate = r2 / (r2 + 0.09f);

    // h0 for k = lane, lane+32
    #pragma unroll
    for (int s = 0; s < 2; s++) {
        int k = lane + 32 * s;
        float a = psi_b0[k];
        #pragma unroll
        for (int i = 0; i < 6; i++) a += feat[i] * psi_w0[i * HID + k];
        h0s[wid][k] = gelu_exact(a);
    }
    __syncwarp();

    // h1 + W2 contraction for q = lane, lane+32
    float outv[DLAT] = {0.f, 0.f, 0.f, 0.f, 0.f};
    #pragma unroll
    for (int s = 0; s < 2; s++) {
        int q = lane + 32 * s;
        float a = psi_b1[q];
        #pragma unroll 8
        for (int k = 0; k < HID; k++) a += h0s[wid][k] * psi_w1[k * HID + q];
        float g = gelu_exact(a);
        #pragma unroll
        for (int d = 0; d < DLAT; d++) outv[d] += g * psi_w2[q * DLAT + d];
    }
    #pragma unroll
    for (int d = 0; d < DLAT; d++) {
        float v = outv[d];
        #pragma unroll
        for (int o = 16; o > 0; o >>= 1)
            v += __shfl_down_sync(0xffffffffu, v, o);
        outv[d] = v;
    }
    if (lane == 0) {
        #pragma unroll
        for (int d = 0; d < DLAT; d++) outv[d] += psi_b2[d];
        g_tab4[j] = make_float4(outv[0] * gate, outv[1] * gate,
                                outv[2] * gate, outv[3] * gate);
        g_tab1[j] = outv[4] * gate;
    }
}

// ================= main kernel =================
__global__ __launch_bounds__(NTHREADS, 6)
void tau_jastrow_kernel(
    const float* __restrict__ x, const float* __restrict__ tau, const float* __restrict__ freqs,
    const float* __restrict__ phi_w0, const float* __restrict__ phi_b0,
    const float* __restrict__ phi_w1, const float* __restrict__ phi_b1,
    const float* __restrict__ phi_w2, const float* __restrict__ phi_b2,
    const float* __restrict__ rho_w0, const float* __restrict__ rho_b0,
    const float* __restrict__ rho_w1, const float* __restrict__ rho_b1,
    const float* __restrict__ rho_w2, const float* __restrict__ rho_b2,
    const float* __restrict__ tp_w0, const float* __restrict__ tp_b0,
    const float* __restrict__ tp_w1, const float* __restrict__ tp_b1,
    float* __restrict__ out, int Btot)
{
    extern __shared__ float sm[];
    const int tid = threadIdx.x;
    const int lane = tid & 31, wrp = tid >> 5;

    // ---- stage table + phi small weights + all 4 batches' x ----
    {
        float4* st4 = (float4*)(sm + OFF_TAB4);
        for (int i = tid; i < TAB_SLOTS; i += NTHREADS) st4[i] = g_tab4[i];
        for (int i = tid; i < TAB_SLOTS; i += NTHREADS) sm[OFF_TAB1 + i] = g_tab1[i];
    }
    for (int i = tid; i < 3 * HID; i += NTHREADS) sm[OFF_PHI_W0 + i] = phi_w0[i];
    for (int i = tid; i < HID * DLAT; i += NTHREADS) sm[OFF_PHI_W2 + i] = phi_w2[i];
    if (tid < HID) { sm[OFF_PHI_B0 + tid] = phi_b0[tid]; sm[OFF_PHI_B1 + tid] = phi_b1[tid]; }
    if (tid < DLAT) sm[OFF_PHI_B2 + tid] = phi_b2[tid];

    const int base = blockIdx.x * BPB;
    const int nb = (Btot - base < BPB) ? (Btot - base) : BPB;
    for (int i = tid; i < nb * NPART * DDIM; i += NTHREADS)
        sm[OFF_X4 + i] = x[(size_t)base * (NPART * DDIM) + i];

    // ---- pair indices (triu k=1 row-major) ----
    int pi = 0, pj = 0;
    {
        int p2 = tid, i2 = 0, cnt = NPART - 1;
        while (cnt > 0 && p2 >= cnt) { p2 -= cnt; i2++; cnt--; }
        pi = i2; pj = i2 + 1 + p2;
        if (pj >= NPART) pj = NPART - 1;
    }
    const bool active = (tid < NPAIR);
    const float gamma = ((pi < NPART / 2) == (pj < NPART / 2))
                        ? (1.0f / (DDIM + 1)) : (1.0f / (DDIM - 1));

    __syncthreads();   // staging + x4 visible

    // ============== barrier-free main loop: warps independent ==============
    for (int bi = 0; bi < nb; ++bi) {
        const float* xb = sm + OFF_X4 + bi * (NPART * DDIM);

        float vals[8];
        #pragma unroll
        for (int v = 0; v < 8; v++) vals[v] = 0.f;
        if (tid < NPART * DDIM) {
            float xv = xb[tid];
            vals[7] = xv * xv;
        }

        if (active) {
            float d0 = xb[pi * 3 + 0] - xb[pj * 3 + 0];
            float d1 = xb[pi * 3 + 1] - xb[pj * 3 + 1];
            float d2 = xb[pi * 3 + 2] - xb[pj * 3 + 2];
            float r2 = d0 * d0 + d1 * d1 + d2 * d2;
            float rt2 = r2 + 0.04f;
            float tt = __fdividef(1.0f, fmaf(25.0f, rt2, 1.0f));
            float t = -__logf(tt);                       // s1
            float r = sqrtf(r2 + 1.1920929e-7f);
            vals[5] = t;
            vals[6] = gamma * r * __expf(-r);            // cusp (exact path)

            // Catmull-Rom spline eval
            float idxf = (t - TAB_T0) * TAB_INVH;
            int i = (int)idxf;
            if (i > TAB_N - 1) i = TAB_N - 1;
            if (i < 0) i = 0;
            float uf = idxf - (float)i;
            float u2 = uf * uf, u3 = u2 * uf;
            float cw0 = 0.5f * (-u3 + 2.0f * u2 - uf);
            float cw1 = 0.5f * (3.0f * u3 - 5.0f * u2 + 2.0f);
            float cw2 = 0.5f * (-3.0f * u3 + 4.0f * u2 + uf);
            float cw3 = 0.5f * (u3 - u2);
            const float4* t4 = (const float4*)(sm + OFF_TAB4);
            float4 e0 = t4[i], e1 = t4[i + 1], e2 = t4[i + 2], e3 = t4[i + 3];
            vals[0] = cw0 * e0.x + cw1 * e1.x + cw2 * e2.x + cw3 * e3.x;
            vals[1] = cw0 * e0.y + cw1 * e1.y + cw2 * e2.y + cw3 * e3.y;
            vals[2] = cw0 * e0.z + cw1 * e1.z + cw2 * e2.z + cw3 * e3.z;
            vals[3] = cw0 * e0.w + cw1 * e1.w + cw2 * e2.w + cw3 * e3.w;
            vals[4] = cw0 * sm[OFF_TAB1 + i]     + cw1 * sm[OFF_TAB1 + i + 1]
                    + cw2 * sm[OFF_TAB1 + i + 2] + cw3 * sm[OFF_TAB1 + i + 3];
        }

        // warp-local 8-channel reduce, store per-warp partials
        #pragma unroll
        for (int v = 0; v < 8; v++) {
            float t = vals[v];
            #pragma unroll
            for (int o = 16; o > 0; o >>= 1)
                t += __shfl_down_sync(0xffffffffu, t, o);
            if (lane == 0) sm[OFF_PART + bi * 32 + v * 4 + wrp] = t;
        }
    }
    __syncthreads();   // partials visible; table region now dead

    // ======================= batched tail =======================
    // ---- finalize main-loop partials (all batches at once) ----
    if (tid < 32) {
        int bi = tid >> 3, ch = tid & 7;
        const float* pp = sm + OFF_PART + bi * 32 + ch * 4;
        float s = pp[0] + pp[1] + pp[2] + pp[3];
        float* rin = sm + OFF_RHOIN4 + bi * 28;
        if (ch < 5) {
            rin[5 + ch] = s * (1.0f / NPAIR);            // table folds b2 and gate
        } else if (ch == 5) {
            rin[11] = s * (1.0f / NPAIR);                // s1_mean
        } else if (ch == 6) {
            sm[OFF_CUSP + bi] = s;
        } else {
            rin[10] = s * (1.0f / (NPART * DDIM));       // r2_mean
        }
    }
    // ---- stage phi W1T (k-tiled transposed) ----
    {
        const float4* gw = (const float4*)phi_w1;
        #pragma unroll
        for (int i = 0; i < 8; i++) {
            int idx4 = tid + 128 * i;
            float4 v = gw[idx4];
            int k = idx4 >> 4;
            int j0 = (idx4 & 15) * 4;
            float* d = sm + OFF_PHI_W1T + (k >> 2) * 256 + (k & 3) + j0 * 4;
            d[0] = v.x; d[4] = v.y; d[8] = v.z; d[12] = v.w;
        }
    }
    // ---- phi h0 for all nb batches, TRANSPOSED store [kt][kc][row] ----
    {
        const int R = tid >> 1, q = R >> 4, p = R & 15, kh = tid & 1;
        const int qq = (q < nb) ? q : 0;
        const float* xb = x + (size_t)(base + qq) * (NPART * DDIM) + p * 3;
        float xv0 = xb[0], xv1 = xb[1], xv2 = xb[2];
        const float4* w0 = (const float4*)(sm + OFF_PHI_W0);
        const float4* b0 = (const float4*)(sm + OFF_PHI_B0);
        #pragma unroll
        for (int t8 = 0; t8 < 8; t8++) {
            int kt = kh * 8 + t8;
            float4 a = b0[kt];
            float4 w;
            w = w0[0 * 16 + kt];
            a.x += xv0 * w.x; a.y += xv0 * w.y; a.z += xv0 * w.z; a.w += xv0 * w.w;
            w = w0[1 * 16 + kt];
            a.x += xv1 * w.x; a.y += xv1 * w.y; a.z += xv1 * w.z; a.w += xv1 * w.w;
            w = w0[2 * 16 + kt];
            a.x += xv2 * w.x; a.y += xv2 * w.y; a.z += xv2 * w.z; a.w += xv2 * w.w;
            float2 g01 = unpack2(gelu2(pack2(a.x, a.y)));
            float2 g23 = unpack2(gelu2(pack2(a.z, a.w)));
            float* dst = sm + OFF_H0T + kt * 256 + R;   // aliases dead table
            dst[0]   = g01.x;
            dst[64]  = g01.y;
            dst[128] = g23.x;
            dst[192] = g23.y;
        }
    }
    __syncthreads();
    // ---- phi h1 GEMM (64x64 @ 64x64) packed f32x2; warp w == batch w ----
    {
        const int rg = tid >> 4, cg = tid & 15;   // rg: 8 rows (4 row-pairs); cg: 4 cols
        const int q = rg >> 1;
        ull acc[4][4];
        #pragma unroll
        for (int c = 0; c < 4; c++) {
            ull bi1 = dup2(sm[OFF_PHI_B1 + cg + 16 * c]);
            #pragma unroll
            for (int p = 0; p < 4; p++) acc[p][c] = bi1;
        }
        const float4* w1t4 = (const float4*)(sm + OFF_PHI_W1T);
        #pragma unroll 1
        for (int kt = 0; kt < 16; kt++) {
            float4 bv0 = w1t4[kt * 64 + cg];
            float4 bv1 = w1t4[kt * 64 + cg + 16];
            float4 bv2 = w1t4[kt * 64 + cg + 32];
            float4 bv3 = w1t4[kt * 64 + cg + 48];
            const float* hb = sm + OFF_H0T + kt * 256 + rg * 8;
            #define KC_STEP(kc, comp)                                       \
            {                                                               \
                ull b20 = dup2(bv0.comp);                                   \
                ull b21 = dup2(bv1.comp);                                   \
                ull b22 = dup2(bv2.comp);                                   \
                ull b23 = dup2(bv3.comp);                                   \
                const ulonglong2* ap2 = (const ulonglong2*)(hb + (kc) * 64);\
                _Pragma("unroll")                                           \
                for (int p2 = 0; p2 < 2; p2++) {                            \
                    ulonglong2 aa2 = ap2[p2];                               \
                    ffma2(acc[2 * p2][0], aa2.x, b20);                      \
                    ffma2(acc[2 * p2][1], aa2.x, b21);                      \
                    ffma2(acc[2 * p2][2], aa2.x, b22);                      \
                    ffma2(acc[2 * p2][3], aa2.x, b23);                      \
                    ffma2(acc[2 * p2 + 1][0], aa2.y, b20);                  \
                    ffma2(acc[2 * p2 + 1][1], aa2.y, b21);                  \
                    ffma2(acc[2 * p2 + 1][2], aa2.y, b22);                  \
                    ffma2(acc[2 * p2 + 1][3], aa2.y, b23);                  \
                }                                                           \
            }
            KC_STEP(0, x) KC_STEP(1, y) KC_STEP(2, z) KC_STEP(3, w)
            #undef KC_STEP
        }
        // epilogue: packed gelu -> W2 (row-pairs stay packed; both rows same batch)
        ull pv2[5];
        #pragma unroll
        for (int d = 0; d < 5; d++) pv2[d] = dup2(0.f);
        #pragma unroll
        for (int c = 0; c < 4; c++) {
            const int j = cg + 16 * c;
            ull w2d[5];
            #pragma unroll
            for (int d = 0; d < 5; d++) w2d[d] = dup2(sm[OFF_PHI_W2 + j * 5 + d]);
            #pragma unroll
            for (int p = 0; p < 4; p++) {
                ull gg = gelu2(acc[p][c]);
                #pragma unroll
                for (int d = 0; d < 5; d++) pv2[d] = fma2(gg, w2d[d], pv2[d]);
            }
        }
        float pv[5];
        #pragma unroll
        for (int d = 0; d < 5; d++) {
            float2 f = unpack2(pv2[d]);
            float t = f.x + f.y;
            #pragma unroll
            for (int o = 16; o > 0; o >>= 1)
                t += __shfl_down_sync(0xffffffffu, t, o);
            pv[d] = t;
        }
        if (lane == 0 && q < nb) {
            float* rin = sm + OFF_RHOIN4 + q * 28;
            #pragma unroll
            for (int d = 0; d < 5; d++)
                rin[d] = pv[d] * (1.0f / NPART) + sm[OFF_PHI_B2 + d];
        }
    }
    __syncthreads();
    // ---- temb for all nb batches (scratch aliases dead phi h0) ----
    if (tid < 32) {
        int q = tid >> 3, i = tid & 7;
        if (q < nb) {
            float t = tau[base + q];
            if (i == 0) sm[OFF_TTF + q * 17] = t;
            float ft = freqs[i] * t;
            sm[OFF_TTF + q * 17 + 1 + i] = __sinf(ft);
            sm[OFF_TTF + q * 17 + 9 + i] = __cosf(ft);
        }
    }
    __syncthreads();
    if (tid < 64) {
        int q = tid >> 4, j = tid & 15;
        float a = tp_b0[j];
        #pragma unroll
        for (int i = 0; i < 2 * NFREQ + 1; i++)
            a += sm[OFF_TTF + q * 17 + i] * tp_w0[i * TEMB + j];
        sm[OFF_THT + q * 16 + j] = gelu_f(a);
    }
    __syncthreads();
    if (tid < 64) {
        int q = tid >> 4, j = tid & 15;
        float a = tp_b1[j];
        #pragma unroll
        for (int i = 0; i < TEMB; i++)
            a += sm[OFF_THT + q * 16 + i] * tp_w1[i * TEMB + j];
        sm[OFF_RHOIN4 + q * 28 + 12 + j] = a;
    }
    __syncthreads();
    // ---- rho h0: 256 outputs, 2 per thread ----
    #pragma unroll
    for (int s = 0; s < 2; s++) {
        int idx = tid + s * 128;
        int q = idx >> 6, j = idx & 63;
        float a = rho_b0[j];
        const float* rin = sm + OFF_RHOIN4 + q * 28;
        #pragma unroll 4
        for (int i = 0; i < RHOIN; i++) a += rin[i] * rho_w0[i * HID + j];
        sm[OFF_TRH0 + q * 64 + j] = gelu_f(a);
    }
    __syncthreads();
    // ---- rho h1 + w2, per-batch reduce ----
    float part[2];
    #pragma unroll
    for (int s = 0; s < 2; s++) {
        int idx = tid + s * 128;
        int q = idx >> 6, j = idx & 63;
        float a = rho_b1[j];
        const float* rh = sm + OFF_TRH0 + q * 64;
        #pragma unroll 4
        for (int k = 0; k < HID; k++) a += rh[k] * rho_w1[k * HID + j];
        part[s] = gelu_f(a) * rho_w2[j];
    }
    {
        #pragma unroll
        for (int o = 16; o > 0; o >>= 1) {
            part[0] += __shfl_down_sync(0xffffffffu, part[0], o);
            part[1] += __shfl_down_sync(0xffffffffu, part[1], o);
        }
        if (lane == 0) { sm[OFF_RED + wrp] = part[0]; sm[OFF_RED + 4 + wrp] = part[1]; }
    }
    __syncthreads();
    if (tid < 4 && tid < nb) {
        float ssum = sm[OFF_RED + 2 * tid] + sm[OFF_RED + 2 * tid + 1];
        out[base + tid] = ssum + rho_b2[0] + sm[OFF_CUSP + tid];
    }
}

extern "C" void kernel_launch(void* const* d_in, const int* in_sizes, int n_in,
                              void* d_out, int out_size) {
    const float* x      = (const float*)d_in[0];
    const float* tau    = (const float*)d_in[1];
    const float* freqs  = (const float*)d_in[2];
    const float* phi_w0 = (const float*)d_in[3];
    const float* phi_b0 = (const float*)d_in[4];
    const float* phi_w1 = (const float*)d_in[5];
    const float* phi_b1 = (const float*)d_in[6];
    const float* phi_w2 = (const float*)d_in[7];
    const float* phi_b2 = (const float*)d_in[8];
    const float* psi_w0 = (const float*)d_in[9];
    const float* psi_b0 = (const float*)d_in[10];
    const float* psi_w1 = (const float*)d_in[11];
    const float* psi_b1 = (const float*)d_in[12];
    const float* psi_w2 = (const float*)d_in[13];
    const float* psi_b2 = (const float*)d_in[14];
    const float* rho_w0 = (const float*)d_in[15];
    const float* rho_b0 = (const float*)d_in[16];
    const float* rho_w1 = (const float*)d_in[17];
    const float* rho_b1 = (const float*)d_in[18];
    const float* rho_w2 = (const float*)d_in[19];
    const float* rho_b2 = (const float*)d_in[20];
    const float* tp_w0  = (const float*)d_in[21];
    const float* tp_b0  = (const float*)d_in[22];
    const float* tp_w1  = (const float*)d_in[23];
    const float* tp_b1  = (const float*)d_in[24];
    float* out = (float*)d_out;

    const int Btot = in_sizes[1];

    // 1) build the psi spline table (warp per knot)
    build_tab_kernel<<<(TAB_SLOTS + 3) / 4, 128>>>(
        psi_w0, psi_b0, psi_w1, psi_b1, psi_w2, psi_b2);

    // 2) main kernel
    const int nblocks = (Btot + BPB - 1) / BPB;
    cudaFuncSetAttribute(tau_jastrow_kernel,
                         cudaFuncAttributeMaxDynamicSharedMemorySize, SMEM_BYTES);
    tau_jastrow_kernel<<<nblocks, NTHREADS, SMEM_BYTES>>>(
        x, tau, freqs,
        phi_w0, phi_b0, phi_w1, phi_b1, phi_w2, phi_b2,
        rho_w0, rho_b0, rho_w1, rho_b1, rho_w2, rho_b2,
        tp_w0, tp_b0, tp_w1, tp_b1,
        out, Btot);
}

// round 14
// speedup vs baseline: 5.9733x; 1.0627x over previous
#include <cuda_runtime.h>
#include <math.h>

#define NPART 16
#define DDIM 3
#define HID 64
#define DLAT 5
#define TEMB 16
#define NFREQ 8
#define NPAIR 120
#define RHOIN 28
#define NTHREADS 128
#define BPB 8

#define TAB_N 512
#define TAB_SLOTS (TAB_N + 4)                       // 516 knots (incl -1 and +2 guards)
#define TAB_T0 0.6931471805599453f
#define TAB_TMAX 9.0f
#define TAB_H ((TAB_TMAX - TAB_T0) / (float)TAB_N)
#define TAB_INVH ((float)TAB_N / (TAB_TMAX - TAB_T0))

typedef unsigned long long ull;

// table: channels 0-3 of psi_out*gate in float4, channel 4 separate
__device__ float4 g_tab4[TAB_SLOTS];
__device__ float  g_tab1[TAB_SLOTS];

// ---- dynamic smem layout (float offsets) ----
// union region [0, 4096):
//   main phase : table [0,2580) | PART [2580,2836) | X8 [2836,3220)
//   phi passes : h0 transposed [16][256] = [0,4096)
//   post-GEMM  : TTF [0,136) | THT [256,384) | TRH0 [512,1024)
#define OFF_TAB4    0              // 516 float4 = 2064 floats
#define OFF_TAB1    2064           // 516 (table ends 2580)
#define OFF_PART    2580           // 8 batches x 8 ch x 4 warps = 256
#define OFF_X8      2836           // 8 x 48 = 384
#define OFF_H0T     0              // 4096 (phi passes)
#define OFF_TTF     0              // 8 x 17 = 136
#define OFF_THT     256            // 8 x 16 = 128
#define OFF_TRH0    512            // 8 x 64 = 512
#define OFF_PHI_W1T 4096           // 4096
#define OFF_PHI_W0  8192           // 192
#define OFF_PHI_B0  8384           // 64
#define OFF_PHI_B1  8448           // 64
#define OFF_PHI_W2  8512           // 320
#define OFF_PHI_B2  8832           // 8
#define OFF_RED     8840           // 16
#define OFF_RHOIN4  8856           // 8 x 28 = 224
#define OFF_CUSP    9080           // 8
#define SMEM_FLOATS 9088
#define SMEM_BYTES  (SMEM_FLOATS * 4)

// ---- packed f32x2 helpers ----
__device__ __forceinline__ ull pack2(float lo, float hi) {
    ull r; asm("mov.b64 %0, {%1, %2};" : "=l"(r) : "f"(lo), "f"(hi)); return r;
}
__device__ __forceinline__ ull dup2(float b) {
    ull r; asm("mov.b64 %0, {%1, %1};" : "=l"(r) : "f"(b)); return r;
}
__device__ __forceinline__ float2 unpack2(ull v) {
    float2 f; asm("mov.b64 {%0, %1}, %2;" : "=f"(f.x), "=f"(f.y) : "l"(v)); return f;
}
__device__ __forceinline__ void ffma2(ull& d, ull a, ull b) {
    asm("fma.rn.f32x2 %0, %1, %2, %0;" : "+l"(d) : "l"(a), "l"(b));
}
__device__ __forceinline__ ull fma2(ull a, ull b, ull c) {
    ull d; asm("fma.rn.f32x2 %0, %1, %2, %3;" : "=l"(d) : "l"(a), "l"(b), "l"(c)); return d;
}
__device__ __forceinline__ ull mul2(ull a, ull b) {
    ull d; asm("mul.rn.f32x2 %0, %1, %2;" : "=l"(d) : "l"(a), "l"(b)); return d;
}
__device__ __forceinline__ ull add2(ull a, ull b) {
    ull d; asm("add.rn.f32x2 %0, %1, %2;" : "=l"(d) : "l"(a), "l"(b)); return d;
}

// ---- gelu: A&S 7.1.26 erf (|err|<=1.5e-7), branchless (EX2 on MUFU pipe)
__device__ __forceinline__ float gelu_f(float x) {
    float ax = fabsf(x);
    float z = ax * 0.70710678118f;
    float t = __fdividef(1.0f, fmaf(0.3275911f, z, 1.0f));
    float p = t * fmaf(t, fmaf(t, fmaf(t, fmaf(t, 1.061405429f, -1.453152027f),
                         1.421413741f), -0.284496736f), 0.254829592f);
    float q = p * exp2f(-1.442695041f * z * z);
    return 0.5f * ((x + ax) - ax * q);
}

__device__ __forceinline__ ull gelu2(ull x2) {
    ull ax2;
    asm("and.b64 %0, %1, %2;" : "=l"(ax2) : "l"(x2), "l"(0x7fffffff7fffffffULL));
    ull z2 = mul2(ax2, dup2(0.70710678118f));
    float2 z = unpack2(z2);
    float tx = __fdividef(1.0f, fmaf(0.3275911f, z.x, 1.0f));
    float ty = __fdividef(1.0f, fmaf(0.3275911f, z.y, 1.0f));
    ull t2 = pack2(tx, ty);
    ull p2 = fma2(t2, dup2(1.061405429f), dup2(-1.453152027f));
    p2 = fma2(p2, t2, dup2(1.421413741f));
    p2 = fma2(p2, t2, dup2(-0.284496736f));
    p2 = fma2(p2, t2, dup2(0.254829592f));
    p2 = mul2(p2, t2);
    float2 m = unpack2(mul2(mul2(z2, z2), dup2(-1.442695041f)));
    ull q2 = mul2(p2, pack2(exp2f(m.x), exp2f(m.y)));
    ull s2 = add2(x2, ax2);
    ull w2 = mul2(ax2, q2);
    return fma2(w2, dup2(-0.5f), mul2(s2, dup2(0.5f)));
}

// precise gelu for the table builder
__device__ __forceinline__ float gelu_exact(float x) {
    return 0.5f * x * (1.0f + erff(x * 0.70710678118654752f));
}

// ================= table builder: warp per knot =================
__global__ void build_tab_kernel(
    const float* __restrict__ psi_w0, const float* __restrict__ psi_b0,
    const float* __restrict__ psi_w1, const float* __restrict__ psi_b1,
    const float* __restrict__ psi_w2, const float* __restrict__ psi_b2)
{
    __shared__ float h0s[4][HID];
    const int wid = threadIdx.x >> 5, lane = threadIdx.x & 31;
    const int j = blockIdx.x * 4 + wid;
    if (j >= TAB_SLOTS) return;

    float t = TAB_T0 + (float)(j - 1) * TAB_H;      // knot j-1
    float r2 = expm1f(t) * 0.04f - 0.04f;           // invert t = log1p(25*(r2+0.04))
    float rt2 = r2 + 0.04f;
    float u = rt2 * 25.0f;
    float feat[6];
    float s1 = log1pf(u);
    feat[0] = s1;
    feat[1] = r2 / rt2;
    feat[2] = u * expf(-u);
    feat[3] = expf(-0.25f * s1);
    feat[4] = expf(-s1);
    feat[5] = expf(-4.0f * s1);
    float gate = r2 / (r2 + 0.09f);

    #pragma unroll
    for (int s = 0; s < 2; s++) {
        int k = lane + 32 * s;
        float a = psi_b0[k];
        #pragma unroll
        for (int i = 0; i < 6; i++) a += feat[i] * psi_w0[i * HID + k];
        h0s[wid][k] = gelu_exact(a);
    }
    __syncwarp();

    float outv[DLAT] = {0.f, 0.f, 0.f, 0.f, 0.f};
    #pragma unroll
    for (int s = 0; s < 2; s++) {
        int q = lane + 32 * s;
        float a = psi_b1[q];
        #pragma unroll 8
        for (int k = 0; k < HID; k++) a += h0s[wid][k] * psi_w1[k * HID + q];
        float g = gelu_exact(a);
        #pragma unroll
        for (int d = 0; d < DLAT; d++) outv[d] += g * psi_w2[q * DLAT + d];
    }
    #pragma unroll
    for (int d = 0; d < DLAT; d++) {
        float v = outv[d];
        #pragma unroll
        for (int o = 16; o > 0; o >>= 1)
            v += __shfl_down_sync(0xffffffffu, v, o);
        outv[d] = v;
    }
    if (lane == 0) {
        #pragma unroll
        for (int d = 0; d < DLAT; d++) outv[d] += psi_b2[d];
        g_tab4[j] = make_float4(outv[0] * gate, outv[1] * gate,
                                outv[2] * gate, outv[3] * gate);
        g_tab1[j] = outv[4] * gate;
    }
}

// ================= main kernel =================
__global__ __launch_bounds__(NTHREADS, 6)
void tau_jastrow_kernel(
    const float* __restrict__ x, const float* __restrict__ tau, const float* __restrict__ freqs,
    const float* __restrict__ phi_w0, const float* __restrict__ phi_b0,
    const float* __restrict__ phi_w1, const float* __restrict__ phi_b1,
    const float* __restrict__ phi_w2, const float* __restrict__ phi_b2,
    const float* __restrict__ rho_w0, const float* __restrict__ rho_b0,
    const float* __restrict__ rho_w1, const float* __restrict__ rho_b1,
    const float* __restrict__ rho_w2, const float* __restrict__ rho_b2,
    const float* __restrict__ tp_w0, const float* __restrict__ tp_b0,
    const float* __restrict__ tp_w1, const float* __restrict__ tp_b1,
    float* __restrict__ out, int Btot)
{
    extern __shared__ float sm[];
    const int tid = threadIdx.x;
    const int lane = tid & 31, wrp = tid >> 5;

    const int base = blockIdx.x * BPB;
    const int nb = (Btot - base < BPB) ? (Btot - base) : BPB;

    // ---- stage: table, phi W1T (once), small weights, all 8 batches' x ----
    {
        float4* st4 = (float4*)(sm + OFF_TAB4);
        for (int i = tid; i < TAB_SLOTS; i += NTHREADS) st4[i] = g_tab4[i];
        for (int i = tid; i < TAB_SLOTS; i += NTHREADS) sm[OFF_TAB1 + i] = g_tab1[i];
    }
    {
        const float4* gw = (const float4*)phi_w1;
        #pragma unroll
        for (int i = 0; i < 8; i++) {
            int idx4 = tid + 128 * i;
            float4 v = gw[idx4];
            int k = idx4 >> 4;
            int j0 = (idx4 & 15) * 4;
            float* d = sm + OFF_PHI_W1T + (k >> 2) * 256 + (k & 3) + j0 * 4;
            d[0] = v.x; d[4] = v.y; d[8] = v.z; d[12] = v.w;
        }
    }
    for (int i = tid; i < 3 * HID; i += NTHREADS) sm[OFF_PHI_W0 + i] = phi_w0[i];
    for (int i = tid; i < HID * DLAT; i += NTHREADS) sm[OFF_PHI_W2 + i] = phi_w2[i];
    if (tid < HID) { sm[OFF_PHI_B0 + tid] = phi_b0[tid]; sm[OFF_PHI_B1 + tid] = phi_b1[tid]; }
    if (tid < DLAT) sm[OFF_PHI_B2 + tid] = phi_b2[tid];
    for (int i = tid; i < nb * NPART * DDIM; i += NTHREADS)
        sm[OFF_X8 + i] = x[(size_t)base * (NPART * DDIM) + i];

    // ---- pair indices (triu k=1 row-major) ----
    int pi = 0, pj = 0;
    {
        int p2 = tid, i2 = 0, cnt = NPART - 1;
        while (cnt > 0 && p2 >= cnt) { p2 -= cnt; i2++; cnt--; }
        pi = i2; pj = i2 + 1 + p2;
        if (pj >= NPART) pj = NPART - 1;
    }
    const bool active = (tid < NPAIR);
    const float gamma = ((pi < NPART / 2) == (pj < NPART / 2))
                        ? (1.0f / (DDIM + 1)) : (1.0f / (DDIM - 1));

    __syncthreads();

    // ============== barrier-free main loop over up to 8 batches ==============
    for (int bi = 0; bi < nb; ++bi) {
        const float* xb = sm + OFF_X8 + bi * (NPART * DDIM);

        float vals[8];
        #pragma unroll
        for (int v = 0; v < 8; v++) vals[v] = 0.f;
        if (tid < NPART * DDIM) {
            float xv = xb[tid];
            vals[7] = xv * xv;
        }

        if (active) {
            float d0 = xb[pi * 3 + 0] - xb[pj * 3 + 0];
            float d1 = xb[pi * 3 + 1] - xb[pj * 3 + 1];
            float d2 = xb[pi * 3 + 2] - xb[pj * 3 + 2];
            float r2 = d0 * d0 + d1 * d1 + d2 * d2;
            float rt2 = r2 + 0.04f;
            float tt = __fdividef(1.0f, fmaf(25.0f, rt2, 1.0f));
            float t = -__logf(tt);                       // s1
            float r = sqrtf(r2 + 1.1920929e-7f);
            vals[5] = t;
            vals[6] = gamma * r * __expf(-r);            // cusp (exact path)

            float idxf = (t - TAB_T0) * TAB_INVH;
            int i = (int)idxf;
            if (i > TAB_N - 1) i = TAB_N - 1;
            if (i < 0) i = 0;
            float uf = idxf - (float)i;
            float u2 = uf * uf, u3 = u2 * uf;
            float cw0 = 0.5f * (-u3 + 2.0f * u2 - uf);
            float cw1 = 0.5f * (3.0f * u3 - 5.0f * u2 + 2.0f);
            float cw2 = 0.5f * (-3.0f * u3 + 4.0f * u2 + uf);
            float cw3 = 0.5f * (u3 - u2);
            const float4* t4 = (const float4*)(sm + OFF_TAB4);
            float4 e0 = t4[i], e1 = t4[i + 1], e2 = t4[i + 2], e3 = t4[i + 3];
            vals[0] = cw0 * e0.x + cw1 * e1.x + cw2 * e2.x + cw3 * e3.x;
            vals[1] = cw0 * e0.y + cw1 * e1.y + cw2 * e2.y + cw3 * e3.y;
            vals[2] = cw0 * e0.z + cw1 * e1.z + cw2 * e2.z + cw3 * e3.z;
            vals[3] = cw0 * e0.w + cw1 * e1.w + cw2 * e2.w + cw3 * e3.w;
            vals[4] = cw0 * sm[OFF_TAB1 + i]     + cw1 * sm[OFF_TAB1 + i + 1]
                    + cw2 * sm[OFF_TAB1 + i + 2] + cw3 * sm[OFF_TAB1 + i + 3];
        }

        #pragma unroll
        for (int v = 0; v < 8; v++) {
            float t = vals[v];
            #pragma unroll
            for (int o = 16; o > 0; o >>= 1)
                t += __shfl_down_sync(0xffffffffu, t, o);
            if (lane == 0) sm[OFF_PART + bi * 32 + v * 4 + wrp] = t;
        }
    }
    __syncthreads();   // partials visible

    // ---- finalize main-loop partials (8 batches x 8 channels) ----
    if (tid < 64) {
        int bi = tid >> 3, ch = tid & 7;
        if (bi < nb) {
            const float* pp = sm + OFF_PART + bi * 32 + ch * 4;
            float s = pp[0] + pp[1] + pp[2] + pp[3];
            float* rin = sm + OFF_RHOIN4 + bi * 28;
            if (ch < 5) {
                rin[5 + ch] = s * (1.0f / NPAIR);        // table folds b2 and gate
            } else if (ch == 5) {
                rin[11] = s * (1.0f / NPAIR);            // s1_mean
            } else if (ch == 6) {
                sm[OFF_CUSP + bi] = s;
            } else {
                rin[10] = s * (1.0f / (NPART * DDIM));   // r2_mean
            }
        }
    }
    __syncthreads();   // PART/table region about to be overwritten by phi h0

    // ======================= phi: two passes of 4 batches =======================
    #pragma unroll 1
    for (int ps = 0; ps < 2; ps++) {
        const int b0 = ps * 4;
        // ---- phi h0 (4 batches), TRANSPOSED store [kt][kc][row] ----
        {
            const int R = tid >> 1, q = R >> 4, p = R & 15, kh = tid & 1;
            int qg = base + b0 + q;
            if (qg > Btot - 1) qg = Btot - 1;
            const float* xb = x + (size_t)qg * (NPART * DDIM) + p * 3;
            float xv0 = xb[0], xv1 = xb[1], xv2 = xb[2];
            const float4* w0 = (const float4*)(sm + OFF_PHI_W0);
            const float4* b0p = (const float4*)(sm + OFF_PHI_B0);
            #pragma unroll
            for (int t8 = 0; t8 < 8; t8++) {
                int kt = kh * 8 + t8;
                float4 a = b0p[kt];
                float4 w;
                w = w0[0 * 16 + kt];
                a.x += xv0 * w.x; a.y += xv0 * w.y; a.z += xv0 * w.z; a.w += xv0 * w.w;
                w = w0[1 * 16 + kt];
                a.x += xv1 * w.x; a.y += xv1 * w.y; a.z += xv1 * w.z; a.w += xv1 * w.w;
                w = w0[2 * 16 + kt];
                a.x += xv2 * w.x; a.y += xv2 * w.y; a.z += xv2 * w.z; a.w += xv2 * w.w;
                float2 g01 = unpack2(gelu2(pack2(a.x, a.y)));
                float2 g23 = unpack2(gelu2(pack2(a.z, a.w)));
                float* dst = sm + OFF_H0T + kt * 256 + R;
                dst[0]   = g01.x;
                dst[64]  = g01.y;
                dst[128] = g23.x;
                dst[192] = g23.y;
            }
        }
        __syncthreads();
        // ---- phi h1 GEMM packed f32x2; warp w == local batch w ----
        {
            const int rg = tid >> 4, cg = tid & 15;
            const int q = rg >> 1;
            ull acc[4][4];
            #pragma unroll
            for (int c = 0; c < 4; c++) {
                ull bi1 = dup2(sm[OFF_PHI_B1 + cg + 16 * c]);
                #pragma unroll
                for (int p = 0; p < 4; p++) acc[p][c] = bi1;
            }
            const float4* w1t4 = (const float4*)(sm + OFF_PHI_W1T);
            #pragma unroll 1
            for (int kt = 0; kt < 16; kt++) {
                float4 bv0 = w1t4[kt * 64 + cg];
                float4 bv1 = w1t4[kt * 64 + cg + 16];
                float4 bv2 = w1t4[kt * 64 + cg + 32];
                float4 bv3 = w1t4[kt * 64 + cg + 48];
                const float* hb = sm + OFF_H0T + kt * 256 + rg * 8;
                #define KC_STEP(kc, comp)                                       \
                {                                                               \
                    ull b20 = dup2(bv0.comp);                                   \
                    ull b21 = dup2(bv1.comp);                                   \
                    ull b22 = dup2(bv2.comp);                                   \
                    ull b23 = dup2(bv3.comp);                                   \
                    const ulonglong2* ap2 = (const ulonglong2*)(hb + (kc) * 64);\
                    _Pragma("unroll")                                           \
                    for (int p2 = 0; p2 < 2; p2++) {                            \
                        ulonglong2 aa2 = ap2[p2];                               \
                        ffma2(acc[2 * p2][0], aa2.x, b20);                      \
                        ffma2(acc[2 * p2][1], aa2.x, b21);                      \
                        ffma2(acc[2 * p2][2], aa2.x, b22);                      \
                        ffma2(acc[2 * p2][3], aa2.x, b23);                      \
                        ffma2(acc[2 * p2 + 1][0], aa2.y, b20);                  \
                        ffma2(acc[2 * p2 + 1][1], aa2.y, b21);                  \
                        ffma2(acc[2 * p2 + 1][2], aa2.y, b22);                  \
                        ffma2(acc[2 * p2 + 1][3], aa2.y, b23);                  \
                    }                                                           \
                }
                KC_STEP(0, x) KC_STEP(1, y) KC_STEP(2, z) KC_STEP(3, w)
                #undef KC_STEP
            }
            ull pv2[5];
            #pragma unroll
            for (int d = 0; d < 5; d++) pv2[d] = dup2(0.f);
            #pragma unroll
            for (int c = 0; c < 4; c++) {
                const int j = cg + 16 * c;
                ull w2d[5];
                #pragma unroll
                for (int d = 0; d < 5; d++) w2d[d] = dup2(sm[OFF_PHI_W2 + j * 5 + d]);
                #pragma unroll
                for (int p = 0; p < 4; p++) {
                    ull gg = gelu2(acc[p][c]);
                    #pragma unroll
                    for (int d = 0; d < 5; d++) pv2[d] = fma2(gg, w2d[d], pv2[d]);
                }
            }
            float pv[5];
            #pragma unroll
            for (int d = 0; d < 5; d++) {
                float2 f = unpack2(pv2[d]);
                float t = f.x + f.y;
                #pragma unroll
                for (int o = 16; o > 0; o >>= 1)
                    t += __shfl_down_sync(0xffffffffu, t, o);
                pv[d] = t;
            }
            if (lane == 0 && b0 + q < nb) {
                float* rin = sm + OFF_RHOIN4 + (b0 + q) * 28;
                #pragma unroll
                for (int d = 0; d < 5; d++)
                    rin[d] = pv[d] * (1.0f / NPART) + sm[OFF_PHI_B2 + d];
            }
        }
        __syncthreads();
    }

    // ======================= temb + rho for all 8 batches =======================
    if (tid < 64) {
        int q = tid >> 3, i = tid & 7;
        int qg = base + q;
        if (qg > Btot - 1) qg = Btot - 1;
        float t = tau[qg];
        if (i == 0) sm[OFF_TTF + q * 17] = t;
        float ft = freqs[i] * t;
        sm[OFF_TTF + q * 17 + 1 + i] = __sinf(ft);
        sm[OFF_TTF + q * 17 + 9 + i] = __cosf(ft);
    }
    __syncthreads();
    {   // temb layer 0: 8 batches x 16 outputs = 128 threads exactly
        int q = tid >> 4, j = tid & 15;
        float a = tp_b0[j];
        #pragma unroll
        for (int i = 0; i < 2 * NFREQ + 1; i++)
            a += sm[OFF_TTF + q * 17 + i] * tp_w0[i * TEMB + j];
        sm[OFF_THT + q * 16 + j] = gelu_f(a);
    }
    __syncthreads();
    {   // temb layer 1
        int q = tid >> 4, j = tid & 15;
        float a = tp_b1[j];
        #pragma unroll
        for (int i = 0; i < TEMB; i++)
            a += sm[OFF_THT + q * 16 + i] * tp_w1[i * TEMB + j];
        sm[OFF_RHOIN4 + q * 28 + 12 + j] = a;
    }
    __syncthreads();
    // ---- rho h0: 512 outputs, 4 per thread ----
    #pragma unroll
    for (int s = 0; s < 4; s++) {
        int idx = tid + s * 128;
        int q = idx >> 6, j = idx & 63;
        float a = rho_b0[j];
        const float* rin = sm + OFF_RHOIN4 + q * 28;
        #pragma unroll 4
        for (int i = 0; i < RHOIN; i++) a += rin[i] * rho_w0[i * HID + j];
        sm[OFF_TRH0 + q * 64 + j] = gelu_f(a);
    }
    __syncthreads();
    // ---- rho h1 + w2, per-batch reduce ----
    float part[4];
    #pragma unroll
    for (int s = 0; s < 4; s++) {
        int idx = tid + s * 128;
        int q = idx >> 6, j = idx & 63;
        float a = rho_b1[j];
        const float* rh = sm + OFF_TRH0 + q * 64;
        #pragma unroll 4
        for (int k = 0; k < HID; k++) a += rh[k] * rho_w1[k * HID + j];
        part[s] = gelu_f(a) * rho_w2[j];
    }
    {
        #pragma unroll
        for (int o = 16; o > 0; o >>= 1) {
            #pragma unroll
            for (int s = 0; s < 4; s++)
                part[s] += __shfl_down_sync(0xffffffffu, part[s], o);
        }
        if (lane == 0) {
            #pragma unroll
            for (int s = 0; s < 4; s++)
                sm[OFF_RED + s * 4 + wrp] = part[s];
        }
    }
    __syncthreads();
    if (tid < 8 && tid < nb) {
        // batch q: s = q>>1, warp pair = {2*(q&1), 2*(q&1)+1}
        int s = tid >> 1, wb = (tid & 1) * 2;
        float ssum = sm[OFF_RED + s * 4 + wb] + sm[OFF_RED + s * 4 + wb + 1];
        out[base + tid] = ssum + rho_b2[0] + sm[OFF_CUSP + tid];
    }
}

extern "C" void kernel_launch(void* const* d_in, const int* in_sizes, int n_in,
                              void* d_out, int out_size) {
    const float* x      = (const float*)d_in[0];
    const float* tau    = (const float*)d_in[1];
    const float* freqs  = (const float*)d_in[2];
    const float* phi_w0 = (const float*)d_in[3];
    const float* phi_b0 = (const float*)d_in[4];
    const float* phi_w1 = (const float*)d_in[5];
    const float* phi_b1 = (const float*)d_in[6];
    const float* phi_w2 = (const float*)d_in[7];
    const float* phi_b2 = (const float*)d_in[8];
    const float* psi_w0 = (const float*)d_in[9];
    const float* psi_b0 = (const float*)d_in[10];
    const float* psi_w1 = (const float*)d_in[11];
    const float* psi_b1 = (const float*)d_in[12];
    const float* psi_w2 = (const float*)d_in[13];
    const float* psi_b2 = (const float*)d_in[14];
    const float* rho_w0 = (const float*)d_in[15];
    const float* rho_b0 = (const float*)d_in[16];
    const float* rho_w1 = (const float*)d_in[17];
    const float* rho_b1 = (const float*)d_in[18];
    const float* rho_w2 = (const float*)d_in[19];
    const float* rho_b2 = (const float*)d_in[20];
    const float* tp_w0  = (const float*)d_in[21];
    const float* tp_b0  = (const float*)d_in[22];
    const float* tp_w1  = (const float*)d_in[23];
    const float* tp_b1  = (const float*)d_in[24];
    float* out = (float*)d_out;

    const int Btot = in_sizes[1];

    // 1) build the psi spline table (warp per knot)
    build_tab_kernel<<<(TAB_SLOTS + 3) / 4, 128>>>(
        psi_w0, psi_b0, psi_w1, psi_b1, psi_w2, psi_b2);

    // 2) main kernel
    const int nblocks = (Btot + BPB - 1) / BPB;
    cudaFuncSetAttribute(tau_jastrow_kernel,
                         cudaFuncAttributeMaxDynamicSharedMemorySize, SMEM_BYTES);
    tau_jastrow_kernel<<<nblocks, NTHREADS, SMEM_BYTES>>>(
        x, tau, freqs,
        phi_w0, phi_b0, phi_w1, phi_b1, phi_w2, phi_b2,
        rho_w0, rho_b0, rho_w1, rho_b1, rho_w2, rho_b2,
        tp_w0, tp_b0, tp_w1, tp_b1,
        out, Btot);
}